// round 1
// baseline (speedup 1.0000x reference)
#include <cuda_runtime.h>

// Problem constants
#define BATCH   1024
#define TT      8
#define NN      49
#define CDIM    96
#define HEADS   3
#define HD      32
#define NWIN    64
#define LDSX    97      // padded row stride (odd -> conflict-free stride-row access)
#define ROWS    56      // padded row count (49 -> 56 spatial; 7 seqs * 8 = 56 temporal)

// smem sizes (floats)
#define SM_COMMON (4*ROWS*LDSX + 96*96)
#define SM_SP_FLOATS (SM_COMMON + 3*49*49)
#define SM_T_FLOATS  (SM_COMMON + 7*3*8*8)
#define SMEM_SP (SM_SP_FLOATS * 4)
#define SMEM_T  (SM_T_FLOATS * 4)

__global__ __launch_bounds__(256, 1)
void spatial_kernel(const float* __restrict__ x, const float* __restrict__ mask,
                    const float* __restrict__ qkv_w, const float* __restrict__ qkv_b,
                    const float* __restrict__ pw, const float* __restrict__ pb,
                    float* __restrict__ out)
{
    extern __shared__ float sm[];
    float* xs = sm;                       // ROWS x LDSX (also reused for attn output)
    float* qs = xs + ROWS*LDSX;
    float* ks = qs + ROWS*LDSX;
    float* vs = ks + ROWS*LDSX;
    float* ws = vs + ROWS*LDSX;           // 96x96 weight chunk
    float* at = ws + 96*96;               // 3*49*49 scores

    const int bt   = blockIdx.x;
    const int tid  = threadIdx.x;
    const int lane = tid & 31;
    const int warp = tid >> 5;

    // ---- load x sequence (49x96) ----
    const float* xg = x + (size_t)bt * (NN*CDIM);
    for (int idx = tid; idx < NN*CDIM; idx += 256) {
        int r = idx / CDIM, c = idx - r*CDIM;
        xs[r*LDSX + c] = xg[idx];
    }
    __syncthreads();

    int rrow[7], rclamp[7];
    #pragma unroll
    for (int rr = 0; rr < 7; rr++) { rrow[rr] = warp + 8*rr; rclamp[rr] = min(rrow[rr], NN-1); }

    // ---- QKV: 3 chunks of 96 cols each ----
    for (int wsel = 0; wsel < 3; wsel++) {
        for (int idx = tid; idx < 96*96; idx += 256) {
            int k = idx / 96, j = idx - k*96;
            ws[idx] = qkv_w[k*288 + wsel*96 + j];
        }
        __syncthreads();
        float acc[7][3];
        #pragma unroll
        for (int rr = 0; rr < 7; rr++) {
            #pragma unroll
            for (int cc = 0; cc < 3; cc++)
                acc[rr][cc] = qkv_b[wsel*96 + lane + 32*cc];
        }
        for (int k = 0; k < 96; k++) {
            float w0 = ws[k*96 + lane];
            float w1 = ws[k*96 + lane + 32];
            float w2 = ws[k*96 + lane + 64];
            #pragma unroll
            for (int rr = 0; rr < 7; rr++) {
                float xv = xs[rclamp[rr]*LDSX + k];
                acc[rr][0] += xv*w0; acc[rr][1] += xv*w1; acc[rr][2] += xv*w2;
            }
        }
        float* dst = (wsel == 0) ? qs : (wsel == 1) ? ks : vs;
        #pragma unroll
        for (int rr = 0; rr < 7; rr++) {
            #pragma unroll
            for (int cc = 0; cc < 3; cc++)
                dst[rrow[rr]*LDSX + lane + 32*cc] = acc[rr][cc];
        }
        __syncthreads();
    }

    // ---- scores: s[h][i][j] = scale*q.k + mask ----
    const float scale = 0.17677669529663687f;
    const float* mrow = mask + (size_t)(bt & (NWIN-1)) * (49*49);
    for (int e = tid; e < HEADS*49*49; e += 256) {
        int h = e / 2401;
        int rem = e - h*2401;
        int i = rem / 49;
        const float* qp = qs + i*LDSX + h*HD;
        const float* kp = ks + (rem - i*49)*LDSX + h*HD;
        float s = 0.f;
        #pragma unroll
        for (int d = 0; d < HD; d++) s += qp[d]*kp[d];
        at[e] = s*scale + mrow[rem];
    }
    __syncthreads();

    // ---- softmax over rows of length 49 (one warp per row) ----
    for (int row = warp; row < HEADS*49; row += 8) {
        float* arow = at + row*49;
        float v0 = arow[lane];
        float v1 = (lane + 32 < 49) ? arow[lane + 32] : -3.0e38f;
        float mx = fmaxf(v0, v1);
        #pragma unroll
        for (int o = 16; o; o >>= 1) mx = fmaxf(mx, __shfl_xor_sync(0xffffffffu, mx, o));
        v0 = __expf(v0 - mx);
        v1 = (lane + 32 < 49) ? __expf(v1 - mx) : 0.f;
        float s = v0 + v1;
        #pragma unroll
        for (int o = 16; o; o >>= 1) s += __shfl_xor_sync(0xffffffffu, s, o);
        float inv = __frcp_rn(s);
        arow[lane] = v0*inv;
        if (lane + 32 < 49) arow[lane + 32] = v1*inv;
    }
    __syncthreads();

    // ---- PV: out[i][h*32+d] = sum_j attn[h][i][j] * v[j][h*32+d] ----
    {
        float acc[7][3];
        #pragma unroll
        for (int rr = 0; rr < 7; rr++) { acc[rr][0]=0.f; acc[rr][1]=0.f; acc[rr][2]=0.f; }
        for (int j = 0; j < 49; j++) {
            float v0 = vs[j*LDSX + lane];
            float v1 = vs[j*LDSX + 32 + lane];
            float v2 = vs[j*LDSX + 64 + lane];
            #pragma unroll
            for (int rr = 0; rr < 7; rr++) {
                int ib = rclamp[rr]*49 + j;
                acc[rr][0] += at[ib]*v0;
                acc[rr][1] += at[2401 + ib]*v1;
                acc[rr][2] += at[4802 + ib]*v2;
            }
        }
        #pragma unroll
        for (int rr = 0; rr < 7; rr++) {
            #pragma unroll
            for (int cc = 0; cc < 3; cc++)
                xs[rrow[rr]*LDSX + lane + 32*cc] = acc[rr][cc];   // reuse xs for attn out
        }
    }
    for (int idx = tid; idx < 96*96; idx += 256) ws[idx] = pw[idx];
    __syncthreads();

    // ---- output projection + store ----
    {
        float po[7][3];
        #pragma unroll
        for (int rr = 0; rr < 7; rr++) {
            #pragma unroll
            for (int cc = 0; cc < 3; cc++)
                po[rr][cc] = pb[lane + 32*cc];
        }
        for (int k = 0; k < 96; k++) {
            float w0 = ws[k*96 + lane];
            float w1 = ws[k*96 + lane + 32];
            float w2 = ws[k*96 + lane + 64];
            #pragma unroll
            for (int rr = 0; rr < 7; rr++) {
                float xv = xs[rclamp[rr]*LDSX + k];
                po[rr][0] += xv*w0; po[rr][1] += xv*w1; po[rr][2] += xv*w2;
            }
        }
        float* og = out + (size_t)bt * (NN*CDIM);
        #pragma unroll
        for (int rr = 0; rr < 7; rr++) {
            if (rrow[rr] < NN) {
                #pragma unroll
                for (int cc = 0; cc < 3; cc++)
                    og[rrow[rr]*CDIM + lane + 32*cc] = po[rr][cc];
            }
        }
    }
}

__global__ __launch_bounds__(256, 1)
void temporal_kernel(const float* __restrict__ x,
                     const float* __restrict__ qkv_w, const float* __restrict__ qkv_b,
                     const float* __restrict__ pw, const float* __restrict__ pb,
                     float* __restrict__ out)
{
    extern __shared__ float sm[];
    float* xs = sm;
    float* qs = xs + ROWS*LDSX;
    float* ks = qs + ROWS*LDSX;
    float* vs = ks + ROWS*LDSX;
    float* ws = vs + ROWS*LDSX;
    float* at = ws + 96*96;     // 7*3*8*8

    const int g    = blockIdx.x;
    const int b    = g / 7;
    const int n0   = (g - b*7) * 7;
    const int tid  = threadIdx.x;
    const int lane = tid & 31;
    const int warp = tid >> 5;

    // ---- load 7 sequences x 8 tokens: row r = sl*8 + t ----
    for (int idx = tid; idx < ROWS*CDIM; idx += 256) {
        int r = idx / CDIM, c = idx - r*CDIM;
        int sl = r >> 3, t = r & 7;
        xs[r*LDSX + c] = x[(((size_t)b*TT + t)*NN + (n0 + sl))*CDIM + c];
    }
    __syncthreads();

    // ---- QKV ----
    for (int wsel = 0; wsel < 3; wsel++) {
        for (int idx = tid; idx < 96*96; idx += 256) {
            int k = idx / 96, j = idx - k*96;
            ws[idx] = qkv_w[k*288 + wsel*96 + j];
        }
        __syncthreads();
        float acc[7][3];
        #pragma unroll
        for (int rr = 0; rr < 7; rr++) {
            #pragma unroll
            for (int cc = 0; cc < 3; cc++)
                acc[rr][cc] = qkv_b[wsel*96 + lane + 32*cc];
        }
        for (int k = 0; k < 96; k++) {
            float w0 = ws[k*96 + lane];
            float w1 = ws[k*96 + lane + 32];
            float w2 = ws[k*96 + lane + 64];
            #pragma unroll
            for (int rr = 0; rr < 7; rr++) {
                float xv = xs[(warp + 8*rr)*LDSX + k];
                acc[rr][0] += xv*w0; acc[rr][1] += xv*w1; acc[rr][2] += xv*w2;
            }
        }
        float* dst = (wsel == 0) ? qs : (wsel == 1) ? ks : vs;
        #pragma unroll
        for (int rr = 0; rr < 7; rr++) {
            #pragma unroll
            for (int cc = 0; cc < 3; cc++)
                dst[(warp + 8*rr)*LDSX + lane + 32*cc] = acc[rr][cc];
        }
        __syncthreads();
    }

    // ---- scores (no mask): 7 seqs * 3 heads * 8 * 8 ----
    const float scale = 0.17677669529663687f;
    for (int e = tid; e < 7*3*64; e += 256) {
        int sl  = e / 192;
        int rem = e - sl*192;
        int h   = rem >> 6;
        int ij  = rem & 63;
        int i   = ij >> 3, j = ij & 7;
        const float* qp = qs + (sl*8 + i)*LDSX + h*HD;
        const float* kp = ks + (sl*8 + j)*LDSX + h*HD;
        float s = 0.f;
        #pragma unroll
        for (int d = 0; d < HD; d++) s += qp[d]*kp[d];
        at[e] = s*scale;
    }
    __syncthreads();

    // ---- softmax: 168 rows of 8, one thread per row ----
    if (tid < 7*3*8) {
        float* arow = at + tid*8;
        float mx = arow[0];
        #pragma unroll
        for (int j = 1; j < 8; j++) mx = fmaxf(mx, arow[j]);
        float ev[8]; float s = 0.f;
        #pragma unroll
        for (int j = 0; j < 8; j++) { ev[j] = __expf(arow[j] - mx); s += ev[j]; }
        float inv = __frcp_rn(s);
        #pragma unroll
        for (int j = 0; j < 8; j++) arow[j] = ev[j]*inv;
    }
    __syncthreads();

    // ---- PV: r = warp + 8*rr -> sl = rr, i = warp ----
    {
        float acc[7][3];
        #pragma unroll
        for (int rr = 0; rr < 7; rr++) { acc[rr][0]=0.f; acc[rr][1]=0.f; acc[rr][2]=0.f; }
        #pragma unroll
        for (int j = 0; j < 8; j++) {
            #pragma unroll
            for (int rr = 0; rr < 7; rr++) {
                const float* vp = vs + (rr*8 + j)*LDSX + lane;
                int ab = rr*192 + warp*8 + j;
                acc[rr][0] += at[ab      ]*vp[0];
                acc[rr][1] += at[ab +  64]*vp[32];
                acc[rr][2] += at[ab + 128]*vp[64];
            }
        }
        #pragma unroll
        for (int rr = 0; rr < 7; rr++) {
            #pragma unroll
            for (int cc = 0; cc < 3; cc++)
                xs[(warp + 8*rr)*LDSX + lane + 32*cc] = acc[rr][cc];
        }
    }
    for (int idx = tid; idx < 96*96; idx += 256) ws[idx] = pw[idx];
    __syncthreads();

    // ---- projection + store to transposed x_t layout ----
    {
        float po[7][3];
        #pragma unroll
        for (int rr = 0; rr < 7; rr++) {
            #pragma unroll
            for (int cc = 0; cc < 3; cc++)
                po[rr][cc] = pb[lane + 32*cc];
        }
        for (int k = 0; k < 96; k++) {
            float w0 = ws[k*96 + lane];
            float w1 = ws[k*96 + lane + 32];
            float w2 = ws[k*96 + lane + 64];
            #pragma unroll
            for (int rr = 0; rr < 7; rr++) {
                float xv = xs[(warp + 8*rr)*LDSX + k];
                po[rr][0] += xv*w0; po[rr][1] += xv*w1; po[rr][2] += xv*w2;
            }
        }
        #pragma unroll
        for (int rr = 0; rr < 7; rr++) {
            // row r = warp + 8*rr : t = warp, n = n0 + rr
            float* og = out + (((size_t)b*TT + warp)*NN + (n0 + rr))*CDIM;
            #pragma unroll
            for (int cc = 0; cc < 3; cc++)
                og[lane + 32*cc] = po[rr][cc];
        }
    }
}

extern "C" void kernel_launch(void* const* d_in, const int* in_sizes, int n_in,
                              void* d_out, int out_size)
{
    const float* x      = (const float*)d_in[0];
    const float* mask   = (const float*)d_in[1];
    const float* qkv_w  = (const float*)d_in[2];
    const float* qkv_b  = (const float*)d_in[3];
    const float* psw    = (const float*)d_in[4];
    const float* psb    = (const float*)d_in[5];
    const float* ptw    = (const float*)d_in[6];
    const float* ptb    = (const float*)d_in[7];

    float* out_t  = (float*)d_out;                               // x_t  (tuple elem 0)
    float* out_sp = out_t + (size_t)BATCH*TT*NN*CDIM;            // x_sp (tuple elem 1)

    cudaFuncSetAttribute(spatial_kernel,  cudaFuncAttributeMaxDynamicSharedMemorySize, SMEM_SP);
    cudaFuncSetAttribute(temporal_kernel, cudaFuncAttributeMaxDynamicSharedMemorySize, SMEM_T);

    spatial_kernel<<<BATCH*TT, 256, SMEM_SP>>>(x, mask, qkv_w, qkv_b, psw, psb, out_sp);
    temporal_kernel<<<BATCH*7, 256, SMEM_T>>>(x, qkv_w, qkv_b, ptw, ptb, out_t);
}

// round 2
// speedup vs baseline: 1.7305x; 1.7305x over previous
#include <cuda_runtime.h>

#define BATCH   1024
#define TT      8
#define NN      49
#define CDIM    96
#define HEADS   3
#define HD      32
#define PADX    100     // row pad (floats): 16B aligned rows, conflict-free patterns
#define ATP     52      // score-row pad
#define SP_ROWS 49
#define T_ROWS  56

// smem bytes
#define SMEM_SP ((4*SP_ROWS*PADX + 48*96 + SP_ROWS*ATP) * 4)     // 107024
#define SMEM_T  ((4*T_ROWS*PADX  + 48*96 + 7*HEADS*64)  * 4)     // 113408

__global__ __launch_bounds__(256, 2)
void spatial_kernel(const float* __restrict__ x, const float* __restrict__ mask,
                    const float* __restrict__ qkv_w, const float* __restrict__ qkv_b,
                    const float* __restrict__ pw, const float* __restrict__ pb,
                    float* __restrict__ out)
{
    extern __shared__ float sm[];
    float* xs = sm;                        // 49 x 100 (reused for attn output)
    float* qs = xs + SP_ROWS*PADX;
    float* ks = qs + SP_ROWS*PADX;
    float* vs = ks + SP_ROWS*PADX;
    float* ws = vs + SP_ROWS*PADX;         // 48 x 96 weight half
    float* at = ws + 48*96;                // 49 x 52 per-head scores

    const int bt   = blockIdx.x;
    const int tid  = threadIdx.x;
    const int lane = tid & 31;
    const int warp = tid >> 5;

    // ---- load x (49x96), vectorized ----
    const float4* xg4 = (const float4*)(x + (size_t)bt * (NN*CDIM));
    for (int v = tid; v < NN*24; v += 256) {
        int r = v / 24, c4 = v - r*24;
        *(float4*)(xs + r*PADX + c4*4) = xg4[v];
    }
    __syncthreads();

    int rrow[7], rclamp[7];
    #pragma unroll
    for (int rr = 0; rr < 7; rr++) { rrow[rr] = warp + 8*rr; rclamp[rr] = min(rrow[rr], NN-1); }

    // ---- QKV: 3 chunks, each with w staged in two 48-row halves ----
    for (int wsel = 0; wsel < 3; wsel++) {
        float acc[7][3];
        #pragma unroll
        for (int rr = 0; rr < 7; rr++) {
            acc[rr][0] = qkv_b[wsel*96 + lane];
            acc[rr][1] = qkv_b[wsel*96 + lane + 32];
            acc[rr][2] = qkv_b[wsel*96 + lane + 64];
        }
        for (int half = 0; half < 2; half++) {
            __syncthreads();   // prior consumers of ws done
            for (int v = tid; v < 48*24; v += 256) {
                int kl = v / 24, j4 = v - kl*24;
                *(float4*)(ws + kl*96 + j4*4) =
                    *(const float4*)(qkv_w + (size_t)(half*48 + kl)*288 + wsel*96 + j4*4);
            }
            __syncthreads();
            const int kb = half*48;
            for (int k4 = 0; k4 < 48; k4 += 4) {
                float4 xv[7];
                #pragma unroll
                for (int rr = 0; rr < 7; rr++)
                    xv[rr] = *(const float4*)(xs + rclamp[rr]*PADX + kb + k4);
                #pragma unroll
                for (int dk = 0; dk < 4; dk++) {
                    float w0 = ws[(k4+dk)*96 + lane];
                    float w1 = ws[(k4+dk)*96 + lane + 32];
                    float w2 = ws[(k4+dk)*96 + lane + 64];
                    #pragma unroll
                    for (int rr = 0; rr < 7; rr++) {
                        float xvv = (&xv[rr].x)[dk];
                        acc[rr][0] += xvv*w0; acc[rr][1] += xvv*w1; acc[rr][2] += xvv*w2;
                    }
                }
            }
        }
        float* dst = (wsel == 0) ? qs : (wsel == 1) ? ks : vs;
        #pragma unroll
        for (int rr = 0; rr < 7; rr++) {       // clamped duplicates write identical values
            dst[rclamp[rr]*PADX + lane]      = acc[rr][0];
            dst[rclamp[rr]*PADX + lane + 32] = acc[rr][1];
            dst[rclamp[rr]*PADX + lane + 64] = acc[rr][2];
        }
    }
    __syncthreads();

    // ---- per-head: scores -> softmax -> PV ----
    const float scale = 0.17677669529663687f;
    const float* mrow = mask + (size_t)(bt & 63) * (49*49);
    for (int h = 0; h < HEADS; h++) {
        for (int e = tid; e < 49*49; e += 256) {
            int i = e / 49, j = e - i*49;
            const float4* qp = (const float4*)(qs + i*PADX + h*HD);
            const float4* kp = (const float4*)(ks + j*PADX + h*HD);
            float s = 0.f;
            #pragma unroll
            for (int d = 0; d < 8; d++) {
                float4 a = qp[d], b = kp[d];
                s += a.x*b.x + a.y*b.y + a.z*b.z + a.w*b.w;
            }
            at[i*ATP + j] = s*scale + mrow[e];
        }
        __syncthreads();

        for (int row = warp; row < 49; row += 8) {
            float* arow = at + row*ATP;
            float v0 = arow[lane];
            float v1 = (lane + 32 < 49) ? arow[lane + 32] : -3.0e38f;
            float mx = fmaxf(v0, v1);
            #pragma unroll
            for (int o = 16; o; o >>= 1) mx = fmaxf(mx, __shfl_xor_sync(0xffffffffu, mx, o));
            v0 = __expf(v0 - mx);
            v1 = (lane + 32 < 49) ? __expf(v1 - mx) : 0.f;
            float s = v0 + v1;
            #pragma unroll
            for (int o = 16; o; o >>= 1) s += __shfl_xor_sync(0xffffffffu, s, o);
            float inv = __frcp_rn(s);
            arow[lane] = v0*inv;
            if (lane + 32 < 49) arow[lane + 32] = v1*inv;
        }
        __syncthreads();

        float acc[7];
        #pragma unroll
        for (int rr = 0; rr < 7; rr++) acc[rr] = 0.f;
        for (int j4 = 0; j4 < 48; j4 += 4) {
            float4 a[7];
            #pragma unroll
            for (int rr = 0; rr < 7; rr++)
                a[rr] = *(const float4*)(at + rclamp[rr]*ATP + j4);
            #pragma unroll
            for (int dj = 0; dj < 4; dj++) {
                float v = vs[(j4+dj)*PADX + h*HD + lane];
                #pragma unroll
                for (int rr = 0; rr < 7; rr++)
                    acc[rr] += (&a[rr].x)[dj]*v;
            }
        }
        {
            float v = vs[48*PADX + h*HD + lane];
            #pragma unroll
            for (int rr = 0; rr < 7; rr++)
                acc[rr] += at[rclamp[rr]*ATP + 48]*v;
        }
        #pragma unroll
        for (int rr = 0; rr < 7; rr++)
            xs[rclamp[rr]*PADX + h*HD + lane] = acc[rr];
        __syncthreads();
    }

    // ---- output projection ----
    float po[7][3];
    #pragma unroll
    for (int rr = 0; rr < 7; rr++) {
        po[rr][0] = pb[lane]; po[rr][1] = pb[lane + 32]; po[rr][2] = pb[lane + 64];
    }
    for (int half = 0; half < 2; half++) {
        __syncthreads();
        for (int v = tid; v < 48*24; v += 256) {
            int kl = v / 24, j4 = v - kl*24;
            *(float4*)(ws + kl*96 + j4*4) =
                *(const float4*)(pw + (size_t)(half*48 + kl)*96 + j4*4);
        }
        __syncthreads();
        const int kb = half*48;
        for (int k4 = 0; k4 < 48; k4 += 4) {
            float4 xv[7];
            #pragma unroll
            for (int rr = 0; rr < 7; rr++)
                xv[rr] = *(const float4*)(xs + rclamp[rr]*PADX + kb + k4);
            #pragma unroll
            for (int dk = 0; dk < 4; dk++) {
                float w0 = ws[(k4+dk)*96 + lane];
                float w1 = ws[(k4+dk)*96 + lane + 32];
                float w2 = ws[(k4+dk)*96 + lane + 64];
                #pragma unroll
                for (int rr = 0; rr < 7; rr++) {
                    float xvv = (&xv[rr].x)[dk];
                    po[rr][0] += xvv*w0; po[rr][1] += xvv*w1; po[rr][2] += xvv*w2;
                }
            }
        }
    }
    float* og = out + (size_t)bt * (NN*CDIM);
    #pragma unroll
    for (int rr = 0; rr < 7; rr++) {
        if (rrow[rr] < NN) {
            og[rrow[rr]*CDIM + lane]      = po[rr][0];
            og[rrow[rr]*CDIM + lane + 32] = po[rr][1];
            og[rrow[rr]*CDIM + lane + 64] = po[rr][2];
        }
    }
}

__global__ __launch_bounds__(256, 2)
void temporal_kernel(const float* __restrict__ x,
                     const float* __restrict__ qkv_w, const float* __restrict__ qkv_b,
                     const float* __restrict__ pw, const float* __restrict__ pb,
                     float* __restrict__ out)
{
    extern __shared__ float sm[];
    float* xs = sm;                        // 56 x 100
    float* qs = xs + T_ROWS*PADX;
    float* ks = qs + T_ROWS*PADX;
    float* vs = ks + T_ROWS*PADX;
    float* ws = vs + T_ROWS*PADX;          // 48 x 96
    float* at = ws + 48*96;                // 7*3*64

    const int g    = blockIdx.x;
    const int b    = g / 7;
    const int n0   = (g - b*7) * 7;
    const int tid  = threadIdx.x;
    const int lane = tid & 31;
    const int warp = tid >> 5;

    // ---- load 7 seqs x 8 tokens (row r = sl*8 + t), vectorized ----
    for (int v = tid; v < T_ROWS*24; v += 256) {
        int r = v / 24, c4 = v - r*24;
        int sl = r >> 3, t = r & 7;
        *(float4*)(xs + r*PADX + c4*4) =
            *(const float4*)(x + (((size_t)b*TT + t)*NN + (n0 + sl))*CDIM + c4*4);
    }
    __syncthreads();

    // rows handled by this thread: r = warp + 8*rr  (sl = rr, t/i = warp)
    // ---- QKV ----
    for (int wsel = 0; wsel < 3; wsel++) {
        float acc[7][3];
        #pragma unroll
        for (int rr = 0; rr < 7; rr++) {
            acc[rr][0] = qkv_b[wsel*96 + lane];
            acc[rr][1] = qkv_b[wsel*96 + lane + 32];
            acc[rr][2] = qkv_b[wsel*96 + lane + 64];
        }
        for (int half = 0; half < 2; half++) {
            __syncthreads();
            for (int v = tid; v < 48*24; v += 256) {
                int kl = v / 24, j4 = v - kl*24;
                *(float4*)(ws + kl*96 + j4*4) =
                    *(const float4*)(qkv_w + (size_t)(half*48 + kl)*288 + wsel*96 + j4*4);
            }
            __syncthreads();
            const int kb = half*48;
            for (int k4 = 0; k4 < 48; k4 += 4) {
                float4 xv[7];
                #pragma unroll
                for (int rr = 0; rr < 7; rr++)
                    xv[rr] = *(const float4*)(xs + (warp + 8*rr)*PADX + kb + k4);
                #pragma unroll
                for (int dk = 0; dk < 4; dk++) {
                    float w0 = ws[(k4+dk)*96 + lane];
                    float w1 = ws[(k4+dk)*96 + lane + 32];
                    float w2 = ws[(k4+dk)*96 + lane + 64];
                    #pragma unroll
                    for (int rr = 0; rr < 7; rr++) {
                        float xvv = (&xv[rr].x)[dk];
                        acc[rr][0] += xvv*w0; acc[rr][1] += xvv*w1; acc[rr][2] += xvv*w2;
                    }
                }
            }
        }
        float* dst = (wsel == 0) ? qs : (wsel == 1) ? ks : vs;
        #pragma unroll
        for (int rr = 0; rr < 7; rr++) {
            dst[(warp + 8*rr)*PADX + lane]      = acc[rr][0];
            dst[(warp + 8*rr)*PADX + lane + 32] = acc[rr][1];
            dst[(warp + 8*rr)*PADX + lane + 64] = acc[rr][2];
        }
    }
    __syncthreads();

    // ---- scores (no mask): at[sl*192 + h*64 + i*8 + j] ----
    const float scale = 0.17677669529663687f;
    for (int e = tid; e < 7*HEADS*64; e += 256) {
        int sl  = e / 192;
        int rem = e - sl*192;
        int h   = rem >> 6;
        int ij  = rem & 63;
        int i   = ij >> 3, j = ij & 7;
        const float4* qp = (const float4*)(qs + (sl*8 + i)*PADX + h*HD);
        const float4* kp = (const float4*)(ks + (sl*8 + j)*PADX + h*HD);
        float s = 0.f;
        #pragma unroll
        for (int d = 0; d < 8; d++) {
            float4 a = qp[d], bb = kp[d];
            s += a.x*bb.x + a.y*bb.y + a.z*bb.z + a.w*bb.w;
        }
        at[e] = s*scale;
    }
    __syncthreads();

    // ---- softmax: 168 rows of 8, one thread per row ----
    if (tid < 7*HEADS*8) {
        float* arow = at + tid*8;
        float4 a0 = *(float4*)arow;
        float4 a1 = *(float4*)(arow + 4);
        float mx = fmaxf(fmaxf(fmaxf(a0.x, a0.y), fmaxf(a0.z, a0.w)),
                         fmaxf(fmaxf(a1.x, a1.y), fmaxf(a1.z, a1.w)));
        float e0 = __expf(a0.x - mx), e1 = __expf(a0.y - mx), e2 = __expf(a0.z - mx), e3 = __expf(a0.w - mx);
        float e4 = __expf(a1.x - mx), e5 = __expf(a1.y - mx), e6 = __expf(a1.z - mx), e7 = __expf(a1.w - mx);
        float inv = __frcp_rn(e0+e1+e2+e3+e4+e5+e6+e7);
        a0.x = e0*inv; a0.y = e1*inv; a0.z = e2*inv; a0.w = e3*inv;
        a1.x = e4*inv; a1.y = e5*inv; a1.z = e6*inv; a1.w = e7*inv;
        *(float4*)arow = a0;
        *(float4*)(arow + 4) = a1;
    }
    __syncthreads();

    // ---- PV, one sl at a time (i = warp) ----
    for (int rr = 0; rr < 7; rr++) {
        const float* atb = at + rr*192 + warp*8;
        float A0[8], A1[8], A2[8];
        *(float4*)A0     = *(const float4*)(atb);
        *(float4*)(A0+4) = *(const float4*)(atb + 4);
        *(float4*)A1     = *(const float4*)(atb + 64);
        *(float4*)(A1+4) = *(const float4*)(atb + 68);
        *(float4*)A2     = *(const float4*)(atb + 128);
        *(float4*)(A2+4) = *(const float4*)(atb + 132);
        float acc0 = 0.f, acc1 = 0.f, acc2 = 0.f;
        #pragma unroll
        for (int j = 0; j < 8; j++) {
            const float* vp = vs + (rr*8 + j)*PADX + lane;
            acc0 += A0[j]*vp[0];
            acc1 += A1[j]*vp[32];
            acc2 += A2[j]*vp[64];
        }
        xs[(warp + 8*rr)*PADX + lane]      = acc0;
        xs[(warp + 8*rr)*PADX + lane + 32] = acc1;
        xs[(warp + 8*rr)*PADX + lane + 64] = acc2;
    }

    // ---- projection ----
    float po[7][3];
    #pragma unroll
    for (int rr = 0; rr < 7; rr++) {
        po[rr][0] = pb[lane]; po[rr][1] = pb[lane + 32]; po[rr][2] = pb[lane + 64];
    }
    for (int half = 0; half < 2; half++) {
        __syncthreads();
        for (int v = tid; v < 48*24; v += 256) {
            int kl = v / 24, j4 = v - kl*24;
            *(float4*)(ws + kl*96 + j4*4) =
                *(const float4*)(pw + (size_t)(half*48 + kl)*96 + j4*4);
        }
        __syncthreads();
        const int kb = half*48;
        for (int k4 = 0; k4 < 48; k4 += 4) {
            float4 xv[7];
            #pragma unroll
            for (int rr = 0; rr < 7; rr++)
                xv[rr] = *(const float4*)(xs + (warp + 8*rr)*PADX + kb + k4);
            #pragma unroll
            for (int dk = 0; dk < 4; dk++) {
                float w0 = ws[(k4+dk)*96 + lane];
                float w1 = ws[(k4+dk)*96 + lane + 32];
                float w2 = ws[(k4+dk)*96 + lane + 64];
                #pragma unroll
                for (int rr = 0; rr < 7; rr++) {
                    float xvv = (&xv[rr].x)[dk];
                    po[rr][0] += xvv*w0; po[rr][1] += xvv*w1; po[rr][2] += xvv*w2;
                }
            }
        }
    }
    #pragma unroll
    for (int rr = 0; rr < 7; rr++) {
        float* og = out + (((size_t)b*TT + warp)*NN + (n0 + rr))*CDIM;
        og[lane]      = po[rr][0];
        og[lane + 32] = po[rr][1];
        og[lane + 64] = po[rr][2];
    }
}

extern "C" void kernel_launch(void* const* d_in, const int* in_sizes, int n_in,
                              void* d_out, int out_size)
{
    const float* x      = (const float*)d_in[0];
    const float* mask   = (const float*)d_in[1];
    const float* qkv_w  = (const float*)d_in[2];
    const float* qkv_b  = (const float*)d_in[3];
    const float* psw    = (const float*)d_in[4];
    const float* psb    = (const float*)d_in[5];
    const float* ptw    = (const float*)d_in[6];
    const float* ptb    = (const float*)d_in[7];

    float* out_t  = (float*)d_out;                        // x_t  (tuple elem 0)
    float* out_sp = out_t + (size_t)BATCH*TT*NN*CDIM;     // x_sp (tuple elem 1)

    cudaFuncSetAttribute(spatial_kernel,  cudaFuncAttributeMaxDynamicSharedMemorySize, SMEM_SP);
    cudaFuncSetAttribute(temporal_kernel, cudaFuncAttributeMaxDynamicSharedMemorySize, SMEM_T);

    spatial_kernel<<<BATCH*TT, 256, SMEM_SP>>>(x, mask, qkv_w, qkv_b, psw, psb, out_sp);
    temporal_kernel<<<BATCH*7, 256, SMEM_T>>>(x, qkv_w, qkv_b, ptw, ptb, out_t);
}

// round 4
// speedup vs baseline: 2.2637x; 1.3082x over previous
#include <cuda_runtime.h>

#define BATCH   1024
#define TT      8
#define NN      49
#define CDIM    96
#define HEADS   3
#define HD      32
#define PADX    100     // row pad (floats): 16B aligned rows
#define ATP     52      // score-row pad
#define NTOK    (BATCH*TT*NN)        // 401408 tokens
#define QKV_LD  288

// scratch: qkv for all tokens, layout [token][288] with token = (b*TT+t)*NN + n
__device__ float g_qkv[(size_t)NTOK * QKV_LD];

// smem bytes
#define SMEM_A ((64*PADX + 48*96) * 4)                                       // 44032
#define SMEM_SP ((3*NN*PADX + 48*96 + NN*ATP + NN*PADX) * 4)                 // 107024
#define SMEM_T  ((4*56*PADX + 48*96 + 7*HEADS*64) * 4)                       // 113408

// ============================ Kernel A: QKV GEMM ============================
// 64 tokens per block; thread = 8 rows (warp*8+rr) x 3 cols (lane+{0,32,64})
__global__ __launch_bounds__(256, 3)
void qkv_kernel(const float* __restrict__ x,
                const float* __restrict__ qkv_w, const float* __restrict__ qkv_b)
{
    extern __shared__ float sm[];
    float* xs = sm;              // 64 x 100
    float* ws = xs + 64*PADX;    // 48 x 96

    const int row0 = blockIdx.x * 64;
    const int tid  = threadIdx.x;
    const int lane = tid & 31;
    const int warp = tid >> 5;

    // load 64 token rows (64x96)
    const float4* xg4 = (const float4*)(x + (size_t)row0 * CDIM);
    for (int v = tid; v < 64*24; v += 256) {
        int r = v / 24, c4 = v - r*24;
        *(float4*)(xs + r*PADX + c4*4) = xg4[v];
    }

    for (int wsel = 0; wsel < 3; wsel++) {
        float acc[8][3];
        #pragma unroll
        for (int rr = 0; rr < 8; rr++) {
            acc[rr][0] = qkv_b[wsel*96 + lane];
            acc[rr][1] = qkv_b[wsel*96 + lane + 32];
            acc[rr][2] = qkv_b[wsel*96 + lane + 64];
        }
        #pragma unroll
        for (int half = 0; half < 2; half++) {
            __syncthreads();
            for (int v = tid; v < 48*24; v += 256) {
                int kl = v / 24, j4 = v - kl*24;
                *(float4*)(ws + kl*96 + j4*4) =
                    *(const float4*)(qkv_w + (size_t)(half*48 + kl)*QKV_LD + wsel*96 + j4*4);
            }
            __syncthreads();
            const int kb = half*48;
            for (int k4 = 0; k4 < 48; k4 += 4) {
                float4 xv[8];
                #pragma unroll
                for (int rr = 0; rr < 8; rr++)
                    xv[rr] = *(const float4*)(xs + (warp*8 + rr)*PADX + kb + k4);
                #pragma unroll
                for (int dk = 0; dk < 4; dk++) {
                    float w0 = ws[(k4+dk)*96 + lane];
                    float w1 = ws[(k4+dk)*96 + lane + 32];
                    float w2 = ws[(k4+dk)*96 + lane + 64];
                    #pragma unroll
                    for (int rr = 0; rr < 8; rr++) {
                        float xvv = (&xv[rr].x)[dk];
                        acc[rr][0] += xvv*w0; acc[rr][1] += xvv*w1; acc[rr][2] += xvv*w2;
                    }
                }
            }
        }
        #pragma unroll
        for (int rr = 0; rr < 8; rr++) {
            float* og = g_qkv + (size_t)(row0 + warp*8 + rr)*QKV_LD + wsel*96;
            og[lane]      = acc[rr][0];
            og[lane + 32] = acc[rr][1];
            og[lane + 64] = acc[rr][2];
        }
    }
}

// ======================= Kernel B: spatial attn + proj ======================
__global__ __launch_bounds__(256, 2)
void spatial_kernel(const float* __restrict__ mask,
                    const float* __restrict__ pw, const float* __restrict__ pb,
                    float* __restrict__ out)
{
    extern __shared__ float sm[];
    float* qs = sm;
    float* ks = qs + NN*PADX;
    float* vs = ks + NN*PADX;
    float* ws = vs + NN*PADX;    // 48 x 96
    float* at = ws + 48*96;      // 49 x 52
    float* xo = at + NN*ATP;     // 49 x 100 attn output

    const int bt   = blockIdx.x;
    const int tid  = threadIdx.x;
    const int lane = tid & 31;
    const int warp = tid >> 5;

    // ---- load q/k/v for 49 tokens ----
    const float* qg = g_qkv + (size_t)bt * NN * QKV_LD;
    for (int v = tid; v < NN*24; v += 256) {
        int r = v / 24, c4 = (v - r*24)*4;
        const float4* src = (const float4*)(qg + (size_t)r*QKV_LD + c4);
        *(float4*)(qs + r*PADX + c4) = src[0];
        *(float4*)(ks + r*PADX + c4) = src[24];     // +96 floats
        *(float4*)(vs + r*PADX + c4) = src[48];     // +192 floats
    }
    __syncthreads();

    int rrow[7], rclamp[7];
    #pragma unroll
    for (int rr = 0; rr < 7; rr++) { rrow[rr] = warp + 8*rr; rclamp[rr] = min(rrow[rr], NN-1); }

    // ---- per-head: scores -> softmax -> PV ----
    const float scale = 0.17677669529663687f;
    const float* mrow = mask + (size_t)(bt & 63) * (49*49);
    for (int h = 0; h < HEADS; h++) {
        for (int e = tid; e < 49*49; e += 256) {
            int i = e / 49, j = e - i*49;
            const float4* qp = (const float4*)(qs + i*PADX + h*HD);
            const float4* kp = (const float4*)(ks + j*PADX + h*HD);
            float s = 0.f;
            #pragma unroll
            for (int d = 0; d < 8; d++) {
                float4 a = qp[d], b = kp[d];
                s += a.x*b.x + a.y*b.y + a.z*b.z + a.w*b.w;
            }
            at[i*ATP + j] = s*scale + mrow[e];
        }
        __syncthreads();

        for (int row = warp; row < 49; row += 8) {
            float* arow = at + row*ATP;
            float v0 = arow[lane];
            float v1 = (lane + 32 < 49) ? arow[lane + 32] : -3.0e38f;
            float mx = fmaxf(v0, v1);
            #pragma unroll
            for (int o = 16; o; o >>= 1) mx = fmaxf(mx, __shfl_xor_sync(0xffffffffu, mx, o));
            v0 = __expf(v0 - mx);
            v1 = (lane + 32 < 49) ? __expf(v1 - mx) : 0.f;
            float s = v0 + v1;
            #pragma unroll
            for (int o = 16; o; o >>= 1) s += __shfl_xor_sync(0xffffffffu, s, o);
            float inv = __frcp_rn(s);
            arow[lane] = v0*inv;
            if (lane + 32 < 49) arow[lane + 32] = v1*inv;
        }
        __syncthreads();

        float acc[7];
        #pragma unroll
        for (int rr = 0; rr < 7; rr++) acc[rr] = 0.f;
        for (int j4 = 0; j4 < 48; j4 += 4) {
            float4 a[7];
            #pragma unroll
            for (int rr = 0; rr < 7; rr++)
                a[rr] = *(const float4*)(at + rclamp[rr]*ATP + j4);
            #pragma unroll
            for (int dj = 0; dj < 4; dj++) {
                float v = vs[(j4+dj)*PADX + h*HD + lane];
                #pragma unroll
                for (int rr = 0; rr < 7; rr++)
                    acc[rr] += (&a[rr].x)[dj]*v;
            }
        }
        {
            float v = vs[48*PADX + h*HD + lane];
            #pragma unroll
            for (int rr = 0; rr < 7; rr++)
                acc[rr] += at[rclamp[rr]*ATP + 48]*v;
        }
        #pragma unroll
        for (int rr = 0; rr < 7; rr++)
            xo[rclamp[rr]*PADX + h*HD + lane] = acc[rr];
        __syncthreads();
    }

    // ---- output projection ----
    float po[7][3];
    #pragma unroll
    for (int rr = 0; rr < 7; rr++) {
        po[rr][0] = pb[lane]; po[rr][1] = pb[lane + 32]; po[rr][2] = pb[lane + 64];
    }
    #pragma unroll
    for (int half = 0; half < 2; half++) {
        __syncthreads();
        for (int v = tid; v < 48*24; v += 256) {
            int kl = v / 24, j4 = v - kl*24;
            *(float4*)(ws + kl*96 + j4*4) =
                *(const float4*)(pw + (size_t)(half*48 + kl)*96 + j4*4);
        }
        __syncthreads();
        const int kb = half*48;
        for (int k4 = 0; k4 < 48; k4 += 4) {
            float4 xv[7];
            #pragma unroll
            for (int rr = 0; rr < 7; rr++)
                xv[rr] = *(const float4*)(xo + rclamp[rr]*PADX + kb + k4);
            #pragma unroll
            for (int dk = 0; dk < 4; dk++) {
                float w0 = ws[(k4+dk)*96 + lane];
                float w1 = ws[(k4+dk)*96 + lane + 32];
                float w2 = ws[(k4+dk)*96 + lane + 64];
                #pragma unroll
                for (int rr = 0; rr < 7; rr++) {
                    float xvv = (&xv[rr].x)[dk];
                    po[rr][0] += xvv*w0; po[rr][1] += xvv*w1; po[rr][2] += xvv*w2;
                }
            }
        }
    }
    float* og = out + (size_t)bt * (NN*CDIM);
    #pragma unroll
    for (int rr = 0; rr < 7; rr++) {
        if (rrow[rr] < NN) {
            og[rrow[rr]*CDIM + lane]      = po[rr][0];
            og[rrow[rr]*CDIM + lane + 32] = po[rr][1];
            og[rrow[rr]*CDIM + lane + 64] = po[rr][2];
        }
    }
}

// ====================== Kernel C: temporal attn + proj ======================
__global__ __launch_bounds__(256, 2)
void temporal_kernel(const float* __restrict__ pw, const float* __restrict__ pb,
                     float* __restrict__ out)
{
    extern __shared__ float sm[];
    float* qs = sm;
    float* ks = qs + 56*PADX;
    float* vs = ks + 56*PADX;
    float* xo = vs + 56*PADX;
    float* ws = xo + 56*PADX;    // 48 x 96
    float* at = ws + 48*96;      // 7*3*64

    const int g    = blockIdx.x;
    const int b    = g / 7;
    const int n0   = (g - b*7) * 7;
    const int tid  = threadIdx.x;
    const int lane = tid & 31;
    const int warp = tid >> 5;

    // ---- load q/k/v for 7 seqs x 8 tokens (row r = sl*8 + t) ----
    for (int v = tid; v < 56*24; v += 256) {
        int r = v / 24, c4 = (v - r*24)*4;
        int sl = r >> 3, t = r & 7;
        const float4* src = (const float4*)(g_qkv + (size_t)((b*TT + t)*NN + n0 + sl)*QKV_LD + c4);
        *(float4*)(qs + r*PADX + c4) = src[0];
        *(float4*)(ks + r*PADX + c4) = src[24];
        *(float4*)(vs + r*PADX + c4) = src[48];
    }
    __syncthreads();

    // ---- scores: at[sl*192 + h*64 + i*8 + j] ----
    const float scale = 0.17677669529663687f;
    for (int e = tid; e < 7*HEADS*64; e += 256) {
        int sl  = e / 192;
        int rem = e - sl*192;
        int h   = rem >> 6;
        int ij  = rem & 63;
        int i   = ij >> 3, j = ij & 7;
        const float4* qp = (const float4*)(qs + (sl*8 + i)*PADX + h*HD);
        const float4* kp = (const float4*)(ks + (sl*8 + j)*PADX + h*HD);
        float s = 0.f;
        #pragma unroll
        for (int d = 0; d < 8; d++) {
            float4 a = qp[d], bb = kp[d];
            s += a.x*bb.x + a.y*bb.y + a.z*bb.z + a.w*bb.w;
        }
        at[e] = s*scale;
    }
    __syncthreads();

    // ---- softmax: 168 rows of 8 ----
    if (tid < 7*HEADS*8) {
        float* arow = at + tid*8;
        float4 a0 = *(float4*)arow;
        float4 a1 = *(float4*)(arow + 4);
        float mx = fmaxf(fmaxf(fmaxf(a0.x, a0.y), fmaxf(a0.z, a0.w)),
                         fmaxf(fmaxf(a1.x, a1.y), fmaxf(a1.z, a1.w)));
        float e0 = __expf(a0.x - mx), e1 = __expf(a0.y - mx), e2 = __expf(a0.z - mx), e3 = __expf(a0.w - mx);
        float e4 = __expf(a1.x - mx), e5 = __expf(a1.y - mx), e6 = __expf(a1.z - mx), e7 = __expf(a1.w - mx);
        float inv = __frcp_rn(e0+e1+e2+e3+e4+e5+e6+e7);
        a0.x = e0*inv; a0.y = e1*inv; a0.z = e2*inv; a0.w = e3*inv;
        a1.x = e4*inv; a1.y = e5*inv; a1.z = e6*inv; a1.w = e7*inv;
        *(float4*)arow = a0;
        *(float4*)(arow + 4) = a1;
    }
    __syncthreads();

    // ---- PV (i = warp, sl = rr) ----
    for (int rr = 0; rr < 7; rr++) {
        const float* atb = at + rr*192 + warp*8;
        float A0[8], A1[8], A2[8];
        *(float4*)A0     = *(const float4*)(atb);
        *(float4*)(A0+4) = *(const float4*)(atb + 4);
        *(float4*)A1     = *(const float4*)(atb + 64);
        *(float4*)(A1+4) = *(const float4*)(atb + 68);
        *(float4*)A2     = *(const float4*)(atb + 128);
        *(float4*)(A2+4) = *(const float4*)(atb + 132);
        float acc0 = 0.f, acc1 = 0.f, acc2 = 0.f;
        #pragma unroll
        for (int j = 0; j < 8; j++) {
            const float* vp = vs + (rr*8 + j)*PADX + lane;
            acc0 += A0[j]*vp[0];
            acc1 += A1[j]*vp[32];
            acc2 += A2[j]*vp[64];
        }
        xo[(warp + 8*rr)*PADX + lane]      = acc0;
        xo[(warp + 8*rr)*PADX + lane + 32] = acc1;
        xo[(warp + 8*rr)*PADX + lane + 64] = acc2;
    }

    // ---- projection ----
    float po[7][3];
    #pragma unroll
    for (int rr = 0; rr < 7; rr++) {
        po[rr][0] = pb[lane]; po[rr][1] = pb[lane + 32]; po[rr][2] = pb[lane + 64];
    }
    #pragma unroll
    for (int half = 0; half < 2; half++) {
        __syncthreads();
        for (int v = tid; v < 48*24; v += 256) {
            int kl = v / 24, j4 = v - kl*24;
            *(float4*)(ws + kl*96 + j4*4) =
                *(const float4*)(pw + (size_t)(half*48 + kl)*96 + j4*4);
        }
        __syncthreads();
        const int kb = half*48;
        for (int k4 = 0; k4 < 48; k4 += 4) {
            float4 xv[7];
            #pragma unroll
            for (int rr = 0; rr < 7; rr++)
                xv[rr] = *(const float4*)(xo + (warp + 8*rr)*PADX + kb + k4);
            #pragma unroll
            for (int dk = 0; dk < 4; dk++) {
                float w0 = ws[(k4+dk)*96 + lane];
                float w1 = ws[(k4+dk)*96 + lane + 32];
                float w2 = ws[(k4+dk)*96 + lane + 64];
                #pragma unroll
                for (int rr = 0; rr < 7; rr++) {
                    float xvv = (&xv[rr].x)[dk];
                    po[rr][0] += xvv*w0; po[rr][1] += xvv*w1; po[rr][2] += xvv*w2;
                }
            }
        }
    }
    #pragma unroll
    for (int rr = 0; rr < 7; rr++) {
        float* og = out + (((size_t)b*TT + warp)*NN + (n0 + rr))*CDIM;
        og[lane]      = po[rr][0];
        og[lane + 32] = po[rr][1];
        og[lane + 64] = po[rr][2];
    }
}

extern "C" void kernel_launch(void* const* d_in, const int* in_sizes, int n_in,
                              void* d_out, int out_size)
{
    const float* x      = (const float*)d_in[0];
    const float* mask   = (const float*)d_in[1];
    const float* qkv_w  = (const float*)d_in[2];
    const float* qkv_b  = (const float*)d_in[3];
    const float* psw    = (const float*)d_in[4];
    const float* psb    = (const float*)d_in[5];
    const float* ptw    = (const float*)d_in[6];
    const float* ptb    = (const float*)d_in[7];

    float* out_t  = (float*)d_out;                        // x_t  (tuple elem 0)
    float* out_sp = out_t + (size_t)BATCH*TT*NN*CDIM;     // x_sp (tuple elem 1)

    cudaFuncSetAttribute(qkv_kernel,      cudaFuncAttributeMaxDynamicSharedMemorySize, SMEM_A);
    cudaFuncSetAttribute(spatial_kernel,  cudaFuncAttributeMaxDynamicSharedMemorySize, SMEM_SP);
    cudaFuncSetAttribute(temporal_kernel, cudaFuncAttributeMaxDynamicSharedMemorySize, SMEM_T);

    qkv_kernel<<<NTOK/64, 256, SMEM_A>>>(x, qkv_w, qkv_b);
    spatial_kernel<<<BATCH*TT, 256, SMEM_SP>>>(mask, psw, psb, out_sp);
    temporal_kernel<<<BATCH*7, 256, SMEM_T>>>(ptw, ptb, out_t);
}

// round 7
// speedup vs baseline: 2.7314x; 1.2066x over previous
#include <cuda_runtime.h>
#include <cuda_bf16.h>
#include <cstdint>

#define BATCH   1024
#define TT      8
#define NN      49
#define CDIM    96
#define HEADS   3
#define HD      32
#define PADX    100
#define ATP     52
#define NTOK    (BATCH*TT*NN)        // 401408 tokens = 3136 * 128
#define QKV_LD  288

__device__ float g_qkv[(size_t)NTOK * QKV_LD];

#define SMEM_SP ((3*NN*PADX + 48*96 + NN*ATP + NN*PADX) * 4)                 // 107024
#define SMEM_T  ((4*56*PADX + 48*96 + 7*HEADS*64) * 4)                       // 113408

// ---- qkv mma kernel smem layout (bytes) ----
#define LDA 104                     // bf16 row stride (208B: 16B-aligned, conflict-free LDSM)
#define QK_AHI   0                  // 128*104*2 = 26624
#define QK_ALO   26624
#define QK_BHI   53248              // 96*104*2 = 19968
#define QK_BLO   73216
#define QK_BIAS  93184              // 288 floats
#define SMEM_QKV 94336

// ======================= mma helpers (base ISA, no sm_103a features) =======================
__device__ __forceinline__ uint32_t smem_u32(const void* p) {
    uint32_t a;
    asm("{ .reg .u64 t; cvta.to.shared.u64 t, %1; cvt.u32.u64 %0, t; }" : "=r"(a) : "l"(p));
    return a;
}
__device__ __forceinline__ void ldsm4(uint32_t* r, uint32_t addr) {
    asm volatile("ldmatrix.sync.aligned.m8n8.x4.shared.b16 {%0,%1,%2,%3}, [%4];"
                 : "=r"(r[0]), "=r"(r[1]), "=r"(r[2]), "=r"(r[3]) : "r"(addr));
}
__device__ __forceinline__ void ldsm2t(uint32_t* r, uint32_t addr) {
    asm volatile("ldmatrix.sync.aligned.m8n8.x2.trans.shared.b16 {%0,%1}, [%2];"
                 : "=r"(r[0]), "=r"(r[1]) : "r"(addr));
}
__device__ __forceinline__ void mma16816(float* d, const uint32_t* a, const uint32_t* b) {
    asm volatile("mma.sync.aligned.m16n8k16.row.col.f32.bf16.bf16.f32 "
                 "{%0,%1,%2,%3}, {%4,%5,%6,%7}, {%8,%9}, {%0,%1,%2,%3};"
                 : "+f"(d[0]), "+f"(d[1]), "+f"(d[2]), "+f"(d[3])
                 : "r"(a[0]), "r"(a[1]), "r"(a[2]), "r"(a[3]), "r"(b[0]), "r"(b[1]));
}
__device__ __forceinline__ uint32_t bfpk(float a, float b) {
    __nv_bfloat162 h = __floats2bfloat162_rn(a, b);   // a -> low half
    return *(uint32_t*)&h;
}

// ================= Kernel A: QKV GEMM on HMMA (bf16 3-term split) =================
__global__ __launch_bounds__(256, 2)
void qkv_mma_kernel(const float* __restrict__ x,
                    const float* __restrict__ qkv_w, const float* __restrict__ qkv_b)
{
    extern __shared__ char smem[];
    const uint32_t sbase = smem_u32(smem);
    __nv_bfloat16* B_hi = (__nv_bfloat16*)(smem + QK_BHI);
    __nv_bfloat16* B_lo = (__nv_bfloat16*)(smem + QK_BLO);
    float* bias_sm = (float*)(smem + QK_BIAS);

    const int tid  = threadIdx.x;
    const int lane = tid & 31;
    const int warp = tid >> 5;
    const int row0 = blockIdx.x * 128;

    // ---- convert x tile (128x96) to bf16 hi/lo in smem ----
    for (int v = tid; v < 128*24; v += 256) {
        int r = v / 24, c = (v - (v/24)*24) * 4;
        float4 f = *(const float4*)(x + (size_t)(row0 + r)*96 + c);
        __nv_bfloat16 h0 = __float2bfloat16_rn(f.x), h1 = __float2bfloat16_rn(f.y);
        __nv_bfloat16 h2 = __float2bfloat16_rn(f.z), h3 = __float2bfloat16_rn(f.w);
        uint32_t off = (r*LDA + c)*2;
        *(uint32_t*)(smem + QK_AHI + off)     = bfpk(f.x, f.y) , 0;   // placeholder avoided below
        // (proper packing below)
        __nv_bfloat162 hp0 = __halves2bfloat162(h0, h1);
        __nv_bfloat162 hp1 = __halves2bfloat162(h2, h3);
        *(uint32_t*)(smem + QK_AHI + off)     = *(uint32_t*)&hp0;
        *(uint32_t*)(smem + QK_AHI + off + 4) = *(uint32_t*)&hp1;
        *(uint32_t*)(smem + QK_ALO + off)     = bfpk(f.x - __bfloat162float(h0), f.y - __bfloat162float(h1));
        *(uint32_t*)(smem + QK_ALO + off + 4) = bfpk(f.z - __bfloat162float(h2), f.w - __bfloat162float(h3));
    }
    for (int v = tid; v < 288; v += 256) bias_sm[v] = qkv_b[v];
    __syncthreads();

    // ---- load A fragments (persist across all chunks): 6 k-tiles, hi+lo ----
    uint32_t ah[6][4], al[6][4];
    {
        int arow = warp*16 + (lane & 15);
        int acol = (lane >> 4) * 8;
        #pragma unroll
        for (int kt = 0; kt < 6; kt++) {
            uint32_t boff = (arow*LDA + kt*16 + acol)*2;
            ldsm4(ah[kt], sbase + QK_AHI + boff);
            ldsm4(al[kt], sbase + QK_ALO + boff);
        }
    }

    for (int chunk = 0; chunk < 3; chunk++) {
        __syncthreads();   // prior chunk's LDSM of B done by all warps
        // ---- convert w chunk [96k x 96n] to bf16 hi/lo ----
        for (int v = tid; v < 96*96; v += 256) {
            int k = v / 96, n = v - (v/96)*96;
            float wv = qkv_w[(size_t)k*QKV_LD + chunk*96 + n];
            __nv_bfloat16 h = __float2bfloat16_rn(wv);
            B_hi[k*LDA + n] = h;
            B_lo[k*LDA + n] = __float2bfloat16_rn(wv - __bfloat162float(h));
        }
        __syncthreads();

        const int brow = lane & 15;
        #pragma unroll
        for (int nt = 0; nt < 12; nt++) {
            const int n0 = nt*8;
            uint32_t bh[6][2], bl[6][2];
            #pragma unroll
            for (int kt = 0; kt < 6; kt++) {
                uint32_t boff = ((kt*16 + brow)*LDA + n0)*2;
                ldsm2t(bh[kt], sbase + QK_BHI + boff);
                ldsm2t(bl[kt], sbase + QK_BLO + boff);
            }
            float acc[4] = {0.f, 0.f, 0.f, 0.f};
            #pragma unroll
            for (int kt = 0; kt < 6; kt++) {
                mma16816(acc, ah[kt], bh[kt]);
                mma16816(acc, al[kt], bh[kt]);
                mma16816(acc, ah[kt], bl[kt]);
            }
            // bias + store
            int r  = lane >> 2;
            int c2 = (lane & 3)*2;
            float2 bs = *(float2*)(bias_sm + chunk*96 + n0 + c2);
            size_t gb = (size_t)(row0 + warp*16 + r)*QKV_LD + chunk*96 + n0 + c2;
            float2 o0 = {acc[0] + bs.x, acc[1] + bs.y};
            float2 o1 = {acc[2] + bs.x, acc[3] + bs.y};
            *(float2*)(g_qkv + gb)            = o0;
            *(float2*)(g_qkv + gb + 8*QKV_LD) = o1;
        }
    }
}

// ======================= Kernel B: spatial attn + proj ======================
__global__ __launch_bounds__(256, 2)
void spatial_kernel(const float* __restrict__ mask,
                    const float* __restrict__ pw, const float* __restrict__ pb,
                    float* __restrict__ out)
{
    extern __shared__ float sm[];
    float* qs = sm;
    float* ks = qs + NN*PADX;
    float* vs = ks + NN*PADX;
    float* ws = vs + NN*PADX;    // 48 x 96
    float* at = ws + 48*96;      // 49 x 52
    float* xo = at + NN*ATP;     // 49 x 100

    const int bt   = blockIdx.x;
    const int tid  = threadIdx.x;
    const int lane = tid & 31;
    const int warp = tid >> 5;

    const float* qg = g_qkv + (size_t)bt * NN * QKV_LD;
    for (int v = tid; v < NN*24; v += 256) {
        int r = v / 24, c4 = (v - r*24)*4;
        const float4* src = (const float4*)(qg + (size_t)r*QKV_LD + c4);
        *(float4*)(qs + r*PADX + c4) = src[0];
        *(float4*)(ks + r*PADX + c4) = src[24];
        *(float4*)(vs + r*PADX + c4) = src[48];
    }
    __syncthreads();

    int rrow[7], rclamp[7];
    #pragma unroll
    for (int rr = 0; rr < 7; rr++) { rrow[rr] = warp + 8*rr; rclamp[rr] = min(rrow[rr], NN-1); }

    const float scale = 0.17677669529663687f;
    const float* mrow = mask + (size_t)(bt & 63) * (49*49);
    for (int h = 0; h < HEADS; h++) {
        for (int e = tid; e < 49*49; e += 256) {
            int i = e / 49, j = e - i*49;
            const float4* qp = (const float4*)(qs + i*PADX + h*HD);
            const float4* kp = (const float4*)(ks + j*PADX + h*HD);
            float s = 0.f;
            #pragma unroll
            for (int d = 0; d < 8; d++) {
                float4 a = qp[d], b = kp[d];
                s += a.x*b.x + a.y*b.y + a.z*b.z + a.w*b.w;
            }
            at[i*ATP + j] = s*scale + mrow[e];
        }
        __syncthreads();

        for (int row = warp; row < 49; row += 8) {
            float* arow = at + row*ATP;
            float v0 = arow[lane];
            float v1 = (lane + 32 < 49) ? arow[lane + 32] : -3.0e38f;
            float mx = fmaxf(v0, v1);
            #pragma unroll
            for (int o = 16; o; o >>= 1) mx = fmaxf(mx, __shfl_xor_sync(0xffffffffu, mx, o));
            v0 = __expf(v0 - mx);
            v1 = (lane + 32 < 49) ? __expf(v1 - mx) : 0.f;
            float s = v0 + v1;
            #pragma unroll
            for (int o = 16; o; o >>= 1) s += __shfl_xor_sync(0xffffffffu, s, o);
            float inv = __frcp_rn(s);
            arow[lane] = v0*inv;
            if (lane + 32 < 49) arow[lane + 32] = v1*inv;
        }
        __syncthreads();

        float acc[7];
        #pragma unroll
        for (int rr = 0; rr < 7; rr++) acc[rr] = 0.f;
        for (int j4 = 0; j4 < 48; j4 += 4) {
            float4 a[7];
            #pragma unroll
            for (int rr = 0; rr < 7; rr++)
                a[rr] = *(const float4*)(at + rclamp[rr]*ATP + j4);
            #pragma unroll
            for (int dj = 0; dj < 4; dj++) {
                float v = vs[(j4+dj)*PADX + h*HD + lane];
                #pragma unroll
                for (int rr = 0; rr < 7; rr++)
                    acc[rr] += (&a[rr].x)[dj]*v;
            }
        }
        {
            float v = vs[48*PADX + h*HD + lane];
            #pragma unroll
            for (int rr = 0; rr < 7; rr++)
                acc[rr] += at[rclamp[rr]*ATP + 48]*v;
        }
        #pragma unroll
        for (int rr = 0; rr < 7; rr++)
            xo[rclamp[rr]*PADX + h*HD + lane] = acc[rr];
        __syncthreads();
    }

    float po[7][3];
    #pragma unroll
    for (int rr = 0; rr < 7; rr++) {
        po[rr][0] = pb[lane]; po[rr][1] = pb[lane + 32]; po[rr][2] = pb[lane + 64];
    }
    #pragma unroll
    for (int half = 0; half < 2; half++) {
        __syncthreads();
        for (int v = tid; v < 48*24; v += 256) {
            int kl = v / 24, j4 = v - kl*24;
            *(float4*)(ws + kl*96 + j4*4) =
                *(const float4*)(pw + (size_t)(half*48 + kl)*96 + j4*4);
        }
        __syncthreads();
        const int kb = half*48;
        for (int k4 = 0; k4 < 48; k4 += 4) {
            float4 xv[7];
            #pragma unroll
            for (int rr = 0; rr < 7; rr++)
                xv[rr] = *(const float4*)(xo + rclamp[rr]*PADX + kb + k4);
            #pragma unroll
            for (int dk = 0; dk < 4; dk++) {
                float w0 = ws[(k4+dk)*96 + lane];
                float w1 = ws[(k4+dk)*96 + lane + 32];
                float w2 = ws[(k4+dk)*96 + lane + 64];
                #pragma unroll
                for (int rr = 0; rr < 7; rr++) {
                    float xvv = (&xv[rr].x)[dk];
                    po[rr][0] += xvv*w0; po[rr][1] += xvv*w1; po[rr][2] += xvv*w2;
                }
            }
        }
    }
    float* og = out + (size_t)bt * (NN*CDIM);
    #pragma unroll
    for (int rr = 0; rr < 7; rr++) {
        if (rrow[rr] < NN) {
            og[rrow[rr]*CDIM + lane]      = po[rr][0];
            og[rrow[rr]*CDIM + lane + 32] = po[rr][1];
            og[rrow[rr]*CDIM + lane + 64] = po[rr][2];
        }
    }
}

// ====================== Kernel C: temporal attn + proj ======================
__global__ __launch_bounds__(256, 2)
void temporal_kernel(const float* __restrict__ pw, const float* __restrict__ pb,
                     float* __restrict__ out)
{
    extern __shared__ float sm[];
    float* qs = sm;
    float* ks = qs + 56*PADX;
    float* vs = ks + 56*PADX;
    float* xo = vs + 56*PADX;
    float* ws = xo + 56*PADX;
    float* at = ws + 48*96;

    const int g    = blockIdx.x;
    const int b    = g / 7;
    const int n0   = (g - b*7) * 7;
    const int tid  = threadIdx.x;
    const int lane = tid & 31;
    const int warp = tid >> 5;

    for (int v = tid; v < 56*24; v += 256) {
        int r = v / 24, c4 = (v - r*24)*4;
        int sl = r >> 3, t = r & 7;
        const float4* src = (const float4*)(g_qkv + (size_t)((b*TT + t)*NN + n0 + sl)*QKV_LD + c4);
        *(float4*)(qs + r*PADX + c4) = src[0];
        *(float4*)(ks + r*PADX + c4) = src[24];
        *(float4*)(vs + r*PADX + c4) = src[48];
    }
    __syncthreads();

    const float scale = 0.17677669529663687f;
    for (int e = tid; e < 7*HEADS*64; e += 256) {
        int sl  = e / 192;
        int rem = e - sl*192;
        int h   = rem >> 6;
        int ij  = rem & 63;
        int i   = ij >> 3, j = ij & 7;
        const float4* qp = (const float4*)(qs + (sl*8 + i)*PADX + h*HD);
        const float4* kp = (const float4*)(ks + (sl*8 + j)*PADX + h*HD);
        float s = 0.f;
        #pragma unroll
        for (int d = 0; d < 8; d++) {
            float4 a = qp[d], bb = kp[d];
            s += a.x*bb.x + a.y*bb.y + a.z*bb.z + a.w*bb.w;
        }
        at[e] = s*scale;
    }
    __syncthreads();

    if (tid < 7*HEADS*8) {
        float* arow = at + tid*8;
        float4 a0 = *(float4*)arow;
        float4 a1 = *(float4*)(arow + 4);
        float mx = fmaxf(fmaxf(fmaxf(a0.x, a0.y), fmaxf(a0.z, a0.w)),
                         fmaxf(fmaxf(a1.x, a1.y), fmaxf(a1.z, a1.w)));
        float e0 = __expf(a0.x - mx), e1 = __expf(a0.y - mx), e2 = __expf(a0.z - mx), e3 = __expf(a0.w - mx);
        float e4 = __expf(a1.x - mx), e5 = __expf(a1.y - mx), e6 = __expf(a1.z - mx), e7 = __expf(a1.w - mx);
        float inv = __frcp_rn(e0+e1+e2+e3+e4+e5+e6+e7);
        a0.x = e0*inv; a0.y = e1*inv; a0.z = e2*inv; a0.w = e3*inv;
        a1.x = e4*inv; a1.y = e5*inv; a1.z = e6*inv; a1.w = e7*inv;
        *(float4*)arow = a0;
        *(float4*)(arow + 4) = a1;
    }
    __syncthreads();

    for (int rr = 0; rr < 7; rr++) {
        const float* atb = at + rr*192 + warp*8;
        float A0[8], A1[8], A2[8];
        *(float4*)A0     = *(const float4*)(atb);
        *(float4*)(A0+4) = *(const float4*)(atb + 4);
        *(float4*)A1     = *(const float4*)(atb + 64);
        *(float4*)(A1+4) = *(const float4*)(atb + 68);
        *(float4*)A2     = *(const float4*)(atb + 128);
        *(float4*)(A2+4) = *(const float4*)(atb + 132);
        float acc0 = 0.f, acc1 = 0.f, acc2 = 0.f;
        #pragma unroll
        for (int j = 0; j < 8; j++) {
            const float* vp = vs + (rr*8 + j)*PADX + lane;
            acc0 += A0[j]*vp[0];
            acc1 += A1[j]*vp[32];
            acc2 += A2[j]*vp[64];
        }
        xo[(warp + 8*rr)*PADX + lane]      = acc0;
        xo[(warp + 8*rr)*PADX + lane + 32] = acc1;
        xo[(warp + 8*rr)*PADX + lane + 64] = acc2;
    }

    float po[7][3];
    #pragma unroll
    for (int rr = 0; rr < 7; rr++) {
        po[rr][0] = pb[lane]; po[rr][1] = pb[lane + 32]; po[rr][2] = pb[lane + 64];
    }
    #pragma unroll
    for (int half = 0; half < 2; half++) {
        __syncthreads();
        for (int v = tid; v < 48*24; v += 256) {
            int kl = v / 24, j4 = v - kl*24;
            *(float4*)(ws + kl*96 + j4*4) =
                *(const float4*)(pw + (size_t)(half*48 + kl)*96 + j4*4);
        }
        __syncthreads();
        const int kb = half*48;
        for (int k4 = 0; k4 < 48; k4 += 4) {
            float4 xv[7];
            #pragma unroll
            for (int rr = 0; rr < 7; rr++)
                xv[rr] = *(const float4*)(xo + (warp + 8*rr)*PADX + kb + k4);
            #pragma unroll
            for (int dk = 0; dk < 4; dk++) {
                float w0 = ws[(k4+dk)*96 + lane];
                float w1 = ws[(k4+dk)*96 + lane + 32];
                float w2 = ws[(k4+dk)*96 + lane + 64];
                #pragma unroll
                for (int rr = 0; rr < 7; rr++) {
                    float xvv = (&xv[rr].x)[dk];
                    po[rr][0] += xvv*w0; po[rr][1] += xvv*w1; po[rr][2] += xvv*w2;
                }
            }
        }
    }
    #pragma unroll
    for (int rr = 0; rr < 7; rr++) {
        float* og = out + (((size_t)b*TT + warp)*NN + (n0 + rr))*CDIM;
        og[lane]      = po[rr][0];
        og[lane + 32] = po[rr][1];
        og[lane + 64] = po[rr][2];
    }
}

extern "C" void kernel_launch(void* const* d_in, const int* in_sizes, int n_in,
                              void* d_out, int out_size)
{
    const float* x      = (const float*)d_in[0];
    const float* mask   = (const float*)d_in[1];
    const float* qkv_w  = (const float*)d_in[2];
    const float* qkv_b  = (const float*)d_in[3];
    const float* psw    = (const float*)d_in[4];
    const float* psb    = (const float*)d_in[5];
    const float* ptw    = (const float*)d_in[6];
    const float* ptb    = (const float*)d_in[7];

    float* out_t  = (float*)d_out;
    float* out_sp = out_t + (size_t)BATCH*TT*NN*CDIM;

    cudaFuncSetAttribute(qkv_mma_kernel,  cudaFuncAttributeMaxDynamicSharedMemorySize, SMEM_QKV);
    cudaFuncSetAttribute(spatial_kernel,  cudaFuncAttributeMaxDynamicSharedMemorySize, SMEM_SP);
    cudaFuncSetAttribute(temporal_kernel, cudaFuncAttributeMaxDynamicSharedMemorySize, SMEM_T);

    qkv_mma_kernel<<<NTOK/128, 256, SMEM_QKV>>>(x, qkv_w, qkv_b);
    spatial_kernel<<<BATCH*TT, 256, SMEM_SP>>>(mask, psw, psb, out_sp);
    temporal_kernel<<<BATCH*7, 256, SMEM_T>>>(ptw, ptb, out_t);
}

// round 9
// speedup vs baseline: 2.8451x; 1.0416x over previous
#include <cuda_runtime.h>
#include <cuda_bf16.h>
#include <cstdint>

#define BATCH   1024
#define TT      8
#define NN      49
#define CDIM    96
#define HEADS   3
#define HD      32
#define PADX    100
#define ATP     52
#define NTOK    (BATCH*TT*NN)        // 401408 tokens = 3136 * 128
#define QKV_LD  288
#define LDA     104                  // bf16 row stride

__device__ float g_qkv[(size_t)NTOK * QKV_LD];

// ---- qkv mma kernel smem layout (bytes) ----
#define QK_AHI   0                  // 128*104*2 = 26624
#define QK_ALO   26624
#define QK_BHI   53248              // 96*104*2 = 19968
#define QK_BLO   73216
#define QK_BIAS  93184              // 288 floats
#define SMEM_QKV 94336

// ---- spatial smem (bytes) ----
#define SP_QS    0                  // 49*100 f
#define SP_KS    19600
#define SP_VS    39200
#define SP_AT    58800              // 49*52 f
#define SP_XOH   68992              // bf16 49*104
#define SP_XOL   79184
#define SP_WH    89376              // bf16 32*104
#define SP_WL    96032
#define SMEM_SP  102688

// ---- temporal smem (bytes) ----
#define T_QS     0                  // 56*100 f
#define T_KS     22400
#define T_VS     44800
#define T_AT     67200              // 1344 f
#define T_XOH    72576              // bf16 56*104
#define T_XOL    84224
#define T_WH     95872              // bf16 32*104
#define T_WL     102528
#define SMEM_T   109184

// ======================= mma helpers (base ISA) =======================
__device__ __forceinline__ uint32_t smem_u32(const void* p) {
    uint32_t a;
    asm("{ .reg .u64 t; cvta.to.shared.u64 t, %1; cvt.u32.u64 %0, t; }" : "=r"(a) : "l"(p));
    return a;
}
__device__ __forceinline__ void ldsm4(uint32_t* r, uint32_t addr) {
    asm volatile("ldmatrix.sync.aligned.m8n8.x4.shared.b16 {%0,%1,%2,%3}, [%4];"
                 : "=r"(r[0]), "=r"(r[1]), "=r"(r[2]), "=r"(r[3]) : "r"(addr));
}
__device__ __forceinline__ void ldsm2t(uint32_t* r, uint32_t addr) {
    asm volatile("ldmatrix.sync.aligned.m8n8.x2.trans.shared.b16 {%0,%1}, [%2];"
                 : "=r"(r[0]), "=r"(r[1]) : "r"(addr));
}
__device__ __forceinline__ void mma16816(float* d, const uint32_t* a, const uint32_t* b) {
    asm volatile("mma.sync.aligned.m16n8k16.row.col.f32.bf16.bf16.f32 "
                 "{%0,%1,%2,%3}, {%4,%5,%6,%7}, {%8,%9}, {%0,%1,%2,%3};"
                 : "+f"(d[0]), "+f"(d[1]), "+f"(d[2]), "+f"(d[3])
                 : "r"(a[0]), "r"(a[1]), "r"(a[2]), "r"(a[3]), "r"(b[0]), "r"(b[1]));
}
__device__ __forceinline__ uint32_t bfpk(float a, float b) {
    __nv_bfloat162 h = __floats2bfloat162_rn(a, b);
    return *(uint32_t*)&h;
}
__device__ __forceinline__ void split_store(char* hi, char* lo, int idx, float v) {
    __nv_bfloat16 h = __float2bfloat16_rn(v);
    ((__nv_bfloat16*)hi)[idx] = h;
    ((__nv_bfloat16*)lo)[idx] = __float2bfloat16_rn(v - __bfloat162float(h));
}

// ================= Kernel A: QKV GEMM on HMMA (bf16 3-term split) =================
__global__ __launch_bounds__(256, 2)
void qkv_mma_kernel(const float* __restrict__ x,
                    const float* __restrict__ qkv_w, const float* __restrict__ qkv_b)
{
    extern __shared__ char smem[];
    const uint32_t sbase = smem_u32(smem);
    __nv_bfloat16* B_hi = (__nv_bfloat16*)(smem + QK_BHI);
    __nv_bfloat16* B_lo = (__nv_bfloat16*)(smem + QK_BLO);
    float* bias_sm = (float*)(smem + QK_BIAS);

    const int tid  = threadIdx.x;
    const int lane = tid & 31;
    const int warp = tid >> 5;
    const int row0 = blockIdx.x * 128;

    for (int v = tid; v < 128*24; v += 256) {
        int r = v / 24, c = (v - (v/24)*24) * 4;
        float4 f = *(const float4*)(x + (size_t)(row0 + r)*96 + c);
        __nv_bfloat16 h0 = __float2bfloat16_rn(f.x), h1 = __float2bfloat16_rn(f.y);
        __nv_bfloat16 h2 = __float2bfloat16_rn(f.z), h3 = __float2bfloat16_rn(f.w);
        uint32_t off = (r*LDA + c)*2;
        __nv_bfloat162 hp0 = __halves2bfloat162(h0, h1);
        __nv_bfloat162 hp1 = __halves2bfloat162(h2, h3);
        *(uint32_t*)(smem + QK_AHI + off)     = *(uint32_t*)&hp0;
        *(uint32_t*)(smem + QK_AHI + off + 4) = *(uint32_t*)&hp1;
        *(uint32_t*)(smem + QK_ALO + off)     = bfpk(f.x - __bfloat162float(h0), f.y - __bfloat162float(h1));
        *(uint32_t*)(smem + QK_ALO + off + 4) = bfpk(f.z - __bfloat162float(h2), f.w - __bfloat162float(h3));
    }
    for (int v = tid; v < 288; v += 256) bias_sm[v] = qkv_b[v];
    __syncthreads();

    uint32_t ah[6][4], al[6][4];
    {
        int arow = warp*16 + (lane & 15);
        int acol = (lane >> 4) * 8;
        #pragma unroll
        for (int kt = 0; kt < 6; kt++) {
            uint32_t boff = (arow*LDA + kt*16 + acol)*2;
            ldsm4(ah[kt], sbase + QK_AHI + boff);
            ldsm4(al[kt], sbase + QK_ALO + boff);
        }
    }

    for (int chunk = 0; chunk < 3; chunk++) {
        __syncthreads();
        for (int v = tid; v < 96*96; v += 256) {
            int k = v / 96, n = v - (v/96)*96;
            float wv = qkv_w[(size_t)k*QKV_LD + chunk*96 + n];
            __nv_bfloat16 h = __float2bfloat16_rn(wv);
            B_hi[k*LDA + n] = h;
            B_lo[k*LDA + n] = __float2bfloat16_rn(wv - __bfloat162float(h));
        }
        __syncthreads();

        const int brow = lane & 15;
        #pragma unroll
        for (int nt = 0; nt < 12; nt++) {
            const int n0 = nt*8;
            uint32_t bh[6][2], bl[6][2];
            #pragma unroll
            for (int kt = 0; kt < 6; kt++) {
                uint32_t boff = ((kt*16 + brow)*LDA + n0)*2;
                ldsm2t(bh[kt], sbase + QK_BHI + boff);
                ldsm2t(bl[kt], sbase + QK_BLO + boff);
            }
            float acc[4] = {0.f, 0.f, 0.f, 0.f};
            #pragma unroll
            for (int kt = 0; kt < 6; kt++) {
                mma16816(acc, ah[kt], bh[kt]);
                mma16816(acc, al[kt], bh[kt]);
                mma16816(acc, ah[kt], bl[kt]);
            }
            int r  = lane >> 2;
            int c2 = (lane & 3)*2;
            float2 bs = *(float2*)(bias_sm + chunk*96 + n0 + c2);
            size_t gb = (size_t)(row0 + warp*16 + r)*QKV_LD + chunk*96 + n0 + c2;
            float2 o0 = {acc[0] + bs.x, acc[1] + bs.y};
            float2 o1 = {acc[2] + bs.x, acc[3] + bs.y};
            *(float2*)(g_qkv + gb)            = o0;
            *(float2*)(g_qkv + gb + 8*QKV_LD) = o1;
        }
    }
}

// ======================= Kernel B: spatial attn + HMMA proj ======================
__global__ __launch_bounds__(256, 2)
void spatial_kernel(const float* __restrict__ mask,
                    const float* __restrict__ pw, const float* __restrict__ pb,
                    float* __restrict__ out)
{
    extern __shared__ char smc[];
    const uint32_t sbase = smem_u32(smc);
    float* qs = (float*)(smc + SP_QS);
    float* ks = (float*)(smc + SP_KS);
    float* vs = (float*)(smc + SP_VS);
    float* at = (float*)(smc + SP_AT);
    char*  xoh = smc + SP_XOH;
    char*  xol = smc + SP_XOL;
    __nv_bfloat16* wh = (__nv_bfloat16*)(smc + SP_WH);
    __nv_bfloat16* wl = (__nv_bfloat16*)(smc + SP_WL);

    const int bt   = blockIdx.x;
    const int tid  = threadIdx.x;
    const int lane = tid & 31;
    const int warp = tid >> 5;

    const float* qg = g_qkv + (size_t)bt * NN * QKV_LD;
    for (int v = tid; v < NN*24; v += 256) {
        int r = v / 24, c4 = (v - r*24)*4;
        const float4* src = (const float4*)(qg + (size_t)r*QKV_LD + c4);
        *(float4*)(qs + r*PADX + c4) = src[0];
        *(float4*)(ks + r*PADX + c4) = src[24];
        *(float4*)(vs + r*PADX + c4) = src[48];
    }
    __syncthreads();

    int rclamp[7];
    #pragma unroll
    for (int rr = 0; rr < 7; rr++) rclamp[rr] = min(warp + 8*rr, NN-1);

    const float scale = 0.17677669529663687f;
    const float* mrow = mask + (size_t)(bt & 63) * (49*49);
    for (int h = 0; h < HEADS; h++) {
        for (int e = tid; e < 49*49; e += 256) {
            int i = e / 49, j = e - i*49;
            const float4* qp = (const float4*)(qs + i*PADX + h*HD);
            const float4* kp = (const float4*)(ks + j*PADX + h*HD);
            float s = 0.f;
            #pragma unroll
            for (int d = 0; d < 8; d++) {
                float4 a = qp[d], b = kp[d];
                s += a.x*b.x + a.y*b.y + a.z*b.z + a.w*b.w;
            }
            at[i*ATP + j] = s*scale + mrow[e];
        }
        __syncthreads();

        for (int row = warp; row < 49; row += 8) {
            float* arow = at + row*ATP;
            float v0 = arow[lane];
            float v1 = (lane + 32 < 49) ? arow[lane + 32] : -3.0e38f;
            float mx = fmaxf(v0, v1);
            #pragma unroll
            for (int o = 16; o; o >>= 1) mx = fmaxf(mx, __shfl_xor_sync(0xffffffffu, mx, o));
            v0 = __expf(v0 - mx);
            v1 = (lane + 32 < 49) ? __expf(v1 - mx) : 0.f;
            float s = v0 + v1;
            #pragma unroll
            for (int o = 16; o; o >>= 1) s += __shfl_xor_sync(0xffffffffu, s, o);
            float inv = __frcp_rn(s);
            arow[lane] = v0*inv;
            if (lane + 32 < 49) arow[lane + 32] = v1*inv;
        }
        __syncthreads();

        float acc[7];
        #pragma unroll
        for (int rr = 0; rr < 7; rr++) acc[rr] = 0.f;
        for (int j4 = 0; j4 < 48; j4 += 4) {
            float4 a[7];
            #pragma unroll
            for (int rr = 0; rr < 7; rr++)
                a[rr] = *(const float4*)(at + rclamp[rr]*ATP + j4);
            #pragma unroll
            for (int dj = 0; dj < 4; dj++) {
                float v = vs[(j4+dj)*PADX + h*HD + lane];
                #pragma unroll
                for (int rr = 0; rr < 7; rr++)
                    acc[rr] += (&a[rr].x)[dj]*v;
            }
        }
        {
            float v = vs[48*PADX + h*HD + lane];
            #pragma unroll
            for (int rr = 0; rr < 7; rr++)
                acc[rr] += at[rclamp[rr]*ATP + 48]*v;
        }
        #pragma unroll
        for (int rr = 0; rr < 7; rr++)
            split_store(xoh, xol, rclamp[rr]*LDA + h*HD + lane, acc[rr]);
        __syncthreads();
    }

    // ---- HMMA projection: 4 M-tiles {0,16,32,33} x 2 N-halves ----
    const int wt = warp >> 1;
    const int nh = (warp & 1) * 48;
    const int r0 = (wt == 3) ? 33 : wt*16;

    float acc[6][4];
    #pragma unroll
    for (int nt = 0; nt < 6; nt++)
        acc[nt][0] = acc[nt][1] = acc[nt][2] = acc[nt][3] = 0.f;

    for (int s = 0; s < 3; s++) {
        __syncthreads();
        for (int v = tid; v < 32*96; v += 256) {
            int kl = v / 96, n = v - (v/96)*96;
            float wv = pw[(size_t)(s*32 + kl)*96 + n];
            __nv_bfloat16 h = __float2bfloat16_rn(wv);
            wh[kl*LDA + n] = h;
            wl[kl*LDA + n] = __float2bfloat16_rn(wv - __bfloat162float(h));
        }
        __syncthreads();

        uint32_t ah[2][4], al[2][4];
        int arow = r0 + (lane & 15);
        int acol = (lane >> 4)*8;
        #pragma unroll
        for (int kt = 0; kt < 2; kt++) {
            uint32_t off = (arow*LDA + s*32 + kt*16 + acol)*2;
            ldsm4(ah[kt], sbase + SP_XOH + off);
            ldsm4(al[kt], sbase + SP_XOL + off);
        }
        #pragma unroll
        for (int nt = 0; nt < 6; nt++) {
            uint32_t bh[2][2], bl[2][2];
            #pragma unroll
            for (int kt = 0; kt < 2; kt++) {
                uint32_t off = ((kt*16 + (lane & 15))*LDA + nh + nt*8)*2;
                ldsm2t(bh[kt], sbase + SP_WH + off);
                ldsm2t(bl[kt], sbase + SP_WL + off);
            }
            #pragma unroll
            for (int kt = 0; kt < 2; kt++) {
                mma16816(acc[nt], ah[kt], bh[kt]);
                mma16816(acc[nt], al[kt], bh[kt]);
                mma16816(acc[nt], ah[kt], bl[kt]);
            }
        }
    }

    float* og = out + (size_t)bt * (NN*CDIM);
    const int r  = lane >> 2;
    const int c2 = (lane & 3)*2;
    #pragma unroll
    for (int nt = 0; nt < 6; nt++) {
        int col = nh + nt*8 + c2;
        float2 bs = {pb[col], pb[col+1]};
        int ra = r0 + r, rb = r0 + r + 8;
        if (ra < NN) { og[ra*CDIM + col] = acc[nt][0] + bs.x; og[ra*CDIM + col + 1] = acc[nt][1] + bs.y; }
        if (rb < NN) { og[rb*CDIM + col] = acc[nt][2] + bs.x; og[rb*CDIM + col + 1] = acc[nt][3] + bs.y; }
    }
}

// ====================== Kernel C: temporal attn + HMMA proj ======================
__global__ __launch_bounds__(256, 2)
void temporal_kernel(const float* __restrict__ pw, const float* __restrict__ pb,
                     float* __restrict__ out)
{
    extern __shared__ char smc[];
    const uint32_t sbase = smem_u32(smc);
    float* qs = (float*)(smc + T_QS);
    float* ks = (float*)(smc + T_KS);
    float* vs = (float*)(smc + T_VS);
    float* at = (float*)(smc + T_AT);
    char*  xoh = smc + T_XOH;
    char*  xol = smc + T_XOL;
    __nv_bfloat16* wh = (__nv_bfloat16*)(smc + T_WH);
    __nv_bfloat16* wl = (__nv_bfloat16*)(smc + T_WL);

    const int g    = blockIdx.x;
    const int b    = g / 7;
    const int n0   = (g - b*7) * 7;
    const int tid  = threadIdx.x;
    const int lane = tid & 31;
    const int warp = tid >> 5;

    for (int v = tid; v < 56*24; v += 256) {
        int r = v / 24, c4 = (v - r*24)*4;
        int sl = r >> 3, t = r & 7;
        const float4* src = (const float4*)(g_qkv + (size_t)((b*TT + t)*NN + n0 + sl)*QKV_LD + c4);
        *(float4*)(qs + r*PADX + c4) = src[0];
        *(float4*)(ks + r*PADX + c4) = src[24];
        *(float4*)(vs + r*PADX + c4) = src[48];
    }
    __syncthreads();

    const float scale = 0.17677669529663687f;
    for (int e = tid; e < 7*HEADS*64; e += 256) {
        int sl  = e / 192;
        int rem = e - sl*192;
        int h   = rem >> 6;
        int ij  = rem & 63;
        int i   = ij >> 3, j = ij & 7;
        const float4* qp = (const float4*)(qs + (sl*8 + i)*PADX + h*HD);
        const float4* kp = (const float4*)(ks + (sl*8 + j)*PADX + h*HD);
        float s = 0.f;
        #pragma unroll
        for (int d = 0; d < 8; d++) {
            float4 a = qp[d], bb = kp[d];
            s += a.x*bb.x + a.y*bb.y + a.z*bb.z + a.w*bb.w;
        }
        at[e] = s*scale;
    }
    __syncthreads();

    if (tid < 7*HEADS*8) {
        float* arow = at + tid*8;
        float4 a0 = *(float4*)arow;
        float4 a1 = *(float4*)(arow + 4);
        float mx = fmaxf(fmaxf(fmaxf(a0.x, a0.y), fmaxf(a0.z, a0.w)),
                         fmaxf(fmaxf(a1.x, a1.y), fmaxf(a1.z, a1.w)));
        float e0 = __expf(a0.x - mx), e1 = __expf(a0.y - mx), e2 = __expf(a0.z - mx), e3 = __expf(a0.w - mx);
        float e4 = __expf(a1.x - mx), e5 = __expf(a1.y - mx), e6 = __expf(a1.z - mx), e7 = __expf(a1.w - mx);
        float inv = __frcp_rn(e0+e1+e2+e3+e4+e5+e6+e7);
        a0.x = e0*inv; a0.y = e1*inv; a0.z = e2*inv; a0.w = e3*inv;
        a1.x = e4*inv; a1.y = e5*inv; a1.z = e6*inv; a1.w = e7*inv;
        *(float4*)arow = a0;
        *(float4*)(arow + 4) = a1;
    }
    __syncthreads();

    for (int rr = 0; rr < 7; rr++) {
        const float* atb = at + rr*192 + warp*8;
        float A0[8], A1[8], A2[8];
        *(float4*)A0     = *(const float4*)(atb);
        *(float4*)(A0+4) = *(const float4*)(atb + 4);
        *(float4*)A1     = *(const float4*)(atb + 64);
        *(float4*)(A1+4) = *(const float4*)(atb + 68);
        *(float4*)A2     = *(const float4*)(atb + 128);
        *(float4*)(A2+4) = *(const float4*)(atb + 132);
        float acc0 = 0.f, acc1 = 0.f, acc2 = 0.f;
        #pragma unroll
        for (int j = 0; j < 8; j++) {
            const float* vp = vs + (rr*8 + j)*PADX + lane;
            acc0 += A0[j]*vp[0];
            acc1 += A1[j]*vp[32];
            acc2 += A2[j]*vp[64];
        }
        int row = warp + 8*rr;
        split_store(xoh, xol, row*LDA + lane,      acc0);
        split_store(xoh, xol, row*LDA + lane + 32, acc1);
        split_store(xoh, xol, row*LDA + lane + 64, acc2);
    }

    // ---- HMMA projection: 4 M-tiles {0,16,32,40} x 2 N-halves ----
    const int wt = warp >> 1;
    const int nh = (warp & 1) * 48;
    const int r0 = (wt == 3) ? 40 : wt*16;

    float acc[6][4];
    #pragma unroll
    for (int nt = 0; nt < 6; nt++)
        acc[nt][0] = acc[nt][1] = acc[nt][2] = acc[nt][3] = 0.f;

    for (int s = 0; s < 3; s++) {
        __syncthreads();
        for (int v = tid; v < 32*96; v += 256) {
            int kl = v / 96, n = v - (v/96)*96;
            float wv = pw[(size_t)(s*32 + kl)*96 + n];
            __nv_bfloat16 h = __float2bfloat16_rn(wv);
            wh[kl*LDA + n] = h;
            wl[kl*LDA + n] = __float2bfloat16_rn(wv - __bfloat162float(h));
        }
        __syncthreads();

        uint32_t ah[2][4], al[2][4];
        int arow = r0 + (lane & 15);
        int acol = (lane >> 4)*8;
        #pragma unroll
        for (int kt = 0; kt < 2; kt++) {
            uint32_t off = (arow*LDA + s*32 + kt*16 + acol)*2;
            ldsm4(ah[kt], sbase + T_XOH + off);
            ldsm4(al[kt], sbase + T_XOL + off);
        }
        #pragma unroll
        for (int nt = 0; nt < 6; nt++) {
            uint32_t bh[2][2], bl[2][2];
            #pragma unroll
            for (int kt = 0; kt < 2; kt++) {
                uint32_t off = ((kt*16 + (lane & 15))*LDA + nh + nt*8)*2;
                ldsm2t(bh[kt], sbase + T_WH + off);
                ldsm2t(bl[kt], sbase + T_WL + off);
            }
            #pragma unroll
            for (int kt = 0; kt < 2; kt++) {
                mma16816(acc[nt], ah[kt], bh[kt]);
                mma16816(acc[nt], al[kt], bh[kt]);
                mma16816(acc[nt], ah[kt], bl[kt]);
            }
        }
    }

    const int r  = lane >> 2;
    const int c2 = (lane & 3)*2;
    #pragma unroll
    for (int nt = 0; nt < 6; nt++) {
        int col = nh + nt*8 + c2;
        float2 bs = {pb[col], pb[col+1]};
        #pragma unroll
        for (int half = 0; half < 2; half++) {
            int row = r0 + r + half*8;
            if (row < 56) {
                int sl = row >> 3, t = row & 7;
                float* og = out + (((size_t)b*TT + t)*NN + (n0 + sl))*CDIM;
                og[col]     = acc[nt][half*2]     + bs.x;
                og[col + 1] = acc[nt][half*2 + 1] + bs.y;
            }
        }
    }
}

extern "C" void kernel_launch(void* const* d_in, const int* in_sizes, int n_in,
                              void* d_out, int out_size)
{
    const float* x      = (const float*)d_in[0];
    const float* mask   = (const float*)d_in[1];
    const float* qkv_w  = (const float*)d_in[2];
    const float* qkv_b  = (const float*)d_in[3];
    const float* psw    = (const float*)d_in[4];
    const float* psb    = (const float*)d_in[5];
    const float* ptw    = (const float*)d_in[6];
    const float* ptb    = (const float*)d_in[7];

    float* out_t  = (float*)d_out;
    float* out_sp = out_t + (size_t)BATCH*TT*NN*CDIM;

    cudaFuncSetAttribute(qkv_mma_kernel,  cudaFuncAttributeMaxDynamicSharedMemorySize, SMEM_QKV);
    cudaFuncSetAttribute(spatial_kernel,  cudaFuncAttributeMaxDynamicSharedMemorySize, SMEM_SP);
    cudaFuncSetAttribute(temporal_kernel, cudaFuncAttributeMaxDynamicSharedMemorySize, SMEM_T);

    qkv_mma_kernel<<<NTOK/128, 256, SMEM_QKV>>>(x, qkv_w, qkv_b);
    spatial_kernel<<<BATCH*TT, 256, SMEM_SP>>>(mask, psw, psb, out_sp);
    temporal_kernel<<<BATCH*7, 256, SMEM_T>>>(ptw, ptb, out_t);
}

// round 10
// speedup vs baseline: 3.2690x; 1.1490x over previous
#include <cuda_runtime.h>
#include <cuda_bf16.h>
#include <cstdint>

#define BATCH   1024
#define TT      8
#define NN      49
#define CDIM    96
#define HEADS   3
#define HD      32
#define PADX    100
#define ATP     52
#define NTOK    (BATCH*TT*NN)        // 401408 tokens = 3136 * 128
#define QKV_LD  288
#define LDA     104                  // bf16 row stride
#define LDAP    72                   // attn-prob row stride (bf16)

__device__ float g_qkv[(size_t)NTOK * QKV_LD];

// ---- qkv mma kernel smem layout (bytes) ----
#define QK_AHI   0
#define QK_ALO   26624
#define QK_BHI   53248
#define QK_BLO   73216
#define QK_BIAS  93184
#define SMEM_QKV 94336

// ---- spatial smem (bytes) ----
#define SP_QH    0                   // 49*104*2 = 10192
#define SP_QL    10192
#define SP_WH    0                   // alias q region during proj (32*104*2 = 6656)
#define SP_WL    6656
#define SP_KH    20384               // 56 rows
#define SP_KL    32032
#define SP_VH    43680               // 64 rows
#define SP_VL    56992
#define SP_AT    70304               // 49*52 f32
#define SP_APH   80496               // 49*72 bf16
#define SP_APL   87552
#define SP_XOH   94608               // 49*104 bf16
#define SP_XOL   104800
#define SMEM_SP  114992

// ---- temporal smem (bytes) ----
#define T_QS     0
#define T_KS     22400
#define T_VS     44800
#define T_AT     67200
#define T_XOH    72576
#define T_XOL    84224
#define T_WH     95872
#define T_WL     102528
#define SMEM_T   109184

// ======================= mma helpers (base ISA) =======================
__device__ __forceinline__ uint32_t smem_u32(const void* p) {
    uint32_t a;
    asm("{ .reg .u64 t; cvta.to.shared.u64 t, %1; cvt.u32.u64 %0, t; }" : "=r"(a) : "l"(p));
    return a;
}
__device__ __forceinline__ void ldsm4(uint32_t* r, uint32_t addr) {
    asm volatile("ldmatrix.sync.aligned.m8n8.x4.shared.b16 {%0,%1,%2,%3}, [%4];"
                 : "=r"(r[0]), "=r"(r[1]), "=r"(r[2]), "=r"(r[3]) : "r"(addr));
}
__device__ __forceinline__ void ldsm2(uint32_t* r, uint32_t addr) {      // non-trans
    asm volatile("ldmatrix.sync.aligned.m8n8.x2.shared.b16 {%0,%1}, [%2];"
                 : "=r"(r[0]), "=r"(r[1]) : "r"(addr));
}
__device__ __forceinline__ void ldsm2t(uint32_t* r, uint32_t addr) {     // trans
    asm volatile("ldmatrix.sync.aligned.m8n8.x2.trans.shared.b16 {%0,%1}, [%2];"
                 : "=r"(r[0]), "=r"(r[1]) : "r"(addr));
}
__device__ __forceinline__ void mma16816(float* d, const uint32_t* a, const uint32_t* b) {
    asm volatile("mma.sync.aligned.m16n8k16.row.col.f32.bf16.bf16.f32 "
                 "{%0,%1,%2,%3}, {%4,%5,%6,%7}, {%8,%9}, {%0,%1,%2,%3};"
                 : "+f"(d[0]), "+f"(d[1]), "+f"(d[2]), "+f"(d[3])
                 : "r"(a[0]), "r"(a[1]), "r"(a[2]), "r"(a[3]), "r"(b[0]), "r"(b[1]));
}
__device__ __forceinline__ uint32_t bfpk(float a, float b) {
    __nv_bfloat162 h = __floats2bfloat162_rn(a, b);
    return *(uint32_t*)&h;
}
__device__ __forceinline__ void split_store(char* hi, char* lo, int idx, float v) {
    __nv_bfloat16 h = __float2bfloat16_rn(v);
    ((__nv_bfloat16*)hi)[idx] = h;
    ((__nv_bfloat16*)lo)[idx] = __float2bfloat16_rn(v - __bfloat162float(h));
}
// split a float4 into hi/lo bf16 pairs at element offset eo (must be 4-aligned)
__device__ __forceinline__ void wsplit4(char* hi, char* lo, int eo, float4 f) {
    __nv_bfloat16 h0 = __float2bfloat16_rn(f.x), h1 = __float2bfloat16_rn(f.y);
    __nv_bfloat16 h2 = __float2bfloat16_rn(f.z), h3 = __float2bfloat16_rn(f.w);
    __nv_bfloat162 p0 = __halves2bfloat162(h0, h1);
    __nv_bfloat162 p1 = __halves2bfloat162(h2, h3);
    *(uint32_t*)(hi + eo*2)     = *(uint32_t*)&p0;
    *(uint32_t*)(hi + eo*2 + 4) = *(uint32_t*)&p1;
    *(uint32_t*)(lo + eo*2)     = bfpk(f.x - __bfloat162float(h0), f.y - __bfloat162float(h1));
    *(uint32_t*)(lo + eo*2 + 4) = bfpk(f.z - __bfloat162float(h2), f.w - __bfloat162float(h3));
}

// ================= Kernel A: QKV GEMM on HMMA (unchanged) =================
__global__ __launch_bounds__(256, 2)
void qkv_mma_kernel(const float* __restrict__ x,
                    const float* __restrict__ qkv_w, const float* __restrict__ qkv_b)
{
    extern __shared__ char smem[];
    const uint32_t sbase = smem_u32(smem);
    __nv_bfloat16* B_hi = (__nv_bfloat16*)(smem + QK_BHI);
    __nv_bfloat16* B_lo = (__nv_bfloat16*)(smem + QK_BLO);
    float* bias_sm = (float*)(smem + QK_BIAS);

    const int tid  = threadIdx.x;
    const int lane = tid & 31;
    const int warp = tid >> 5;
    const int row0 = blockIdx.x * 128;

    for (int v = tid; v < 128*24; v += 256) {
        int r = v / 24, c = (v - (v/24)*24) * 4;
        float4 f = *(const float4*)(x + (size_t)(row0 + r)*96 + c);
        wsplit4(smem + QK_AHI, smem + QK_ALO, r*LDA + c, f);
    }
    for (int v = tid; v < 288; v += 256) bias_sm[v] = qkv_b[v];
    __syncthreads();

    uint32_t ah[6][4], al[6][4];
    {
        int arow = warp*16 + (lane & 15);
        int acol = (lane >> 4) * 8;
        #pragma unroll
        for (int kt = 0; kt < 6; kt++) {
            uint32_t boff = (arow*LDA + kt*16 + acol)*2;
            ldsm4(ah[kt], sbase + QK_AHI + boff);
            ldsm4(al[kt], sbase + QK_ALO + boff);
        }
    }

    for (int chunk = 0; chunk < 3; chunk++) {
        __syncthreads();
        for (int v = tid; v < 96*96; v += 256) {
            int k = v / 96, n = v - (v/96)*96;
            float wv = qkv_w[(size_t)k*QKV_LD + chunk*96 + n];
            __nv_bfloat16 h = __float2bfloat16_rn(wv);
            B_hi[k*LDA + n] = h;
            B_lo[k*LDA + n] = __float2bfloat16_rn(wv - __bfloat162float(h));
        }
        __syncthreads();

        const int brow = lane & 15;
        #pragma unroll
        for (int nt = 0; nt < 12; nt++) {
            const int n0 = nt*8;
            uint32_t bh[6][2], bl[6][2];
            #pragma unroll
            for (int kt = 0; kt < 6; kt++) {
                uint32_t boff = ((kt*16 + brow)*LDA + n0)*2;
                ldsm2t(bh[kt], sbase + QK_BHI + boff);
                ldsm2t(bl[kt], sbase + QK_BLO + boff);
            }
            float acc[4] = {0.f, 0.f, 0.f, 0.f};
            #pragma unroll
            for (int kt = 0; kt < 6; kt++) {
                mma16816(acc, ah[kt], bh[kt]);
                mma16816(acc, al[kt], bh[kt]);
                mma16816(acc, ah[kt], bl[kt]);
            }
            int r  = lane >> 2;
            int c2 = (lane & 3)*2;
            float2 bs = *(float2*)(bias_sm + chunk*96 + n0 + c2);
            size_t gb = (size_t)(row0 + warp*16 + r)*QKV_LD + chunk*96 + n0 + c2;
            float2 o0 = {acc[0] + bs.x, acc[1] + bs.y};
            float2 o1 = {acc[2] + bs.x, acc[3] + bs.y};
            *(float2*)(g_qkv + gb)            = o0;
            *(float2*)(g_qkv + gb + 8*QKV_LD) = o1;
        }
    }
}

// ======================= Kernel B: fully-HMMA spatial =======================
__global__ __launch_bounds__(256, 2)
void spatial_kernel(const float* __restrict__ mask,
                    const float* __restrict__ pw, const float* __restrict__ pb,
                    float* __restrict__ out)
{
    extern __shared__ char smc[];
    const uint32_t sbase = smem_u32(smc);
    float* at = (float*)(smc + SP_AT);
    __nv_bfloat16* wh = (__nv_bfloat16*)(smc + SP_WH);
    __nv_bfloat16* wl = (__nv_bfloat16*)(smc + SP_WL);

    const int bt   = blockIdx.x;
    const int tid  = threadIdx.x;
    const int lane = tid & 31;
    const int warp = tid >> 5;
    const float scale = 0.17677669529663687f;

    // ---- load q/k/v, split to bf16 hi/lo (scale folded into q) ----
    const float* qg = g_qkv + (size_t)bt * NN * QKV_LD;
    for (int v = tid; v < NN*24; v += 256) {
        int r = v / 24, c = (v - r*24)*4;
        const float* src = qg + (size_t)r*QKV_LD + c;
        float4 fq = *(const float4*)(src);
        float4 fk = *(const float4*)(src + 96);
        float4 fv = *(const float4*)(src + 192);
        fq.x *= scale; fq.y *= scale; fq.z *= scale; fq.w *= scale;
        wsplit4(smc + SP_QH, smc + SP_QL, r*LDA + c, fq);
        wsplit4(smc + SP_KH, smc + SP_KL, r*LDA + c, fk);
        wsplit4(smc + SP_VH, smc + SP_VL, r*LDA + c, fv);
    }
    // zero v rows 49..63 (attn cols there are 0; avoid 0*NaN)
    for (int i = tid; i < 15*52; i += 256) {
        int row = 49 + i/52, cw = i - (i/52)*52;
        ((uint32_t*)(smc + SP_VH))[row*52 + cw] = 0;
        ((uint32_t*)(smc + SP_VL))[row*52 + cw] = 0;
    }
    // zero attn-prob buffers (pad cols 49..63 must be 0)
    for (int i = tid; i < 49*36; i += 256) {     // 49*72*2/4 = 1764 u32 per buffer
        ((uint32_t*)(smc + SP_APH))[i] = 0;
        ((uint32_t*)(smc + SP_APL))[i] = 0;
    }
    __syncthreads();

    const int mt  = warp >> 1;
    const int r0  = (mt == 3) ? 33 : mt*16;
    const float* mrow = mask + (size_t)(bt & 63) * (49*49);

    for (int h = 0; h < HEADS; h++) {
        // ---- scores: S = Qh * Kh^T  (M=49, N=49, K=32) ----
        {
            uint32_t aqh[2][4], aql[2][4];
            int ar = r0 + (lane & 15);
            #pragma unroll
            for (int kt = 0; kt < 2; kt++) {
                uint32_t off = (ar*LDA + h*32 + kt*16 + (lane >> 4)*8)*2;
                ldsm4(aqh[kt], sbase + SP_QH + off);
                ldsm4(aql[kt], sbase + SP_QL + off);
            }
            int ntlo = (warp & 1) ? 4 : 0;
            int nthi = (warp & 1) ? 7 : 4;
            for (int nt = ntlo; nt < nthi; nt++) {
                const int n0 = nt*8;
                int l = lane & 15;
                uint32_t boff = ((n0 + (l & 7))*LDA + h*32 + (l & 8))*2;
                uint32_t bh[2][2], bl[2][2];
                #pragma unroll
                for (int kt = 0; kt < 2; kt++) {
                    ldsm2(bh[kt], sbase + SP_KH + boff + kt*32);   // +16 cols = 32B
                    ldsm2(bl[kt], sbase + SP_KL + boff + kt*32);
                }
                float acc[4] = {0.f, 0.f, 0.f, 0.f};
                #pragma unroll
                for (int kt = 0; kt < 2; kt++) {
                    mma16816(acc, aqh[kt], bh[kt]);
                    mma16816(acc, aql[kt], bh[kt]);
                    mma16816(acc, aqh[kt], bl[kt]);
                }
                int r  = r0 + (lane >> 2);
                int c0 = n0 + (lane & 3)*2;
                if (c0 < 49)     { at[r*ATP + c0]         = acc[0]; at[(r+8)*ATP + c0]     = acc[2]; }
                if (c0 + 1 < 49) { at[r*ATP + c0 + 1]     = acc[1]; at[(r+8)*ATP + c0 + 1] = acc[3]; }
            }
        }
        __syncthreads();

        // ---- softmax (mask added here) ----
        for (int row = warp; row < 49; row += 8) {
            float* arow = at + row*ATP;
            const float* mq = mrow + row*49;
            float v0 = arow[lane] + mq[lane];
            float v1 = (lane + 32 < 49) ? arow[lane + 32] + mq[lane + 32] : -3.0e38f;
            float mx = fmaxf(v0, v1);
            #pragma unroll
            for (int o = 16; o; o >>= 1) mx = fmaxf(mx, __shfl_xor_sync(0xffffffffu, mx, o));
            v0 = __expf(v0 - mx);
            v1 = (lane + 32 < 49) ? __expf(v1 - mx) : 0.f;
            float s = v0 + v1;
            #pragma unroll
            for (int o = 16; o; o >>= 1) s += __shfl_xor_sync(0xffffffffu, s, o);
            float inv = __frcp_rn(s);
            arow[lane] = v0*inv;
            if (lane + 32 < 49) arow[lane + 32] = v1*inv;
        }
        __syncthreads();

        // ---- split attn probs to bf16 hi/lo ----
        for (int e = tid; e < 49*49; e += 256) {
            int i = e / 49, j = e - (e/49)*49;
            split_store(smc + SP_APH, smc + SP_APL, i*LDAP + j, at[i*ATP + j]);
        }
        __syncthreads();

        // ---- PV: O = P * V  (M=49, N=32, K=64) ----
        {
            uint32_t ah[4][4], al[4][4];
            int ar = r0 + (lane & 15);
            #pragma unroll
            for (int kt = 0; kt < 4; kt++) {
                uint32_t off = (ar*LDAP + kt*16 + (lane >> 4)*8)*2;
                ldsm4(ah[kt], sbase + SP_APH + off);
                ldsm4(al[kt], sbase + SP_APL + off);
            }
            #pragma unroll
            for (int ntl = 0; ntl < 2; ntl++) {
                int d0 = h*32 + (warp & 1)*16 + ntl*8;
                uint32_t bh[4][2], bl[4][2];
                #pragma unroll
                for (int kt = 0; kt < 4; kt++) {
                    uint32_t off = ((kt*16 + (lane & 15))*LDA + d0)*2;
                    ldsm2t(bh[kt], sbase + SP_VH + off);
                    ldsm2t(bl[kt], sbase + SP_VL + off);
                }
                float acc[4] = {0.f, 0.f, 0.f, 0.f};
                #pragma unroll
                for (int kt = 0; kt < 4; kt++) {
                    mma16816(acc, ah[kt], bh[kt]);
                    mma16816(acc, al[kt], bh[kt]);
                    mma16816(acc, ah[kt], bl[kt]);
                }
                int r  = r0 + (lane >> 2);
                int c0 = d0 + (lane & 3)*2;
                split_store(smc + SP_XOH, smc + SP_XOL, r*LDA + c0,       acc[0]);
                split_store(smc + SP_XOH, smc + SP_XOL, r*LDA + c0 + 1,   acc[1]);
                split_store(smc + SP_XOH, smc + SP_XOL, (r+8)*LDA + c0,   acc[2]);
                split_store(smc + SP_XOH, smc + SP_XOL, (r+8)*LDA + c0+1, acc[3]);
            }
        }
        // no sync: next head's scores touch only at; PV fenced by next sync
    }

    // ---- HMMA projection (weights alias q region) ----
    const int nh = (warp & 1) * 48;
    float acc[6][4];
    #pragma unroll
    for (int nt = 0; nt < 6; nt++)
        acc[nt][0] = acc[nt][1] = acc[nt][2] = acc[nt][3] = 0.f;

    for (int s = 0; s < 3; s++) {
        __syncthreads();
        for (int v = tid; v < 32*96; v += 256) {
            int kl = v / 96, n = v - (v/96)*96;
            float wv = pw[(size_t)(s*32 + kl)*96 + n];
            __nv_bfloat16 h = __float2bfloat16_rn(wv);
            wh[kl*LDA + n] = h;
            wl[kl*LDA + n] = __float2bfloat16_rn(wv - __bfloat162float(h));
        }
        __syncthreads();

        uint32_t ah[2][4], al[2][4];
        int arow = r0 + (lane & 15);
        int acol = (lane >> 4)*8;
        #pragma unroll
        for (int kt = 0; kt < 2; kt++) {
            uint32_t off = (arow*LDA + s*32 + kt*16 + acol)*2;
            ldsm4(ah[kt], sbase + SP_XOH + off);
            ldsm4(al[kt], sbase + SP_XOL + off);
        }
        #pragma unroll
        for (int nt = 0; nt < 6; nt++) {
            uint32_t bh[2][2], bl[2][2];
            #pragma unroll
            for (int kt = 0; kt < 2; kt++) {
                uint32_t off = ((kt*16 + (lane & 15))*LDA + nh + nt*8)*2;
                ldsm2t(bh[kt], sbase + SP_WH + off);
                ldsm2t(bl[kt], sbase + SP_WL + off);
            }
            #pragma unroll
            for (int kt = 0; kt < 2; kt++) {
                mma16816(acc[nt], ah[kt], bh[kt]);
                mma16816(acc[nt], al[kt], bh[kt]);
                mma16816(acc[nt], ah[kt], bl[kt]);
            }
        }
    }

    float* og = out + (size_t)bt * (NN*CDIM);
    const int r  = lane >> 2;
    const int c2 = (lane & 3)*2;
    #pragma unroll
    for (int nt = 0; nt < 6; nt++) {
        int col = nh + nt*8 + c2;
        float2 bs = {pb[col], pb[col+1]};
        int ra = r0 + r, rb = r0 + r + 8;
        if (ra < NN) { og[ra*CDIM + col] = acc[nt][0] + bs.x; og[ra*CDIM + col + 1] = acc[nt][1] + bs.y; }
        if (rb < NN) { og[rb*CDIM + col] = acc[nt][2] + bs.x; og[rb*CDIM + col + 1] = acc[nt][3] + bs.y; }
    }
}

// ====================== Kernel C: temporal attn + HMMA proj (unchanged) ======================
__global__ __launch_bounds__(256, 2)
void temporal_kernel(const float* __restrict__ pw, const float* __restrict__ pb,
                     float* __restrict__ out)
{
    extern __shared__ char smc[];
    const uint32_t sbase = smem_u32(smc);
    float* qs = (float*)(smc + T_QS);
    float* ks = (float*)(smc + T_KS);
    float* vs = (float*)(smc + T_VS);
    float* at = (float*)(smc + T_AT);
    char*  xoh = smc + T_XOH;
    char*  xol = smc + T_XOL;
    __nv_bfloat16* wh = (__nv_bfloat16*)(smc + T_WH);
    __nv_bfloat16* wl = (__nv_bfloat16*)(smc + T_WL);

    const int g    = blockIdx.x;
    const int b    = g / 7;
    const int n0   = (g - b*7) * 7;
    const int tid  = threadIdx.x;
    const int lane = tid & 31;
    const int warp = tid >> 5;

    for (int v = tid; v < 56*24; v += 256) {
        int r = v / 24, c4 = (v - r*24)*4;
        int sl = r >> 3, t = r & 7;
        const float4* src = (const float4*)(g_qkv + (size_t)((b*TT + t)*NN + n0 + sl)*QKV_LD + c4);
        *(float4*)(qs + r*PADX + c4) = src[0];
        *(float4*)(ks + r*PADX + c4) = src[24];
        *(float4*)(vs + r*PADX + c4) = src[48];
    }
    __syncthreads();

    const float scale = 0.17677669529663687f;
    for (int e = tid; e < 7*HEADS*64; e += 256) {
        int sl  = e / 192;
        int rem = e - sl*192;
        int h   = rem >> 6;
        int ij  = rem & 63;
        int i   = ij >> 3, j = ij & 7;
        const float4* qp = (const float4*)(qs + (sl*8 + i)*PADX + h*HD);
        const float4* kp = (const float4*)(ks + (sl*8 + j)*PADX + h*HD);
        float s = 0.f;
        #pragma unroll
        for (int d = 0; d < 8; d++) {
            float4 a = qp[d], bb = kp[d];
            s += a.x*bb.x + a.y*bb.y + a.z*bb.z + a.w*bb.w;
        }
        at[e] = s*scale;
    }
    __syncthreads();

    if (tid < 7*HEADS*8) {
        float* arow = at + tid*8;
        float4 a0 = *(float4*)arow;
        float4 a1 = *(float4*)(arow + 4);
        float mx = fmaxf(fmaxf(fmaxf(a0.x, a0.y), fmaxf(a0.z, a0.w)),
                         fmaxf(fmaxf(a1.x, a1.y), fmaxf(a1.z, a1.w)));
        float e0 = __expf(a0.x - mx), e1 = __expf(a0.y - mx), e2 = __expf(a0.z - mx), e3 = __expf(a0.w - mx);
        float e4 = __expf(a1.x - mx), e5 = __expf(a1.y - mx), e6 = __expf(a1.z - mx), e7 = __expf(a1.w - mx);
        float inv = __frcp_rn(e0+e1+e2+e3+e4+e5+e6+e7);
        a0.x = e0*inv; a0.y = e1*inv; a0.z = e2*inv; a0.w = e3*inv;
        a1.x = e4*inv; a1.y = e5*inv; a1.z = e6*inv; a1.w = e7*inv;
        *(float4*)arow = a0;
        *(float4*)(arow + 4) = a1;
    }
    __syncthreads();

    for (int rr = 0; rr < 7; rr++) {
        const float* atb = at + rr*192 + warp*8;
        float A0[8], A1[8], A2[8];
        *(float4*)A0     = *(const float4*)(atb);
        *(float4*)(A0+4) = *(const float4*)(atb + 4);
        *(float4*)A1     = *(const float4*)(atb + 64);
        *(float4*)(A1+4) = *(const float4*)(atb + 68);
        *(float4*)A2     = *(const float4*)(atb + 128);
        *(float4*)(A2+4) = *(const float4*)(atb + 132);
        float acc0 = 0.f, acc1 = 0.f, acc2 = 0.f;
        #pragma unroll
        for (int j = 0; j < 8; j++) {
            const float* vp = vs + (rr*8 + j)*PADX + lane;
            acc0 += A0[j]*vp[0];
            acc1 += A1[j]*vp[32];
            acc2 += A2[j]*vp[64];
        }
        int row = warp + 8*rr;
        split_store(xoh, xol, row*LDA + lane,      acc0);
        split_store(xoh, xol, row*LDA + lane + 32, acc1);
        split_store(xoh, xol, row*LDA + lane + 64, acc2);
    }

    const int wt = warp >> 1;
    const int nh = (warp & 1) * 48;
    const int r0 = (wt == 3) ? 40 : wt*16;

    float acc[6][4];
    #pragma unroll
    for (int nt = 0; nt < 6; nt++)
        acc[nt][0] = acc[nt][1] = acc[nt][2] = acc[nt][3] = 0.f;

    for (int s = 0; s < 3; s++) {
        __syncthreads();
        for (int v = tid; v < 32*96; v += 256) {
            int kl = v / 96, n = v - (v/96)*96;
            float wv = pw[(size_t)(s*32 + kl)*96 + n];
            __nv_bfloat16 h = __float2bfloat16_rn(wv);
            wh[kl*LDA + n] = h;
            wl[kl*LDA + n] = __float2bfloat16_rn(wv - __bfloat162float(h));
        }
        __syncthreads();

        uint32_t ah[2][4], al[2][4];
        int arow = r0 + (lane & 15);
        int acol = (lane >> 4)*8;
        #pragma unroll
        for (int kt = 0; kt < 2; kt++) {
            uint32_t off = (arow*LDA + s*32 + kt*16 + acol)*2;
            ldsm4(ah[kt], sbase + T_XOH + off);
            ldsm4(al[kt], sbase + T_XOL + off);
        }
        #pragma unroll
        for (int nt = 0; nt < 6; nt++) {
            uint32_t bh[2][2], bl[2][2];
            #pragma unroll
            for (int kt = 0; kt < 2; kt++) {
                uint32_t off = ((kt*16 + (lane & 15))*LDA + nh + nt*8)*2;
                ldsm2t(bh[kt], sbase + T_WH + off);
                ldsm2t(bl[kt], sbase + T_WL + off);
            }
            #pragma unroll
            for (int kt = 0; kt < 2; kt++) {
                mma16816(acc[nt], ah[kt], bh[kt]);
                mma16816(acc[nt], al[kt], bh[kt]);
                mma16816(acc[nt], ah[kt], bl[kt]);
            }
        }
    }

    const int r  = lane >> 2;
    const int c2 = (lane & 3)*2;
    #pragma unroll
    for (int nt = 0; nt < 6; nt++) {
        int col = nh + nt*8 + c2;
        float2 bs = {pb[col], pb[col+1]};
        #pragma unroll
        for (int half = 0; half < 2; half++) {
            int row = r0 + r + half*8;
            if (row < 56) {
                int sl = row >> 3, t = row & 7;
                float* og = out + (((size_t)b*TT + t)*NN + (n0 + sl))*CDIM;
                og[col]     = acc[nt][half*2]     + bs.x;
                og[col + 1] = acc[nt][half*2 + 1] + bs.y;
            }
        }
    }
}

extern "C" void kernel_launch(void* const* d_in, const int* in_sizes, int n_in,
                              void* d_out, int out_size)
{
    const float* x      = (const float*)d_in[0];
    const float* mask   = (const float*)d_in[1];
    const float* qkv_w  = (const float*)d_in[2];
    const float* qkv_b  = (const float*)d_in[3];
    const float* psw    = (const float*)d_in[4];
    const float* psb    = (const float*)d_in[5];
    const float* ptw    = (const float*)d_in[6];
    const float* ptb    = (const float*)d_in[7];

    float* out_t  = (float*)d_out;
    float* out_sp = out_t + (size_t)BATCH*TT*NN*CDIM;

    cudaFuncSetAttribute(qkv_mma_kernel,  cudaFuncAttributeMaxDynamicSharedMemorySize, SMEM_QKV);
    cudaFuncSetAttribute(spatial_kernel,  cudaFuncAttributeMaxDynamicSharedMemorySize, SMEM_SP);
    cudaFuncSetAttribute(temporal_kernel, cudaFuncAttributeMaxDynamicSharedMemorySize, SMEM_T);

    qkv_mma_kernel<<<NTOK/128, 256, SMEM_QKV>>>(x, qkv_w, qkv_b);
    spatial_kernel<<<BATCH*TT, 256, SMEM_SP>>>(mask, psw, psb, out_sp);
    temporal_kernel<<<BATCH*7, 256, SMEM_T>>>(ptw, ptb, out_t);
}

// round 11
// speedup vs baseline: 3.3351x; 1.0202x over previous
#include <cuda_runtime.h>
#include <cuda_bf16.h>
#include <cstdint>

#define BATCH   1024
#define TT      8
#define NN      49
#define CDIM    96
#define HEADS   3
#define HD      32
#define PADX    100
#define ATP     52
#define NTOK    (BATCH*TT*NN)
#define QKV_LD  288
#define LDA     104
#define LDAP    72
#define SCALE   0.17677669529663687f

// canonical bf16 hi/lo storage
__device__ __nv_bfloat16 g_qkvh[(size_t)NTOK * QKV_LD];
__device__ __nv_bfloat16 g_qkvl[(size_t)NTOK * QKV_LD];
__device__ __nv_bfloat16 g_wqkvh[96*288], g_wqkvl[96*288];
__device__ __nv_bfloat16 g_pswh[96*96],  g_pswl[96*96];
__device__ __nv_bfloat16 g_ptwh[96*96],  g_ptwl[96*96];

// ---- qkv smem (bytes) ----
#define QK_AHI   0
#define QK_ALO   26624
#define QK_BHI   53248
#define QK_BLO   73216
#define QK_BIAS  93184
#define SMEM_QKV 94336

// ---- spatial smem (bytes) ----
#define SP_QH    0
#define SP_QL    10192
#define SP_WH    0
#define SP_WL    6656
#define SP_KH    20384
#define SP_KL    32032
#define SP_VH    43680
#define SP_VL    56992
#define SP_AT    70304
#define SP_APH   80496
#define SP_APL   87552
#define SP_XOH   94608
#define SP_XOL   104800
#define SMEM_SP  114992

// ---- temporal smem (bytes) ----
#define T_QS     0
#define T_KS     22400
#define T_VS     44800
#define T_AT     67200
#define T_XOH    72576
#define T_XOL    84224
#define T_WH     95872
#define T_WL     102528
#define SMEM_T   109184

// ======================= helpers =======================
__device__ __forceinline__ uint32_t smem_u32(const void* p) {
    uint32_t a;
    asm("{ .reg .u64 t; cvta.to.shared.u64 t, %1; cvt.u32.u64 %0, t; }" : "=r"(a) : "l"(p));
    return a;
}
__device__ __forceinline__ void ldsm4(uint32_t* r, uint32_t addr) {
    asm volatile("ldmatrix.sync.aligned.m8n8.x4.shared.b16 {%0,%1,%2,%3}, [%4];"
                 : "=r"(r[0]), "=r"(r[1]), "=r"(r[2]), "=r"(r[3]) : "r"(addr));
}
__device__ __forceinline__ void ldsm2(uint32_t* r, uint32_t addr) {
    asm volatile("ldmatrix.sync.aligned.m8n8.x2.shared.b16 {%0,%1}, [%2];"
                 : "=r"(r[0]), "=r"(r[1]) : "r"(addr));
}
__device__ __forceinline__ void ldsm2t(uint32_t* r, uint32_t addr) {
    asm volatile("ldmatrix.sync.aligned.m8n8.x2.trans.shared.b16 {%0,%1}, [%2];"
                 : "=r"(r[0]), "=r"(r[1]) : "r"(addr));
}
__device__ __forceinline__ void mma16816(float* d, const uint32_t* a, const uint32_t* b) {
    asm volatile("mma.sync.aligned.m16n8k16.row.col.f32.bf16.bf16.f32 "
                 "{%0,%1,%2,%3}, {%4,%5,%6,%7}, {%8,%9}, {%0,%1,%2,%3};"
                 : "+f"(d[0]), "+f"(d[1]), "+f"(d[2]), "+f"(d[3])
                 : "r"(a[0]), "r"(a[1]), "r"(a[2]), "r"(a[3]), "r"(b[0]), "r"(b[1]));
}
__device__ __forceinline__ uint32_t bfpk(float a, float b) {
    __nv_bfloat162 h = __floats2bfloat162_rn(a, b);
    return *(uint32_t*)&h;
}
__device__ __forceinline__ void split_store(char* hi, char* lo, int idx, float v) {
    __nv_bfloat16 h = __float2bfloat16_rn(v);
    ((__nv_bfloat16*)hi)[idx] = h;
    ((__nv_bfloat16*)lo)[idx] = __float2bfloat16_rn(v - __bfloat162float(h));
}
__device__ __forceinline__ void gsplit(__nv_bfloat16* hi, __nv_bfloat16* lo, size_t idx, float a, float b) {
    __nv_bfloat16 h0 = __float2bfloat16_rn(a), h1 = __float2bfloat16_rn(b);
    *(uint32_t*)(hi + idx) = *(uint32_t*)&(__nv_bfloat162&)*&h0, 0;
    __nv_bfloat162 hp = __halves2bfloat162(h0, h1);
    *(uint32_t*)(hi + idx) = *(uint32_t*)&hp;
    *(uint32_t*)(lo + idx) = bfpk(a - __bfloat162float(h0), b - __bfloat162float(h1));
}

// ================= weight pre-conversion =================
__global__ void wconv_kernel(const float* __restrict__ qkv_w,
                             const float* __restrict__ psw,
                             const float* __restrict__ ptw)
{
    int i = blockIdx.x*256 + threadIdx.x;
    if (i < 96*288) {
        float v = qkv_w[i];
        if ((i % 288) < 96) v *= SCALE;                 // fold scale into Wq
        __nv_bfloat16 h = __float2bfloat16_rn(v);
        g_wqkvh[i] = h;
        g_wqkvl[i] = __float2bfloat16_rn(v - __bfloat162float(h));
    } else if (i < 96*288 + 96*96) {
        int j = i - 96*288;
        float v = psw[j];
        __nv_bfloat16 h = __float2bfloat16_rn(v);
        g_pswh[j] = h;
        g_pswl[j] = __float2bfloat16_rn(v - __bfloat162float(h));
    } else if (i < 96*288 + 2*96*96) {
        int j = i - 96*288 - 96*96;
        float v = ptw[j];
        __nv_bfloat16 h = __float2bfloat16_rn(v);
        g_ptwh[j] = h;
        g_ptwl[j] = __float2bfloat16_rn(v - __bfloat162float(h));
    }
}

// ================= Kernel A: QKV GEMM =================
__global__ __launch_bounds__(256, 2)
void qkv_mma_kernel(const float* __restrict__ x, const float* __restrict__ qkv_b)
{
    extern __shared__ char smem[];
    const uint32_t sbase = smem_u32(smem);
    float* bias_sm = (float*)(smem + QK_BIAS);

    const int tid  = threadIdx.x;
    const int lane = tid & 31;
    const int warp = tid >> 5;
    const int row0 = blockIdx.x * 128;

    for (int v = tid; v < 128*24; v += 256) {
        int r = v / 24, c = (v - (v/24)*24) * 4;
        float4 f = *(const float4*)(x + (size_t)(row0 + r)*96 + c);
        __nv_bfloat16 h0 = __float2bfloat16_rn(f.x), h1 = __float2bfloat16_rn(f.y);
        __nv_bfloat16 h2 = __float2bfloat16_rn(f.z), h3 = __float2bfloat16_rn(f.w);
        __nv_bfloat162 p0 = __halves2bfloat162(h0, h1);
        __nv_bfloat162 p1 = __halves2bfloat162(h2, h3);
        uint32_t off = (r*LDA + c)*2;
        *(uint32_t*)(smem + QK_AHI + off)     = *(uint32_t*)&p0;
        *(uint32_t*)(smem + QK_AHI + off + 4) = *(uint32_t*)&p1;
        *(uint32_t*)(smem + QK_ALO + off)     = bfpk(f.x - __bfloat162float(h0), f.y - __bfloat162float(h1));
        *(uint32_t*)(smem + QK_ALO + off + 4) = bfpk(f.z - __bfloat162float(h2), f.w - __bfloat162float(h3));
    }
    for (int v = tid; v < 288; v += 256)
        bias_sm[v] = qkv_b[v] * ((v < 96) ? SCALE : 1.0f);
    __syncthreads();

    uint32_t ah[6][4], al[6][4];
    {
        int arow = warp*16 + (lane & 15);
        int acol = (lane >> 4) * 8;
        #pragma unroll
        for (int kt = 0; kt < 6; kt++) {
            uint32_t boff = (arow*LDA + kt*16 + acol)*2;
            ldsm4(ah[kt], sbase + QK_AHI + boff);
            ldsm4(al[kt], sbase + QK_ALO + boff);
        }
    }

    for (int chunk = 0; chunk < 3; chunk++) {
        __syncthreads();
        // stage pre-split weights (raw u32 copies)
        for (int v = tid; v < 96*48; v += 256) {
            int k = v / 48, j = v - (v/48)*48;
            ((uint32_t*)(smem + QK_BHI))[k*52 + j] = ((const uint32_t*)g_wqkvh)[k*144 + chunk*48 + j];
            ((uint32_t*)(smem + QK_BLO))[k*52 + j] = ((const uint32_t*)g_wqkvl)[k*144 + chunk*48 + j];
        }
        __syncthreads();

        const int brow = lane & 15;
        #pragma unroll
        for (int nt = 0; nt < 12; nt++) {
            const int n0 = nt*8;
            uint32_t bh[6][2], bl[6][2];
            #pragma unroll
            for (int kt = 0; kt < 6; kt++) {
                uint32_t boff = ((kt*16 + brow)*LDA + n0)*2;
                ldsm2t(bh[kt], sbase + QK_BHI + boff);
                ldsm2t(bl[kt], sbase + QK_BLO + boff);
            }
            float acc[4] = {0.f, 0.f, 0.f, 0.f};
            #pragma unroll
            for (int kt = 0; kt < 6; kt++) {
                mma16816(acc, ah[kt], bh[kt]);
                mma16816(acc, al[kt], bh[kt]);
                mma16816(acc, ah[kt], bl[kt]);
            }
            int r  = lane >> 2;
            int c2 = (lane & 3)*2;
            float2 bs = *(float2*)(bias_sm + chunk*96 + n0 + c2);
            size_t gb = (size_t)(row0 + warp*16 + r)*QKV_LD + chunk*96 + n0 + c2;
            gsplit(g_qkvh, g_qkvl, gb,            acc[0] + bs.x, acc[1] + bs.y);
            gsplit(g_qkvh, g_qkvl, gb + 8*QKV_LD, acc[2] + bs.x, acc[3] + bs.y);
        }
    }
}

// ================= Kernel B: fully-HMMA spatial =================
__global__ __launch_bounds__(256, 2)
void spatial_kernel(const float* __restrict__ mask,
                    const float* __restrict__ pb, float* __restrict__ out)
{
    extern __shared__ char smc[];
    const uint32_t sbase = smem_u32(smc);
    float* at = (float*)(smc + SP_AT);

    const int bt   = blockIdx.x;
    const int tid  = threadIdx.x;
    const int lane = tid & 31;
    const int warp = tid >> 5;

    // ---- raw copies of pre-split q/k/v ----
    {
        const size_t tb = (size_t)bt * NN * QKV_LD;
        for (int v = tid; v < NN*12; v += 256) {
            int r = v / 12, c8 = (v - (v/12)*12)*8;
            size_t src = tb + (size_t)r*QKV_LD + c8;
            uint32_t doff = (r*LDA + c8)*2;
            *(uint4*)(smc + SP_QH + doff) = *(const uint4*)(g_qkvh + src);
            *(uint4*)(smc + SP_QL + doff) = *(const uint4*)(g_qkvl + src);
            *(uint4*)(smc + SP_KH + doff) = *(const uint4*)(g_qkvh + src + 96);
            *(uint4*)(smc + SP_KL + doff) = *(const uint4*)(g_qkvl + src + 96);
            *(uint4*)(smc + SP_VH + doff) = *(const uint4*)(g_qkvh + src + 192);
            *(uint4*)(smc + SP_VL + doff) = *(const uint4*)(g_qkvl + src + 192);
        }
    }
    // zero v rows 49..63
    for (int i = tid; i < 15*52; i += 256) {
        int row = 49 + i/52, cw = i - (i/52)*52;
        ((uint32_t*)(smc + SP_VH))[row*52 + cw] = 0;
        ((uint32_t*)(smc + SP_VL))[row*52 + cw] = 0;
    }
    // zero attn-prob buffers
    for (int i = tid; i < 49*36; i += 256) {
        ((uint32_t*)(smc + SP_APH))[i] = 0;
        ((uint32_t*)(smc + SP_APL))[i] = 0;
    }
    __syncthreads();

    const int mt  = warp >> 1;
    const int r0  = (mt == 3) ? 33 : mt*16;
    const float* mrow = mask + (size_t)(bt & 63) * (49*49);

    for (int h = 0; h < HEADS; h++) {
        // ---- scores ----
        {
            uint32_t aqh[2][4], aql[2][4];
            int ar = r0 + (lane & 15);
            #pragma unroll
            for (int kt = 0; kt < 2; kt++) {
                uint32_t off = (ar*LDA + h*32 + kt*16 + (lane >> 4)*8)*2;
                ldsm4(aqh[kt], sbase + SP_QH + off);
                ldsm4(aql[kt], sbase + SP_QL + off);
            }
            int ntlo = (warp & 1) ? 4 : 0;
            int nthi = (warp & 1) ? 7 : 4;
            for (int nt = ntlo; nt < nthi; nt++) {
                const int n0 = nt*8;
                int l = lane & 15;
                uint32_t boff = ((n0 + (l & 7))*LDA + h*32 + (l & 8))*2;
                uint32_t bh[2][2], bl[2][2];
                #pragma unroll
                for (int kt = 0; kt < 2; kt++) {
                    ldsm2(bh[kt], sbase + SP_KH + boff + kt*32);
                    ldsm2(bl[kt], sbase + SP_KL + boff + kt*32);
                }
                float acc[4] = {0.f, 0.f, 0.f, 0.f};
                #pragma unroll
                for (int kt = 0; kt < 2; kt++) {
                    mma16816(acc, aqh[kt], bh[kt]);
                    mma16816(acc, aql[kt], bh[kt]);
                    mma16816(acc, aqh[kt], bl[kt]);
                }
                int r  = r0 + (lane >> 2);
                int c0 = n0 + (lane & 3)*2;
                if (c0 < 49)     { at[r*ATP + c0]     = acc[0]; at[(r+8)*ATP + c0]     = acc[2]; }
                if (c0 + 1 < 49) { at[r*ATP + c0 + 1] = acc[1]; at[(r+8)*ATP + c0 + 1] = acc[3]; }
            }
        }
        __syncthreads();

        // ---- softmax: writes split probs directly ----
        for (int row = warp; row < 49; row += 8) {
            float* arow = at + row*ATP;
            const float* mq = mrow + row*49;
            float v0 = arow[lane] + mq[lane];
            float v1 = (lane + 32 < 49) ? arow[lane + 32] + mq[lane + 32] : -3.0e38f;
            float mx = fmaxf(v0, v1);
            #pragma unroll
            for (int o = 16; o; o >>= 1) mx = fmaxf(mx, __shfl_xor_sync(0xffffffffu, mx, o));
            v0 = __expf(v0 - mx);
            v1 = (lane + 32 < 49) ? __expf(v1 - mx) : 0.f;
            float s = v0 + v1;
            #pragma unroll
            for (int o = 16; o; o >>= 1) s += __shfl_xor_sync(0xffffffffu, s, o);
            float inv = __frcp_rn(s);
            split_store(smc + SP_APH, smc + SP_APL, row*LDAP + lane, v0*inv);
            if (lane + 32 < 49)
                split_store(smc + SP_APH, smc + SP_APL, row*LDAP + lane + 32, v1*inv);
        }
        __syncthreads();

        // ---- PV ----
        {
            uint32_t ah[4][4], al[4][4];
            int ar = r0 + (lane & 15);
            #pragma unroll
            for (int kt = 0; kt < 4; kt++) {
                uint32_t off = (ar*LDAP + kt*16 + (lane >> 4)*8)*2;
                ldsm4(ah[kt], sbase + SP_APH + off);
                ldsm4(al[kt], sbase + SP_APL + off);
            }
            #pragma unroll
            for (int ntl = 0; ntl < 2; ntl++) {
                int d0 = h*32 + (warp & 1)*16 + ntl*8;
                uint32_t bh[4][2], bl[4][2];
                #pragma unroll
                for (int kt = 0; kt < 4; kt++) {
                    uint32_t off = ((kt*16 + (lane & 15))*LDA + d0)*2;
                    ldsm2t(bh[kt], sbase + SP_VH + off);
                    ldsm2t(bl[kt], sbase + SP_VL + off);
                }
                float acc[4] = {0.f, 0.f, 0.f, 0.f};
                #pragma unroll
                for (int kt = 0; kt < 4; kt++) {
                    mma16816(acc, ah[kt], bh[kt]);
                    mma16816(acc, al[kt], bh[kt]);
                    mma16816(acc, ah[kt], bl[kt]);
                }
                int r  = r0 + (lane >> 2);
                int c0 = d0 + (lane & 3)*2;
                split_store(smc + SP_XOH, smc + SP_XOL, r*LDA + c0,       acc[0]);
                split_store(smc + SP_XOH, smc + SP_XOL, r*LDA + c0 + 1,   acc[1]);
                split_store(smc + SP_XOH, smc + SP_XOL, (r+8)*LDA + c0,   acc[2]);
                split_store(smc + SP_XOH, smc + SP_XOL, (r+8)*LDA + c0+1, acc[3]);
            }
        }
    }

    // ---- HMMA projection (weights alias q region) ----
    const int nh = (warp & 1) * 48;
    float acc[6][4];
    #pragma unroll
    for (int nt = 0; nt < 6; nt++)
        acc[nt][0] = acc[nt][1] = acc[nt][2] = acc[nt][3] = 0.f;

    for (int s = 0; s < 3; s++) {
        __syncthreads();
        for (int v = tid; v < 32*48; v += 256) {
            int kl = v / 48, j = v - (v/48)*48;
            ((uint32_t*)(smc + SP_WH))[kl*52 + j] = ((const uint32_t*)g_pswh)[(s*32 + kl)*48 + j];
            ((uint32_t*)(smc + SP_WL))[kl*52 + j] = ((const uint32_t*)g_pswl)[(s*32 + kl)*48 + j];
        }
        __syncthreads();

        uint32_t ah[2][4], al[2][4];
        int arow = r0 + (lane & 15);
        int acol = (lane >> 4)*8;
        #pragma unroll
        for (int kt = 0; kt < 2; kt++) {
            uint32_t off = (arow*LDA + s*32 + kt*16 + acol)*2;
            ldsm4(ah[kt], sbase + SP_XOH + off);
            ldsm4(al[kt], sbase + SP_XOL + off);
        }
        #pragma unroll
        for (int nt = 0; nt < 6; nt++) {
            uint32_t bh[2][2], bl[2][2];
            #pragma unroll
            for (int kt = 0; kt < 2; kt++) {
                uint32_t off = ((kt*16 + (lane & 15))*LDA + nh + nt*8)*2;
                ldsm2t(bh[kt], sbase + SP_WH + off);
                ldsm2t(bl[kt], sbase + SP_WL + off);
            }
            #pragma unroll
            for (int kt = 0; kt < 2; kt++) {
                mma16816(acc[nt], ah[kt], bh[kt]);
                mma16816(acc[nt], al[kt], bh[kt]);
                mma16816(acc[nt], ah[kt], bl[kt]);
            }
        }
    }

    float* og = out + (size_t)bt * (NN*CDIM);
    const int r  = lane >> 2;
    const int c2 = (lane & 3)*2;
    #pragma unroll
    for (int nt = 0; nt < 6; nt++) {
        int col = nh + nt*8 + c2;
        float2 bs = {pb[col], pb[col+1]};
        int ra = r0 + r, rb = r0 + r + 8;
        if (ra < NN) { og[ra*CDIM + col] = acc[nt][0] + bs.x; og[ra*CDIM + col + 1] = acc[nt][1] + bs.y; }
        if (rb < NN) { og[rb*CDIM + col] = acc[nt][2] + bs.x; og[rb*CDIM + col + 1] = acc[nt][3] + bs.y; }
    }
}

// ================= Kernel C: temporal =================
__global__ __launch_bounds__(256, 2)
void temporal_kernel(const float* __restrict__ pb, float* __restrict__ out)
{
    extern __shared__ char smc[];
    const uint32_t sbase = smem_u32(smc);
    float* qs = (float*)(smc + T_QS);
    float* ks = (float*)(smc + T_KS);
    float* vs = (float*)(smc + T_VS);
    float* at = (float*)(smc + T_AT);
    char*  xoh = smc + T_XOH;
    char*  xol = smc + T_XOL;

    const int g    = blockIdx.x;
    const int b    = g / 7;
    const int n0   = (g - b*7) * 7;
    const int tid  = threadIdx.x;
    const int lane = tid & 31;
    const int warp = tid >> 5;

    // ---- reconstruct fp32 q/k/v from hi+lo ----
    for (int v = tid; v < 56*36; v += 256) {
        int r = v / 36, m = v - (v/36)*36;
        int mat = m / 12, c8 = (m - mat*12)*8;
        int sl = r >> 3, t = r & 7;
        size_t src = ((size_t)(b*TT + t)*NN + n0 + sl)*QKV_LD + mat*96 + c8;
        uint4 hv = *(const uint4*)(g_qkvh + src);
        uint4 lv = *(const uint4*)(g_qkvl + src);
        float* dst = ((mat == 0) ? qs : (mat == 1) ? ks : vs) + r*PADX + c8;
        const __nv_bfloat162* hp = (const __nv_bfloat162*)&hv;
        const __nv_bfloat162* lp = (const __nv_bfloat162*)&lv;
        #pragma unroll
        for (int p = 0; p < 4; p++) {
            float2 hf = __bfloat1622float2(hp[p]);
            float2 lf = __bfloat1622float2(lp[p]);
            dst[p*2]   = hf.x + lf.x;
            dst[p*2+1] = hf.y + lf.y;
        }
    }
    __syncthreads();

    // ---- scores (q pre-scaled) ----
    for (int e = tid; e < 7*HEADS*64; e += 256) {
        int sl  = e / 192;
        int rem = e - sl*192;
        int h   = rem >> 6;
        int ij  = rem & 63;
        int i   = ij >> 3, j = ij & 7;
        const float4* qp = (const float4*)(qs + (sl*8 + i)*PADX + h*HD);
        const float4* kp = (const float4*)(ks + (sl*8 + j)*PADX + h*HD);
        float s = 0.f;
        #pragma unroll
        for (int d = 0; d < 8; d++) {
            float4 a = qp[d], bb = kp[d];
            s += a.x*bb.x + a.y*bb.y + a.z*bb.z + a.w*bb.w;
        }
        at[e] = s;
    }
    __syncthreads();

    if (tid < 7*HEADS*8) {
        float* arow = at + tid*8;
        float4 a0 = *(float4*)arow;
        float4 a1 = *(float4*)(arow + 4);
        float mx = fmaxf(fmaxf(fmaxf(a0.x, a0.y), fmaxf(a0.z, a0.w)),
                         fmaxf(fmaxf(a1.x, a1.y), fmaxf(a1.z, a1.w)));
        float e0 = __expf(a0.x - mx), e1 = __expf(a0.y - mx), e2 = __expf(a0.z - mx), e3 = __expf(a0.w - mx);
        float e4 = __expf(a1.x - mx), e5 = __expf(a1.y - mx), e6 = __expf(a1.z - mx), e7 = __expf(a1.w - mx);
        float inv = __frcp_rn(e0+e1+e2+e3+e4+e5+e6+e7);
        a0.x = e0*inv; a0.y = e1*inv; a0.z = e2*inv; a0.w = e3*inv;
        a1.x = e4*inv; a1.y = e5*inv; a1.z = e6*inv; a1.w = e7*inv;
        *(float4*)arow = a0;
        *(float4*)(arow + 4) = a1;
    }
    __syncthreads();

    for (int rr = 0; rr < 7; rr++) {
        const float* atb = at + rr*192 + warp*8;
        float A0[8], A1[8], A2[8];
        *(float4*)A0     = *(const float4*)(atb);
        *(float4*)(A0+4) = *(const float4*)(atb + 4);
        *(float4*)A1     = *(const float4*)(atb + 64);
        *(float4*)(A1+4) = *(const float4*)(atb + 68);
        *(float4*)A2     = *(const float4*)(atb + 128);
        *(float4*)(A2+4) = *(const float4*)(atb + 132);
        float acc0 = 0.f, acc1 = 0.f, acc2 = 0.f;
        #pragma unroll
        for (int j = 0; j < 8; j++) {
            const float* vp = vs + (rr*8 + j)*PADX + lane;
            acc0 += A0[j]*vp[0];
            acc1 += A1[j]*vp[32];
            acc2 += A2[j]*vp[64];
        }
        int row = warp + 8*rr;
        split_store(xoh, xol, row*LDA + lane,      acc0);
        split_store(xoh, xol, row*LDA + lane + 32, acc1);
        split_store(xoh, xol, row*LDA + lane + 64, acc2);
    }

    const int wt = warp >> 1;
    const int nh = (warp & 1) * 48;
    const int r0 = (wt == 3) ? 40 : wt*16;

    float acc[6][4];
    #pragma unroll
    for (int nt = 0; nt < 6; nt++)
        acc[nt][0] = acc[nt][1] = acc[nt][2] = acc[nt][3] = 0.f;

    for (int s = 0; s < 3; s++) {
        __syncthreads();
        for (int v = tid; v < 32*48; v += 256) {
            int kl = v / 48, j = v - (v/48)*48;
            ((uint32_t*)(smc + T_WH))[kl*52 + j] = ((const uint32_t*)g_ptwh)[(s*32 + kl)*48 + j];
            ((uint32_t*)(smc + T_WL))[kl*52 + j] = ((const uint32_t*)g_ptwl)[(s*32 + kl)*48 + j];
        }
        __syncthreads();

        uint32_t ah[2][4], al[2][4];
        int arow = r0 + (lane & 15);
        int acol = (lane >> 4)*8;
        #pragma unroll
        for (int kt = 0; kt < 2; kt++) {
            uint32_t off = (arow*LDA + s*32 + kt*16 + acol)*2;
            ldsm4(ah[kt], sbase + T_XOH + off);
            ldsm4(al[kt], sbase + T_XOL + off);
        }
        #pragma unroll
        for (int nt = 0; nt < 6; nt++) {
            uint32_t bh[2][2], bl[2][2];
            #pragma unroll
            for (int kt = 0; kt < 2; kt++) {
                uint32_t off = ((kt*16 + (lane & 15))*LDA + nh + nt*8)*2;
                ldsm2t(bh[kt], sbase + T_WH + off);
                ldsm2t(bl[kt], sbase + T_WL + off);
            }
            #pragma unroll
            for (int kt = 0; kt < 2; kt++) {
                mma16816(acc[nt], ah[kt], bh[kt]);
                mma16816(acc[nt], al[kt], bh[kt]);
                mma16816(acc[nt], ah[kt], bl[kt]);
            }
        }
    }

    const int r  = lane >> 2;
    const int c2 = (lane & 3)*2;
    #pragma unroll
    for (int nt = 0; nt < 6; nt++) {
        int col = nh + nt*8 + c2;
        float2 bs = {pb[col], pb[col+1]};
        #pragma unroll
        for (int half = 0; half < 2; half++) {
            int row = r0 + r + half*8;
            if (row < 56) {
                int sl = row >> 3, t = row & 7;
                float* og = out + (((size_t)b*TT + t)*NN + (n0 + sl))*CDIM;
                og[col]     = acc[nt][half*2]     + bs.x;
                og[col + 1] = acc[nt][half*2 + 1] + bs.y;
            }
        }
    }
}

extern "C" void kernel_launch(void* const* d_in, const int* in_sizes, int n_in,
                              void* d_out, int out_size)
{
    const float* x      = (const float*)d_in[0];
    const float* mask   = (const float*)d_in[1];
    const float* qkv_w  = (const float*)d_in[2];
    const float* qkv_b  = (const float*)d_in[3];
    const float* psw    = (const float*)d_in[4];
    const float* psb    = (const float*)d_in[5];
    const float* ptw    = (const float*)d_in[6];
    const float* ptb    = (const float*)d_in[7];

    float* out_t  = (float*)d_out;
    float* out_sp = out_t + (size_t)BATCH*TT*NN*CDIM;

    cudaFuncSetAttribute(qkv_mma_kernel,  cudaFuncAttributeMaxDynamicSharedMemorySize, SMEM_QKV);
    cudaFuncSetAttribute(spatial_kernel,  cudaFuncAttributeMaxDynamicSharedMemorySize, SMEM_SP);
    cudaFuncSetAttribute(temporal_kernel, cudaFuncAttributeMaxDynamicSharedMemorySize, SMEM_T);

    wconv_kernel<<<180, 256>>>(qkv_w, psw, ptw);
    qkv_mma_kernel<<<NTOK/128, 256, SMEM_QKV>>>(x, qkv_b);
    spatial_kernel<<<BATCH*TT, 256, SMEM_SP>>>(mask, psb, out_sp);
    temporal_kernel<<<BATCH*7, 256, SMEM_T>>>(ptb, out_t);
}

// round 13
// speedup vs baseline: 3.7350x; 1.1199x over previous
#include <cuda_runtime.h>
#include <cuda_bf16.h>
#include <cstdint>

#define BATCH   1024
#define TT      8
#define NN      49
#define CDIM    96
#define HEADS   3
#define HD      32
#define PADX    100
#define NTOK    (BATCH*TT*NN)
#define QKV_LD  288
#define LDA     104
#define SCALE   0.17677669529663687f

// canonical bf16 hi/lo storage
__device__ __nv_bfloat16 g_qkvh[(size_t)NTOK * QKV_LD];
__device__ __nv_bfloat16 g_qkvl[(size_t)NTOK * QKV_LD];
__device__ __nv_bfloat16 g_wqkvh[96*288], g_wqkvl[96*288];
__device__ __nv_bfloat16 g_pswh[96*96],  g_pswl[96*96];
__device__ __nv_bfloat16 g_ptwh[96*96],  g_ptwl[96*96];

// ---- qkv smem (bytes) ----
#define QK_AHI   0
#define QK_ALO   26624
#define QK_BHI   53248
#define QK_BLO   73216
#define QK_BIAS  93184
#define SMEM_QKV 94336

// ---- spatial smem (bytes) ----
#define SP_QH    0                   // 49*104*2
#define SP_QL    10192
#define SP_WH    0                   // alias q region during proj
#define SP_WL    6656
#define SP_KH    20384               // 56 rows
#define SP_KL    32032
#define SP_VH    43680               // 64 rows
#define SP_VL    56992
#define SP_XOH   70304               // 49 rows
#define SP_XOL   80496
#define SP_MS    90688               // mask 49*52 f32
#define SMEM_SP  100880

// ---- temporal smem (bytes) ----
#define T_QS     0
#define T_KS     22400
#define T_VS     44800
#define T_AT     67200
#define T_XOH    72576
#define T_XOL    84224
#define T_WH     95872
#define T_WL     102528
#define SMEM_T   109184

// ======================= helpers =======================
__device__ __forceinline__ uint32_t smem_u32(const void* p) {
    uint32_t a;
    asm("{ .reg .u64 t; cvta.to.shared.u64 t, %1; cvt.u32.u64 %0, t; }" : "=r"(a) : "l"(p));
    return a;
}
__device__ __forceinline__ void ldsm4(uint32_t* r, uint32_t addr) {
    asm volatile("ldmatrix.sync.aligned.m8n8.x4.shared.b16 {%0,%1,%2,%3}, [%4];"
                 : "=r"(r[0]), "=r"(r[1]), "=r"(r[2]), "=r"(r[3]) : "r"(addr));
}
__device__ __forceinline__ void ldsm2(uint32_t* r, uint32_t addr) {
    asm volatile("ldmatrix.sync.aligned.m8n8.x2.shared.b16 {%0,%1}, [%2];"
                 : "=r"(r[0]), "=r"(r[1]) : "r"(addr));
}
__device__ __forceinline__ void ldsm2t(uint32_t* r, uint32_t addr) {
    asm volatile("ldmatrix.sync.aligned.m8n8.x2.trans.shared.b16 {%0,%1}, [%2];"
                 : "=r"(r[0]), "=r"(r[1]) : "r"(addr));
}
__device__ __forceinline__ void ldsm4t(uint32_t* r, uint32_t addr) {
    asm volatile("ldmatrix.sync.aligned.m8n8.x4.trans.shared.b16 {%0,%1,%2,%3}, [%4];"
                 : "=r"(r[0]), "=r"(r[1]), "=r"(r[2]), "=r"(r[3]) : "r"(addr));
}
__device__ __forceinline__ void mma16816(float* d, const uint32_t* a, const uint32_t* b) {
    asm volatile("mma.sync.aligned.m16n8k16.row.col.f32.bf16.bf16.f32 "
                 "{%0,%1,%2,%3}, {%4,%5,%6,%7}, {%8,%9}, {%0,%1,%2,%3};"
                 : "+f"(d[0]), "+f"(d[1]), "+f"(d[2]), "+f"(d[3])
                 : "r"(a[0]), "r"(a[1]), "r"(a[2]), "r"(a[3]), "r"(b[0]), "r"(b[1]));
}
__device__ __forceinline__ uint32_t bfpk(float a, float b) {
    __nv_bfloat162 h = __floats2bfloat162_rn(a, b);
    return *(uint32_t*)&h;
}
__device__ __forceinline__ void split_store(char* hi, char* lo, int idx, float v) {
    __nv_bfloat16 h = __float2bfloat16_rn(v);
    ((__nv_bfloat16*)hi)[idx] = h;
    ((__nv_bfloat16*)lo)[idx] = __float2bfloat16_rn(v - __bfloat162float(h));
}
__device__ __forceinline__ void split2(float a, float b, uint32_t& hi, uint32_t& lo) {
    __nv_bfloat16 ha = __float2bfloat16_rn(a), hb = __float2bfloat16_rn(b);
    __nv_bfloat162 hp = __halves2bfloat162(ha, hb);
    hi = *(uint32_t*)&hp;
    lo = bfpk(a - __bfloat162float(ha), b - __bfloat162float(hb));
}
__device__ __forceinline__ void gsplit(__nv_bfloat16* hi, __nv_bfloat16* lo, size_t idx, float a, float b) {
    __nv_bfloat16 h0 = __float2bfloat16_rn(a), h1 = __float2bfloat16_rn(b);
    __nv_bfloat162 hp = __halves2bfloat162(h0, h1);
    *(uint32_t*)(hi + idx) = *(uint32_t*)&hp;
    *(uint32_t*)(lo + idx) = bfpk(a - __bfloat162float(h0), b - __bfloat162float(h1));
}

// ================= weight pre-conversion =================
__global__ void wconv_kernel(const float* __restrict__ qkv_w,
                             const float* __restrict__ psw,
                             const float* __restrict__ ptw)
{
    int i = blockIdx.x*256 + threadIdx.x;
    if (i < 96*288) {
        float v = qkv_w[i];
        if ((i % 288) < 96) v *= SCALE;
        __nv_bfloat16 h = __float2bfloat16_rn(v);
        g_wqkvh[i] = h;
        g_wqkvl[i] = __float2bfloat16_rn(v - __bfloat162float(h));
    } else if (i < 96*288 + 96*96) {
        int j = i - 96*288;
        float v = psw[j];
        __nv_bfloat16 h = __float2bfloat16_rn(v);
        g_pswh[j] = h;
        g_pswl[j] = __float2bfloat16_rn(v - __bfloat162float(h));
    } else if (i < 96*288 + 2*96*96) {
        int j = i - 96*288 - 96*96;
        float v = ptw[j];
        __nv_bfloat16 h = __float2bfloat16_rn(v);
        g_ptwh[j] = h;
        g_ptwl[j] = __float2bfloat16_rn(v - __bfloat162float(h));
    }
}

// ================= Kernel A: QKV GEMM =================
__global__ __launch_bounds__(256, 2)
void qkv_mma_kernel(const float* __restrict__ x, const float* __restrict__ qkv_b)
{
    extern __shared__ char smem[];
    const uint32_t sbase = smem_u32(smem);
    float* bias_sm = (float*)(smem + QK_BIAS);

    const int tid  = threadIdx.x;
    const int lane = tid & 31;
    const int warp = tid >> 5;
    const int row0 = blockIdx.x * 128;

    for (int v = tid; v < 128*24; v += 256) {
        int r = v / 24, c = (v - (v/24)*24) * 4;
        float4 f = *(const float4*)(x + (size_t)(row0 + r)*96 + c);
        __nv_bfloat16 h0 = __float2bfloat16_rn(f.x), h1 = __float2bfloat16_rn(f.y);
        __nv_bfloat16 h2 = __float2bfloat16_rn(f.z), h3 = __float2bfloat16_rn(f.w);
        __nv_bfloat162 p0 = __halves2bfloat162(h0, h1);
        __nv_bfloat162 p1 = __halves2bfloat162(h2, h3);
        uint32_t off = (r*LDA + c)*2;
        *(uint32_t*)(smem + QK_AHI + off)     = *(uint32_t*)&p0;
        *(uint32_t*)(smem + QK_AHI + off + 4) = *(uint32_t*)&p1;
        *(uint32_t*)(smem + QK_ALO + off)     = bfpk(f.x - __bfloat162float(h0), f.y - __bfloat162float(h1));
        *(uint32_t*)(smem + QK_ALO + off + 4) = bfpk(f.z - __bfloat162float(h2), f.w - __bfloat162float(h3));
    }
    for (int v = tid; v < 288; v += 256)
        bias_sm[v] = qkv_b[v] * ((v < 96) ? SCALE : 1.0f);
    __syncthreads();

    uint32_t ah[6][4], al[6][4];
    {
        int arow = warp*16 + (lane & 15);
        int acol = (lane >> 4) * 8;
        #pragma unroll
        for (int kt = 0; kt < 6; kt++) {
            uint32_t boff = (arow*LDA + kt*16 + acol)*2;
            ldsm4(ah[kt], sbase + QK_AHI + boff);
            ldsm4(al[kt], sbase + QK_ALO + boff);
        }
    }

    for (int chunk = 0; chunk < 3; chunk++) {
        __syncthreads();
        for (int v = tid; v < 96*48; v += 256) {
            int k = v / 48, j = v - (v/48)*48;
            ((uint32_t*)(smem + QK_BHI))[k*52 + j] = ((const uint32_t*)g_wqkvh)[k*144 + chunk*48 + j];
            ((uint32_t*)(smem + QK_BLO))[k*52 + j] = ((const uint32_t*)g_wqkvl)[k*144 + chunk*48 + j];
        }
        __syncthreads();

        const int brow = lane & 15;
        #pragma unroll
        for (int nt = 0; nt < 12; nt++) {
            const int n0 = nt*8;
            uint32_t bh[6][2], bl[6][2];
            #pragma unroll
            for (int kt = 0; kt < 6; kt++) {
                uint32_t boff = ((kt*16 + brow)*LDA + n0)*2;
                ldsm2t(bh[kt], sbase + QK_BHI + boff);
                ldsm2t(bl[kt], sbase + QK_BLO + boff);
            }
            float acc[4] = {0.f, 0.f, 0.f, 0.f};
            #pragma unroll
            for (int kt = 0; kt < 6; kt++) {
                mma16816(acc, ah[kt], bh[kt]);
                mma16816(acc, al[kt], bh[kt]);
                mma16816(acc, ah[kt], bl[kt]);
            }
            int r  = lane >> 2;
            int c2 = (lane & 3)*2;
            float2 bs = *(float2*)(bias_sm + chunk*96 + n0 + c2);
            size_t gb = (size_t)(row0 + warp*16 + r)*QKV_LD + chunk*96 + n0 + c2;
            gsplit(g_qkvh, g_qkvl, gb,            acc[0] + bs.x, acc[1] + bs.y);
            gsplit(g_qkvh, g_qkvl, gb + 8*QKV_LD, acc[2] + bs.x, acc[3] + bs.y);
        }
    }
}

// ================= Kernel B: in-register FA-style spatial =================
__global__ __launch_bounds__(256, 2)
void spatial_kernel(const float* __restrict__ mask,
                    const float* __restrict__ pb, float* __restrict__ out)
{
    extern __shared__ char smc[];
    const uint32_t sbase = smem_u32(smc);
    float* ms = (float*)(smc + SP_MS);

    const int bt   = blockIdx.x;
    const int tid  = threadIdx.x;
    const int lane = tid & 31;
    const int warp = tid >> 5;

    // ---- raw copies of pre-split q/k/v ----
    {
        const size_t tb = (size_t)bt * NN * QKV_LD;
        for (int v = tid; v < NN*12; v += 256) {
            int r = v / 12, c8 = (v - (v/12)*12)*8;
            size_t src = tb + (size_t)r*QKV_LD + c8;
            uint32_t doff = (r*LDA + c8)*2;
            *(uint4*)(smc + SP_QH + doff) = *(const uint4*)(g_qkvh + src);
            *(uint4*)(smc + SP_QL + doff) = *(const uint4*)(g_qkvl + src);
            *(uint4*)(smc + SP_KH + doff) = *(const uint4*)(g_qkvh + src + 96);
            *(uint4*)(smc + SP_KL + doff) = *(const uint4*)(g_qkvl + src + 96);
            *(uint4*)(smc + SP_VH + doff) = *(const uint4*)(g_qkvh + src + 192);
            *(uint4*)(smc + SP_VL + doff) = *(const uint4*)(g_qkvl + src + 192);
        }
    }
    // zero v rows 49..63
    for (int i = tid; i < 15*52; i += 256) {
        int row = 49 + i/52, cw = i - (i/52)*52;
        ((uint32_t*)(smc + SP_VH))[row*52 + cw] = 0;
        ((uint32_t*)(smc + SP_VL))[row*52 + cw] = 0;
    }
    // mask -> smem
    {
        const float* mrow = mask + (size_t)(bt & 63) * (49*49);
        for (int i = tid; i < 49*49; i += 256) {
            int r = i / 49, c = i - r*49;
            ms[r*52 + c] = mrow[i];
        }
    }
    __syncthreads();

    const int mt    = warp >> 1;
    const int dhalf = warp & 1;
    const int r0    = (mt == 3) ? 33 : mt*16;
    const int qr    = lane >> 2;
    const int qc    = (lane & 3)*2;
    const int row_a = r0 + qr, row_b = r0 + qr + 8;

    for (int h = 0; h < HEADS; h++) {
        // ---- q fragments ----
        uint32_t aqh[2][4], aql[2][4];
        {
            int ar = r0 + (lane & 15);
            #pragma unroll
            for (int kt = 0; kt < 2; kt++) {
                uint32_t off = (ar*LDA + h*32 + kt*16 + (lane >> 4)*8)*2;
                ldsm4(aqh[kt], sbase + SP_QH + off);
                ldsm4(aql[kt], sbase + SP_QL + off);
            }
        }
        // ---- scores: full 56 cols per warp ----
        float sc[7][4];
        {
            int l = lane & 15;
            #pragma unroll
            for (int nt = 0; nt < 7; nt++) {
                uint32_t boff = ((nt*8 + (l & 7))*LDA + h*32 + (l & 8))*2;
                uint32_t bh[2][2], bl[2][2];
                #pragma unroll
                for (int kt = 0; kt < 2; kt++) {
                    ldsm2(bh[kt], sbase + SP_KH + boff + kt*32);
                    ldsm2(bl[kt], sbase + SP_KL + boff + kt*32);
                }
                float acc[4] = {0.f, 0.f, 0.f, 0.f};
                #pragma unroll
                for (int kt = 0; kt < 2; kt++) {
                    mma16816(acc, aqh[kt], bh[kt]);
                    mma16816(acc, aql[kt], bh[kt]);
                    mma16816(acc, aqh[kt], bl[kt]);
                }
                sc[nt][0] = acc[0]; sc[nt][1] = acc[1];
                sc[nt][2] = acc[2]; sc[nt][3] = acc[3];
            }
        }
        // ---- in-register softmax (rows row_a, row_b) ----
        {
            float mx0 = -3.0e38f, mx1 = -3.0e38f;
            #pragma unroll
            for (int nt = 0; nt < 7; nt++) {
                #pragma unroll
                for (int i = 0; i < 2; i++) {
                    int col = nt*8 + qc + i;
                    if (col < 49) {
                        sc[nt][i]   += ms[row_a*52 + col];
                        sc[nt][2+i] += ms[row_b*52 + col];
                    } else {
                        sc[nt][i] = -3.0e38f; sc[nt][2+i] = -3.0e38f;
                    }
                    mx0 = fmaxf(mx0, sc[nt][i]);
                    mx1 = fmaxf(mx1, sc[nt][2+i]);
                }
            }
            mx0 = fmaxf(mx0, __shfl_xor_sync(0xffffffffu, mx0, 1));
            mx0 = fmaxf(mx0, __shfl_xor_sync(0xffffffffu, mx0, 2));
            mx1 = fmaxf(mx1, __shfl_xor_sync(0xffffffffu, mx1, 1));
            mx1 = fmaxf(mx1, __shfl_xor_sync(0xffffffffu, mx1, 2));
            float s0 = 0.f, s1 = 0.f;
            #pragma unroll
            for (int nt = 0; nt < 7; nt++) {
                #pragma unroll
                for (int i = 0; i < 2; i++) {
                    sc[nt][i]   = __expf(sc[nt][i]   - mx0); s0 += sc[nt][i];
                    sc[nt][2+i] = __expf(sc[nt][2+i] - mx1); s1 += sc[nt][2+i];
                }
            }
            s0 += __shfl_xor_sync(0xffffffffu, s0, 1);
            s0 += __shfl_xor_sync(0xffffffffu, s0, 2);
            s1 += __shfl_xor_sync(0xffffffffu, s1, 1);
            s1 += __shfl_xor_sync(0xffffffffu, s1, 2);
            float inv0 = __frcp_rn(s0), inv1 = __frcp_rn(s1);
            #pragma unroll
            for (int nt = 0; nt < 7; nt++) {
                sc[nt][0] *= inv0; sc[nt][1] *= inv0;
                sc[nt][2] *= inv1; sc[nt][3] *= inv1;
            }
        }
        // ---- pack P fragments (C-layout == A-layout) ----
        uint32_t ph[4][4], pl[4][4];
        #pragma unroll
        for (int kt = 0; kt < 4; kt++) {
            int nta = 2*kt, ntb = 2*kt + 1;
            split2(sc[nta][0], sc[nta][1], ph[kt][0], pl[kt][0]);
            split2(sc[nta][2], sc[nta][3], ph[kt][1], pl[kt][1]);
            if (ntb < 7) {
                split2(sc[ntb][0], sc[ntb][1], ph[kt][2], pl[kt][2]);
                split2(sc[ntb][2], sc[ntb][3], ph[kt][3], pl[kt][3]);
            } else {
                ph[kt][2] = 0; ph[kt][3] = 0; pl[kt][2] = 0; pl[kt][3] = 0;
            }
        }
        // ---- PV directly from registers ----
        #pragma unroll
        for (int ntl = 0; ntl < 2; ntl++) {
            int d0 = h*32 + dhalf*16 + ntl*8;
            uint32_t vh01[4], vl01[4], vh23[4], vl23[4];
            ldsm4t(vh01, sbase + SP_VH + ((lane     )*LDA + d0)*2);
            ldsm4t(vl01, sbase + SP_VL + ((lane     )*LDA + d0)*2);
            ldsm4t(vh23, sbase + SP_VH + ((32 + lane)*LDA + d0)*2);
            ldsm4t(vl23, sbase + SP_VL + ((32 + lane)*LDA + d0)*2);
            float o[4] = {0.f, 0.f, 0.f, 0.f};
            #pragma unroll
            for (int kt = 0; kt < 4; kt++) {
                const uint32_t* bh_ = (kt < 2) ? &vh01[(kt & 1)*2] : &vh23[(kt & 1)*2];
                const uint32_t* bl_ = (kt < 2) ? &vl01[(kt & 1)*2] : &vl23[(kt & 1)*2];
                mma16816(o, ph[kt], bh_);
                mma16816(o, pl[kt], bh_);
                mma16816(o, ph[kt], bl_);
            }
            int c0 = d0 + qc;
            split_store(smc + SP_XOH, smc + SP_XOL, row_a*LDA + c0,     o[0]);
            split_store(smc + SP_XOH, smc + SP_XOL, row_a*LDA + c0 + 1, o[1]);
            split_store(smc + SP_XOH, smc + SP_XOL, row_b*LDA + c0,     o[2]);
            split_store(smc + SP_XOH, smc + SP_XOL, row_b*LDA + c0 + 1, o[3]);
        }
    }

    // ---- HMMA projection (weights alias q region) ----
    const int nh = dhalf * 48;
    float acc[6][4];
    #pragma unroll
    for (int nt = 0; nt < 6; nt++)
        acc[nt][0] = acc[nt][1] = acc[nt][2] = acc[nt][3] = 0.f;

    for (int s = 0; s < 3; s++) {
        __syncthreads();
        for (int v = tid; v < 32*48; v += 256) {
            int kl = v / 48, j = v - (v/48)*48;
            ((uint32_t*)(smc + SP_WH))[kl*52 + j] = ((const uint32_t*)g_pswh)[(s*32 + kl)*48 + j];
            ((uint32_t*)(smc + SP_WL))[kl*52 + j] = ((const uint32_t*)g_pswl)[(s*32 + kl)*48 + j];
        }
        __syncthreads();

        uint32_t ah[2][4], al[2][4];
        int arow = r0 + (lane & 15);
        int acol = (lane >> 4)*8;
        #pragma unroll
        for (int kt = 0; kt < 2; kt++) {
            uint32_t off = (arow*LDA + s*32 + kt*16 + acol)*2;
            ldsm4(ah[kt], sbase + SP_XOH + off);
            ldsm4(al[kt], sbase + SP_XOL + off);
        }
        #pragma unroll
        for (int nt = 0; nt < 6; nt++) {
            uint32_t bh[2][2], bl[2][2];
            #pragma unroll
            for (int kt = 0; kt < 2; kt++) {
                uint32_t off = ((kt*16 + (lane & 15))*LDA + nh + nt*8)*2;
                ldsm2t(bh[kt], sbase + SP_WH + off);
                ldsm2t(bl[kt], sbase + SP_WL + off);
            }
            #pragma unroll
            for (int kt = 0; kt < 2; kt++) {
                mma16816(acc[nt], ah[kt], bh[kt]);
                mma16816(acc[nt], al[kt], bh[kt]);
                mma16816(acc[nt], ah[kt], bl[kt]);
            }
        }
    }

    float* og = out + (size_t)bt * (NN*CDIM);
    #pragma unroll
    for (int nt = 0; nt < 6; nt++) {
        int col = nh + nt*8 + qc;
        float2 bs = {pb[col], pb[col+1]};
        int ra = r0 + qr, rb = r0 + qr + 8;
        if (ra < NN) { og[ra*CDIM + col] = acc[nt][0] + bs.x; og[ra*CDIM + col + 1] = acc[nt][1] + bs.y; }
        if (rb < NN) { og[rb*CDIM + col] = acc[nt][2] + bs.x; og[rb*CDIM + col + 1] = acc[nt][3] + bs.y; }
    }
}

// ================= Kernel C: temporal (unchanged) =================
__global__ __launch_bounds__(256, 2)
void temporal_kernel(const float* __restrict__ pb, float* __restrict__ out)
{
    extern __shared__ char smc[];
    const uint32_t sbase = smem_u32(smc);
    float* qs = (float*)(smc + T_QS);
    float* ks = (float*)(smc + T_KS);
    float* vs = (float*)(smc + T_VS);
    float* at = (float*)(smc + T_AT);
    char*  xoh = smc + T_XOH;
    char*  xol = smc + T_XOL;

    const int g    = blockIdx.x;
    const int b    = g / 7;
    const int n0   = (g - b*7) * 7;
    const int tid  = threadIdx.x;
    const int lane = tid & 31;
    const int warp = tid >> 5;

    for (int v = tid; v < 56*36; v += 256) {
        int r = v / 36, m = v - (v/36)*36;
        int mat = m / 12, c8 = (m - mat*12)*8;
        int sl = r >> 3, t = r & 7;
        size_t src = ((size_t)(b*TT + t)*NN + n0 + sl)*QKV_LD + mat*96 + c8;
        uint4 hv = *(const uint4*)(g_qkvh + src);
        uint4 lv = *(const uint4*)(g_qkvl + src);
        float* dst = ((mat == 0) ? qs : (mat == 1) ? ks : vs) + r*PADX + c8;
        const __nv_bfloat162* hp = (const __nv_bfloat162*)&hv;
        const __nv_bfloat162* lp = (const __nv_bfloat162*)&lv;
        #pragma unroll
        for (int p = 0; p < 4; p++) {
            float2 hf = __bfloat1622float2(hp[p]);
            float2 lf = __bfloat1622float2(lp[p]);
            dst[p*2]   = hf.x + lf.x;
            dst[p*2+1] = hf.y + lf.y;
        }
    }
    __syncthreads();

    for (int e = tid; e < 7*HEADS*64; e += 256) {
        int sl  = e / 192;
        int rem = e - sl*192;
        int h   = rem >> 6;
        int ij  = rem & 63;
        int i   = ij >> 3, j = ij & 7;
        const float4* qp = (const float4*)(qs + (sl*8 + i)*PADX + h*HD);
        const float4* kp = (const float4*)(ks + (sl*8 + j)*PADX + h*HD);
        float s = 0.f;
        #pragma unroll
        for (int d = 0; d < 8; d++) {
            float4 a = qp[d], bb = kp[d];
            s += a.x*bb.x + a.y*bb.y + a.z*bb.z + a.w*bb.w;
        }
        at[e] = s;
    }
    __syncthreads();

    if (tid < 7*HEADS*8) {
        float* arow = at + tid*8;
        float4 a0 = *(float4*)arow;
        float4 a1 = *(float4*)(arow + 4);
        float mx = fmaxf(fmaxf(fmaxf(a0.x, a0.y), fmaxf(a0.z, a0.w)),
                         fmaxf(fmaxf(a1.x, a1.y), fmaxf(a1.z, a1.w)));
        float e0 = __expf(a0.x - mx), e1 = __expf(a0.y - mx), e2 = __expf(a0.z - mx), e3 = __expf(a0.w - mx);
        float e4 = __expf(a1.x - mx), e5 = __expf(a1.y - mx), e6 = __expf(a1.z - mx), e7 = __expf(a1.w - mx);
        float inv = __frcp_rn(e0+e1+e2+e3+e4+e5+e6+e7);
        a0.x = e0*inv; a0.y = e1*inv; a0.z = e2*inv; a0.w = e3*inv;
        a1.x = e4*inv; a1.y = e5*inv; a1.z = e6*inv; a1.w = e7*inv;
        *(float4*)arow = a0;
        *(float4*)(arow + 4) = a1;
    }
    __syncthreads();

    for (int rr = 0; rr < 7; rr++) {
        const float* atb = at + rr*192 + warp*8;
        float A0[8], A1[8], A2[8];
        *(float4*)A0     = *(const float4*)(atb);
        *(float4*)(A0+4) = *(const float4*)(atb + 4);
        *(float4*)A1     = *(const float4*)(atb + 64);
        *(float4*)(A1+4) = *(const float4*)(atb + 68);
        *(float4*)A2     = *(const float4*)(atb + 128);
        *(float4*)(A2+4) = *(const float4*)(atb + 132);
        float acc0 = 0.f, acc1 = 0.f, acc2 = 0.f;
        #pragma unroll
        for (int j = 0; j < 8; j++) {
            const float* vp = vs + (rr*8 + j)*PADX + lane;
            acc0 += A0[j]*vp[0];
            acc1 += A1[j]*vp[32];
            acc2 += A2[j]*vp[64];
        }
        int row = warp + 8*rr;
        split_store(xoh, xol, row*LDA + lane,      acc0);
        split_store(xoh, xol, row*LDA + lane + 32, acc1);
        split_store(xoh, xol, row*LDA + lane + 64, acc2);
    }

    const int wt = warp >> 1;
    const int nh = (warp & 1) * 48;
    const int r0 = (wt == 3) ? 40 : wt*16;

    float acc[6][4];
    #pragma unroll
    for (int nt = 0; nt < 6; nt++)
        acc[nt][0] = acc[nt][1] = acc[nt][2] = acc[nt][3] = 0.f;

    for (int s = 0; s < 3; s++) {
        __syncthreads();
        for (int v = tid; v < 32*48; v += 256) {
            int kl = v / 48, j = v - (v/48)*48;
            ((uint32_t*)(smc + T_WH))[kl*52 + j] = ((const uint32_t*)g_ptwh)[(s*32 + kl)*48 + j];
            ((uint32_t*)(smc + T_WL))[kl*52 + j] = ((const uint32_t*)g_ptwl)[(s*32 + kl)*48 + j];
        }
        __syncthreads();

        uint32_t ah[2][4], al[2][4];
        int arow = r0 + (lane & 15);
        int acol = (lane >> 4)*8;
        #pragma unroll
        for (int kt = 0; kt < 2; kt++) {
            uint32_t off = (arow*LDA + s*32 + kt*16 + acol)*2;
            ldsm4(ah[kt], sbase + T_XOH + off);
            ldsm4(al[kt], sbase + T_XOL + off);
        }
        #pragma unroll
        for (int nt = 0; nt < 6; nt++) {
            uint32_t bh[2][2], bl[2][2];
            #pragma unroll
            for (int kt = 0; kt < 2; kt++) {
                uint32_t off = ((kt*16 + (lane & 15))*LDA + nh + nt*8)*2;
                ldsm2t(bh[kt], sbase + T_WH + off);
                ldsm2t(bl[kt], sbase + T_WL + off);
            }
            #pragma unroll
            for (int kt = 0; kt < 2; kt++) {
                mma16816(acc[nt], ah[kt], bh[kt]);
                mma16816(acc[nt], al[kt], bh[kt]);
                mma16816(acc[nt], ah[kt], bl[kt]);
            }
        }
    }

    const int r  = lane >> 2;
    const int c2 = (lane & 3)*2;
    #pragma unroll
    for (int nt = 0; nt < 6; nt++) {
        int col = nh + nt*8 + c2;
        float2 bs = {pb[col], pb[col+1]};
        #pragma unroll
        for (int half = 0; half < 2; half++) {
            int row = r0 + r + half*8;
            if (row < 56) {
                int sl = row >> 3, t = row & 7;
                float* og = out + (((size_t)b*TT + t)*NN + (n0 + sl))*CDIM;
                og[col]     = acc[nt][half*2]     + bs.x;
                og[col + 1] = acc[nt][half*2 + 1] + bs.y;
            }
        }
    }
}

extern "C" void kernel_launch(void* const* d_in, const int* in_sizes, int n_in,
                              void* d_out, int out_size)
{
    const float* x      = (const float*)d_in[0];
    const float* mask   = (const float*)d_in[1];
    const float* qkv_w  = (const float*)d_in[2];
    const float* qkv_b  = (const float*)d_in[3];
    const float* psw    = (const float*)d_in[4];
    const float* psb    = (const float*)d_in[5];
    const float* ptw    = (const float*)d_in[6];
    const float* ptb    = (const float*)d_in[7];

    float* out_t  = (float*)d_out;
    float* out_sp = out_t + (size_t)BATCH*TT*NN*CDIM;

    cudaFuncSetAttribute(qkv_mma_kernel,  cudaFuncAttributeMaxDynamicSharedMemorySize, SMEM_QKV);
    cudaFuncSetAttribute(spatial_kernel,  cudaFuncAttributeMaxDynamicSharedMemorySize, SMEM_SP);
    cudaFuncSetAttribute(temporal_kernel, cudaFuncAttributeMaxDynamicSharedMemorySize, SMEM_T);

    wconv_kernel<<<180, 256>>>(qkv_w, psw, ptw);
    qkv_mma_kernel<<<NTOK/128, 256, SMEM_QKV>>>(x, qkv_b);
    spatial_kernel<<<BATCH*TT, 256, SMEM_SP>>>(mask, psb, out_sp);
    temporal_kernel<<<BATCH*7, 256, SMEM_T>>>(ptb, out_t);
}

// round 14
// speedup vs baseline: 4.0884x; 1.0946x over previous
#include <cuda_runtime.h>
#include <cuda_bf16.h>
#include <cstdint>

#define BATCH   1024
#define TT      8
#define NN      49
#define CDIM    96
#define HEADS   3
#define HD      32
#define NTOK    (BATCH*TT*NN)
#define QKV_LD  288
#define LDA     104
#define SCALE   0.17677669529663687f

// canonical bf16 hi/lo storage
__device__ __nv_bfloat16 g_qkvh[(size_t)NTOK * QKV_LD];
__device__ __nv_bfloat16 g_qkvl[(size_t)NTOK * QKV_LD];
__device__ __nv_bfloat16 g_wqkvh[96*288], g_wqkvl[96*288];
__device__ __nv_bfloat16 g_pswh[96*96],  g_pswl[96*96];
__device__ __nv_bfloat16 g_ptwh[96*96],  g_ptwl[96*96];

// ---- qkv smem (bytes) ----
#define QK_AHI   0
#define QK_ALO   26624
#define QK_BHI   53248
#define QK_BLO   73216
#define QK_BIAS  93184
#define SMEM_QKV 94336

// ---- spatial smem (bytes) ----
#define SP_QH    0
#define SP_QL    10192
#define SP_WH    0
#define SP_WL    6656
#define SP_KH    20384
#define SP_KL    32032
#define SP_VH    43680
#define SP_VL    56992
#define SP_XOH   70304
#define SP_XOL   80496
#define SP_MS    90688
#define SMEM_SP  100880

// ---- temporal smem (bytes): 56 rows x LDA bf16 per buffer ----
#define T_QH     0                   // 11648
#define T_QL     11648
#define T_WH     0                   // alias q region during proj
#define T_WL     6656
#define T_KH     23296
#define T_KL     34944
#define T_VH     46592
#define T_VL     58240
#define T_XOH    69888
#define T_XOL    81536
#define SMEM_T   93184

// ======================= helpers =======================
__device__ __forceinline__ uint32_t smem_u32(const void* p) {
    uint32_t a;
    asm("{ .reg .u64 t; cvta.to.shared.u64 t, %1; cvt.u32.u64 %0, t; }" : "=r"(a) : "l"(p));
    return a;
}
__device__ __forceinline__ void ldsm4(uint32_t* r, uint32_t addr) {
    asm volatile("ldmatrix.sync.aligned.m8n8.x4.shared.b16 {%0,%1,%2,%3}, [%4];"
                 : "=r"(r[0]), "=r"(r[1]), "=r"(r[2]), "=r"(r[3]) : "r"(addr));
}
__device__ __forceinline__ void ldsm2(uint32_t* r, uint32_t addr) {
    asm volatile("ldmatrix.sync.aligned.m8n8.x2.shared.b16 {%0,%1}, [%2];"
                 : "=r"(r[0]), "=r"(r[1]) : "r"(addr));
}
__device__ __forceinline__ void ldsm2t(uint32_t* r, uint32_t addr) {
    asm volatile("ldmatrix.sync.aligned.m8n8.x2.trans.shared.b16 {%0,%1}, [%2];"
                 : "=r"(r[0]), "=r"(r[1]) : "r"(addr));
}
__device__ __forceinline__ void ldsm4t(uint32_t* r, uint32_t addr) {
    asm volatile("ldmatrix.sync.aligned.m8n8.x4.trans.shared.b16 {%0,%1,%2,%3}, [%4];"
                 : "=r"(r[0]), "=r"(r[1]), "=r"(r[2]), "=r"(r[3]) : "r"(addr));
}
__device__ __forceinline__ void mma16816(float* d, const uint32_t* a, const uint32_t* b) {
    asm volatile("mma.sync.aligned.m16n8k16.row.col.f32.bf16.bf16.f32 "
                 "{%0,%1,%2,%3}, {%4,%5,%6,%7}, {%8,%9}, {%0,%1,%2,%3};"
                 : "+f"(d[0]), "+f"(d[1]), "+f"(d[2]), "+f"(d[3])
                 : "r"(a[0]), "r"(a[1]), "r"(a[2]), "r"(a[3]), "r"(b[0]), "r"(b[1]));
}
__device__ __forceinline__ uint32_t bfpk(float a, float b) {
    __nv_bfloat162 h = __floats2bfloat162_rn(a, b);
    return *(uint32_t*)&h;
}
__device__ __forceinline__ void split_store(char* hi, char* lo, int idx, float v) {
    __nv_bfloat16 h = __float2bfloat16_rn(v);
    ((__nv_bfloat16*)hi)[idx] = h;
    ((__nv_bfloat16*)lo)[idx] = __float2bfloat16_rn(v - __bfloat162float(h));
}
__device__ __forceinline__ void split2(float a, float b, uint32_t& hi, uint32_t& lo) {
    __nv_bfloat16 ha = __float2bfloat16_rn(a), hb = __float2bfloat16_rn(b);
    __nv_bfloat162 hp = __halves2bfloat162(ha, hb);
    hi = *(uint32_t*)&hp;
    lo = bfpk(a - __bfloat162float(ha), b - __bfloat162float(hb));
}
__device__ __forceinline__ void gsplit(__nv_bfloat16* hi, __nv_bfloat16* lo, size_t idx, float a, float b) {
    __nv_bfloat16 h0 = __float2bfloat16_rn(a), h1 = __float2bfloat16_rn(b);
    __nv_bfloat162 hp = __halves2bfloat162(h0, h1);
    *(uint32_t*)(hi + idx) = *(uint32_t*)&hp;
    *(uint32_t*)(lo + idx) = bfpk(a - __bfloat162float(h0), b - __bfloat162float(h1));
}

// ================= weight pre-conversion =================
__global__ void wconv_kernel(const float* __restrict__ qkv_w,
                             const float* __restrict__ psw,
                             const float* __restrict__ ptw)
{
    int i = blockIdx.x*256 + threadIdx.x;
    if (i < 96*288) {
        float v = qkv_w[i];
        if ((i % 288) < 96) v *= SCALE;
        __nv_bfloat16 h = __float2bfloat16_rn(v);
        g_wqkvh[i] = h;
        g_wqkvl[i] = __float2bfloat16_rn(v - __bfloat162float(h));
    } else if (i < 96*288 + 96*96) {
        int j = i - 96*288;
        float v = psw[j];
        __nv_bfloat16 h = __float2bfloat16_rn(v);
        g_pswh[j] = h;
        g_pswl[j] = __float2bfloat16_rn(v - __bfloat162float(h));
    } else if (i < 96*288 + 2*96*96) {
        int j = i - 96*288 - 96*96;
        float v = ptw[j];
        __nv_bfloat16 h = __float2bfloat16_rn(v);
        g_ptwh[j] = h;
        g_ptwl[j] = __float2bfloat16_rn(v - __bfloat162float(h));
    }
}

// ================= Kernel A: QKV GEMM =================
__global__ __launch_bounds__(256, 2)
void qkv_mma_kernel(const float* __restrict__ x, const float* __restrict__ qkv_b)
{
    extern __shared__ char smem[];
    const uint32_t sbase = smem_u32(smem);
    float* bias_sm = (float*)(smem + QK_BIAS);

    const int tid  = threadIdx.x;
    const int lane = tid & 31;
    const int warp = tid >> 5;
    const int row0 = blockIdx.x * 128;

    for (int v = tid; v < 128*24; v += 256) {
        int r = v / 24, c = (v - (v/24)*24) * 4;
        float4 f = *(const float4*)(x + (size_t)(row0 + r)*96 + c);
        __nv_bfloat16 h0 = __float2bfloat16_rn(f.x), h1 = __float2bfloat16_rn(f.y);
        __nv_bfloat16 h2 = __float2bfloat16_rn(f.z), h3 = __float2bfloat16_rn(f.w);
        __nv_bfloat162 p0 = __halves2bfloat162(h0, h1);
        __nv_bfloat162 p1 = __halves2bfloat162(h2, h3);
        uint32_t off = (r*LDA + c)*2;
        *(uint32_t*)(smem + QK_AHI + off)     = *(uint32_t*)&p0;
        *(uint32_t*)(smem + QK_AHI + off + 4) = *(uint32_t*)&p1;
        *(uint32_t*)(smem + QK_ALO + off)     = bfpk(f.x - __bfloat162float(h0), f.y - __bfloat162float(h1));
        *(uint32_t*)(smem + QK_ALO + off + 4) = bfpk(f.z - __bfloat162float(h2), f.w - __bfloat162float(h3));
    }
    for (int v = tid; v < 288; v += 256)
        bias_sm[v] = qkv_b[v] * ((v < 96) ? SCALE : 1.0f);
    __syncthreads();

    uint32_t ah[6][4], al[6][4];
    {
        int arow = warp*16 + (lane & 15);
        int acol = (lane >> 4) * 8;
        #pragma unroll
        for (int kt = 0; kt < 6; kt++) {
            uint32_t boff = (arow*LDA + kt*16 + acol)*2;
            ldsm4(ah[kt], sbase + QK_AHI + boff);
            ldsm4(al[kt], sbase + QK_ALO + boff);
        }
    }

    for (int chunk = 0; chunk < 3; chunk++) {
        __syncthreads();
        for (int v = tid; v < 96*48; v += 256) {
            int k = v / 48, j = v - (v/48)*48;
            ((uint32_t*)(smem + QK_BHI))[k*52 + j] = ((const uint32_t*)g_wqkvh)[k*144 + chunk*48 + j];
            ((uint32_t*)(smem + QK_BLO))[k*52 + j] = ((const uint32_t*)g_wqkvl)[k*144 + chunk*48 + j];
        }
        __syncthreads();

        const int brow = lane & 15;
        #pragma unroll
        for (int nt = 0; nt < 12; nt++) {
            const int n0 = nt*8;
            uint32_t bh[6][2], bl[6][2];
            #pragma unroll
            for (int kt = 0; kt < 6; kt++) {
                uint32_t boff = ((kt*16 + brow)*LDA + n0)*2;
                ldsm2t(bh[kt], sbase + QK_BHI + boff);
                ldsm2t(bl[kt], sbase + QK_BLO + boff);
            }
            float acc[4] = {0.f, 0.f, 0.f, 0.f};
            #pragma unroll
            for (int kt = 0; kt < 6; kt++) {
                mma16816(acc, ah[kt], bh[kt]);
                mma16816(acc, al[kt], bh[kt]);
                mma16816(acc, ah[kt], bl[kt]);
            }
            int r  = lane >> 2;
            int c2 = (lane & 3)*2;
            float2 bs = *(float2*)(bias_sm + chunk*96 + n0 + c2);
            size_t gb = (size_t)(row0 + warp*16 + r)*QKV_LD + chunk*96 + n0 + c2;
            gsplit(g_qkvh, g_qkvl, gb,            acc[0] + bs.x, acc[1] + bs.y);
            gsplit(g_qkvh, g_qkvl, gb + 8*QKV_LD, acc[2] + bs.x, acc[3] + bs.y);
        }
    }
}

// ================= Kernel B: in-register FA-style spatial =================
__global__ __launch_bounds__(256, 2)
void spatial_kernel(const float* __restrict__ mask,
                    const float* __restrict__ pb, float* __restrict__ out)
{
    extern __shared__ char smc[];
    const uint32_t sbase = smem_u32(smc);
    float* ms = (float*)(smc + SP_MS);

    const int bt   = blockIdx.x;
    const int tid  = threadIdx.x;
    const int lane = tid & 31;
    const int warp = tid >> 5;

    {
        const size_t tb = (size_t)bt * NN * QKV_LD;
        for (int v = tid; v < NN*12; v += 256) {
            int r = v / 12, c8 = (v - (v/12)*12)*8;
            size_t src = tb + (size_t)r*QKV_LD + c8;
            uint32_t doff = (r*LDA + c8)*2;
            *(uint4*)(smc + SP_QH + doff) = *(const uint4*)(g_qkvh + src);
            *(uint4*)(smc + SP_QL + doff) = *(const uint4*)(g_qkvl + src);
            *(uint4*)(smc + SP_KH + doff) = *(const uint4*)(g_qkvh + src + 96);
            *(uint4*)(smc + SP_KL + doff) = *(const uint4*)(g_qkvl + src + 96);
            *(uint4*)(smc + SP_VH + doff) = *(const uint4*)(g_qkvh + src + 192);
            *(uint4*)(smc + SP_VL + doff) = *(const uint4*)(g_qkvl + src + 192);
        }
    }
    for (int i = tid; i < 15*52; i += 256) {
        int row = 49 + i/52, cw = i - (i/52)*52;
        ((uint32_t*)(smc + SP_VH))[row*52 + cw] = 0;
        ((uint32_t*)(smc + SP_VL))[row*52 + cw] = 0;
    }
    {
        const float* mrow = mask + (size_t)(bt & 63) * (49*49);
        for (int i = tid; i < 49*49; i += 256) {
            int r = i / 49, c = i - r*49;
            ms[r*52 + c] = mrow[i];
        }
    }
    __syncthreads();

    const int mt    = warp >> 1;
    const int dhalf = warp & 1;
    const int r0    = (mt == 3) ? 33 : mt*16;
    const int qr    = lane >> 2;
    const int qc    = (lane & 3)*2;
    const int row_a = r0 + qr, row_b = r0 + qr + 8;

    for (int h = 0; h < HEADS; h++) {
        uint32_t aqh[2][4], aql[2][4];
        {
            int ar = r0 + (lane & 15);
            #pragma unroll
            for (int kt = 0; kt < 2; kt++) {
                uint32_t off = (ar*LDA + h*32 + kt*16 + (lane >> 4)*8)*2;
                ldsm4(aqh[kt], sbase + SP_QH + off);
                ldsm4(aql[kt], sbase + SP_QL + off);
            }
        }
        float sc[7][4];
        {
            int l = lane & 15;
            #pragma unroll
            for (int nt = 0; nt < 7; nt++) {
                uint32_t boff = ((nt*8 + (l & 7))*LDA + h*32 + (l & 8))*2;
                uint32_t bh[2][2], bl[2][2];
                #pragma unroll
                for (int kt = 0; kt < 2; kt++) {
                    ldsm2(bh[kt], sbase + SP_KH + boff + kt*32);
                    ldsm2(bl[kt], sbase + SP_KL + boff + kt*32);
                }
                float acc[4] = {0.f, 0.f, 0.f, 0.f};
                #pragma unroll
                for (int kt = 0; kt < 2; kt++) {
                    mma16816(acc, aqh[kt], bh[kt]);
                    mma16816(acc, aql[kt], bh[kt]);
                    mma16816(acc, aqh[kt], bl[kt]);
                }
                sc[nt][0] = acc[0]; sc[nt][1] = acc[1];
                sc[nt][2] = acc[2]; sc[nt][3] = acc[3];
            }
        }
        {
            float mx0 = -3.0e38f, mx1 = -3.0e38f;
            #pragma unroll
            for (int nt = 0; nt < 7; nt++) {
                #pragma unroll
                for (int i = 0; i < 2; i++) {
                    int col = nt*8 + qc + i;
                    if (col < 49) {
                        sc[nt][i]   += ms[row_a*52 + col];
                        sc[nt][2+i] += ms[row_b*52 + col];
                    } else {
                        sc[nt][i] = -3.0e38f; sc[nt][2+i] = -3.0e38f;
                    }
                    mx0 = fmaxf(mx0, sc[nt][i]);
                    mx1 = fmaxf(mx1, sc[nt][2+i]);
                }
            }
            mx0 = fmaxf(mx0, __shfl_xor_sync(0xffffffffu, mx0, 1));
            mx0 = fmaxf(mx0, __shfl_xor_sync(0xffffffffu, mx0, 2));
            mx1 = fmaxf(mx1, __shfl_xor_sync(0xffffffffu, mx1, 1));
            mx1 = fmaxf(mx1, __shfl_xor_sync(0xffffffffu, mx1, 2));
            float s0 = 0.f, s1 = 0.f;
            #pragma unroll
            for (int nt = 0; nt < 7; nt++) {
                #pragma unroll
                for (int i = 0; i < 2; i++) {
                    sc[nt][i]   = __expf(sc[nt][i]   - mx0); s0 += sc[nt][i];
                    sc[nt][2+i] = __expf(sc[nt][2+i] - mx1); s1 += sc[nt][2+i];
                }
            }
            s0 += __shfl_xor_sync(0xffffffffu, s0, 1);
            s0 += __shfl_xor_sync(0xffffffffu, s0, 2);
            s1 += __shfl_xor_sync(0xffffffffu, s1, 1);
            s1 += __shfl_xor_sync(0xffffffffu, s1, 2);
            float inv0 = __frcp_rn(s0), inv1 = __frcp_rn(s1);
            #pragma unroll
            for (int nt = 0; nt < 7; nt++) {
                sc[nt][0] *= inv0; sc[nt][1] *= inv0;
                sc[nt][2] *= inv1; sc[nt][3] *= inv1;
            }
        }
        uint32_t ph[4][4], pl[4][4];
        #pragma unroll
        for (int kt = 0; kt < 4; kt++) {
            int nta = 2*kt, ntb = 2*kt + 1;
            split2(sc[nta][0], sc[nta][1], ph[kt][0], pl[kt][0]);
            split2(sc[nta][2], sc[nta][3], ph[kt][1], pl[kt][1]);
            if (ntb < 7) {
                split2(sc[ntb][0], sc[ntb][1], ph[kt][2], pl[kt][2]);
                split2(sc[ntb][2], sc[ntb][3], ph[kt][3], pl[kt][3]);
            } else {
                ph[kt][2] = 0; ph[kt][3] = 0; pl[kt][2] = 0; pl[kt][3] = 0;
            }
        }
        #pragma unroll
        for (int ntl = 0; ntl < 2; ntl++) {
            int d0 = h*32 + dhalf*16 + ntl*8;
            uint32_t vh01[4], vl01[4], vh23[4], vl23[4];
            ldsm4t(vh01, sbase + SP_VH + ((lane     )*LDA + d0)*2);
            ldsm4t(vl01, sbase + SP_VL + ((lane     )*LDA + d0)*2);
            ldsm4t(vh23, sbase + SP_VH + ((32 + lane)*LDA + d0)*2);
            ldsm4t(vl23, sbase + SP_VL + ((32 + lane)*LDA + d0)*2);
            float o[4] = {0.f, 0.f, 0.f, 0.f};
            #pragma unroll
            for (int kt = 0; kt < 4; kt++) {
                const uint32_t* bh_ = (kt < 2) ? &vh01[(kt & 1)*2] : &vh23[(kt & 1)*2];
                const uint32_t* bl_ = (kt < 2) ? &vl01[(kt & 1)*2] : &vl23[(kt & 1)*2];
                mma16816(o, ph[kt], bh_);
                mma16816(o, pl[kt], bh_);
                mma16816(o, ph[kt], bl_);
            }
            int c0 = d0 + qc;
            split_store(smc + SP_XOH, smc + SP_XOL, row_a*LDA + c0,     o[0]);
            split_store(smc + SP_XOH, smc + SP_XOL, row_a*LDA + c0 + 1, o[1]);
            split_store(smc + SP_XOH, smc + SP_XOL, row_b*LDA + c0,     o[2]);
            split_store(smc + SP_XOH, smc + SP_XOL, row_b*LDA + c0 + 1, o[3]);
        }
    }

    const int nh = dhalf * 48;
    float acc[6][4];
    #pragma unroll
    for (int nt = 0; nt < 6; nt++)
        acc[nt][0] = acc[nt][1] = acc[nt][2] = acc[nt][3] = 0.f;

    for (int s = 0; s < 3; s++) {
        __syncthreads();
        for (int v = tid; v < 32*48; v += 256) {
            int kl = v / 48, j = v - (v/48)*48;
            ((uint32_t*)(smc + SP_WH))[kl*52 + j] = ((const uint32_t*)g_pswh)[(s*32 + kl)*48 + j];
            ((uint32_t*)(smc + SP_WL))[kl*52 + j] = ((const uint32_t*)g_pswl)[(s*32 + kl)*48 + j];
        }
        __syncthreads();

        uint32_t ah[2][4], al[2][4];
        int arow = r0 + (lane & 15);
        int acol = (lane >> 4)*8;
        #pragma unroll
        for (int kt = 0; kt < 2; kt++) {
            uint32_t off = (arow*LDA + s*32 + kt*16 + acol)*2;
            ldsm4(ah[kt], sbase + SP_XOH + off);
            ldsm4(al[kt], sbase + SP_XOL + off);
        }
        #pragma unroll
        for (int nt = 0; nt < 6; nt++) {
            uint32_t bh[2][2], bl[2][2];
            #pragma unroll
            for (int kt = 0; kt < 2; kt++) {
                uint32_t off = ((kt*16 + (lane & 15))*LDA + nh + nt*8)*2;
                ldsm2t(bh[kt], sbase + SP_WH + off);
                ldsm2t(bl[kt], sbase + SP_WL + off);
            }
            #pragma unroll
            for (int kt = 0; kt < 2; kt++) {
                mma16816(acc[nt], ah[kt], bh[kt]);
                mma16816(acc[nt], al[kt], bh[kt]);
                mma16816(acc[nt], ah[kt], bl[kt]);
            }
        }
    }

    float* og = out + (size_t)bt * (NN*CDIM);
    #pragma unroll
    for (int nt = 0; nt < 6; nt++) {
        int col = nh + nt*8 + qc;
        float2 bs = {pb[col], pb[col+1]};
        int ra = r0 + qr, rb = r0 + qr + 8;
        if (ra < NN) { og[ra*CDIM + col] = acc[nt][0] + bs.x; og[ra*CDIM + col + 1] = acc[nt][1] + bs.y; }
        if (rb < NN) { og[rb*CDIM + col] = acc[nt][2] + bs.x; og[rb*CDIM + col + 1] = acc[nt][3] + bs.y; }
    }
}

// ================= Kernel C: in-register HMMA temporal =================
__global__ __launch_bounds__(256, 2)
void temporal_kernel(const float* __restrict__ pb, float* __restrict__ out)
{
    extern __shared__ char smc[];
    const uint32_t sbase = smem_u32(smc);

    const int g    = blockIdx.x;
    const int b    = g / 7;
    const int n0   = (g - b*7) * 7;
    const int tid  = threadIdx.x;
    const int lane = tid & 31;
    const int warp = tid >> 5;

    // ---- stage pre-split q/k/v, row r = sl*8 + t ----
    for (int v = tid; v < 56*12; v += 256) {
        int r = v / 12, c8 = (v - (v/12)*12)*8;
        int sl = r >> 3, t = r & 7;
        size_t src = ((size_t)(b*TT + t)*NN + n0 + sl)*QKV_LD + c8;
        uint32_t doff = (r*LDA + c8)*2;
        *(uint4*)(smc + T_QH + doff) = *(const uint4*)(g_qkvh + src);
        *(uint4*)(smc + T_QL + doff) = *(const uint4*)(g_qkvl + src);
        *(uint4*)(smc + T_KH + doff) = *(const uint4*)(g_qkvh + src + 96);
        *(uint4*)(smc + T_KL + doff) = *(const uint4*)(g_qkvl + src + 96);
        *(uint4*)(smc + T_VH + doff) = *(const uint4*)(g_qkvh + src + 192);
        *(uint4*)(smc + T_VL + doff) = *(const uint4*)(g_qkvl + src + 192);
    }
    __syncthreads();

    const int mt    = warp >> 1;
    const int dhalf = warp & 1;
    const int r0    = (mt == 3) ? 40 : mt*16;   // tile spans 2 seqs; tile3 overlaps tile2 on seq5 (benign dup)
    const int qr    = lane >> 2;
    const int qc    = (lane & 3)*2;
    const int row_a = r0 + qr, row_b = r0 + qr + 8;

    for (int h = 0; h < HEADS; h++) {
        // ---- q fragments (16 rows x K=32) ----
        uint32_t aqh[2][4], aql[2][4];
        {
            int ar = r0 + (lane & 15);
            #pragma unroll
            for (int kt = 0; kt < 2; kt++) {
                uint32_t off = (ar*LDA + h*32 + kt*16 + (lane >> 4)*8)*2;
                ldsm4(aqh[kt], sbase + T_QH + off);
                ldsm4(aql[kt], sbase + T_QL + off);
            }
        }
        // ---- scores 16x16 (2 n-tiles of 8 keys = the tile's 2 seqs) ----
        float sc[2][4];
        {
            int l = lane & 15;
            #pragma unroll
            for (int nt = 0; nt < 2; nt++) {
                uint32_t boff = ((r0 + nt*8 + (l & 7))*LDA + h*32 + (l & 8))*2;
                uint32_t bh[2][2], bl[2][2];
                #pragma unroll
                for (int kt = 0; kt < 2; kt++) {
                    ldsm2(bh[kt], sbase + T_KH + boff + kt*32);
                    ldsm2(bl[kt], sbase + T_KL + boff + kt*32);
                }
                float acc[4] = {0.f, 0.f, 0.f, 0.f};
                #pragma unroll
                for (int kt = 0; kt < 2; kt++) {
                    mma16816(acc, aqh[kt], bh[kt]);
                    mma16816(acc, aql[kt], bh[kt]);
                    mma16816(acc, aqh[kt], bl[kt]);
                }
                sc[nt][0] = acc[0]; sc[nt][1] = acc[1];
                sc[nt][2] = acc[2]; sc[nt][3] = acc[3];
            }
        }
        // ---- block-diagonal softmax: row_a valid in nt0, row_b valid in nt1 ----
        {
            float mx0 = fmaxf(sc[0][0], sc[0][1]);
            float mx1 = fmaxf(sc[1][2], sc[1][3]);
            mx0 = fmaxf(mx0, __shfl_xor_sync(0xffffffffu, mx0, 1));
            mx0 = fmaxf(mx0, __shfl_xor_sync(0xffffffffu, mx0, 2));
            mx1 = fmaxf(mx1, __shfl_xor_sync(0xffffffffu, mx1, 1));
            mx1 = fmaxf(mx1, __shfl_xor_sync(0xffffffffu, mx1, 2));
            float e00 = __expf(sc[0][0] - mx0), e01 = __expf(sc[0][1] - mx0);
            float e12 = __expf(sc[1][2] - mx1), e13 = __expf(sc[1][3] - mx1);
            float s0 = e00 + e01, s1 = e12 + e13;
            s0 += __shfl_xor_sync(0xffffffffu, s0, 1);
            s0 += __shfl_xor_sync(0xffffffffu, s0, 2);
            s1 += __shfl_xor_sync(0xffffffffu, s1, 1);
            s1 += __shfl_xor_sync(0xffffffffu, s1, 2);
            float inv0 = __frcp_rn(s0), inv1 = __frcp_rn(s1);
            sc[0][0] = e00*inv0; sc[0][1] = e01*inv0;
            sc[1][2] = e12*inv1; sc[1][3] = e13*inv1;
            sc[0][2] = 0.f; sc[0][3] = 0.f;     // off-diagonal quadrants -> 0
            sc[1][0] = 0.f; sc[1][1] = 0.f;
        }
        // ---- pack P (C-layout == A-layout), K=16 single k-tile ----
        uint32_t ph[4], pl[4];
        split2(sc[0][0], sc[0][1], ph[0], pl[0]);
        split2(sc[0][2], sc[0][3], ph[1], pl[1]);
        split2(sc[1][0], sc[1][1], ph[2], pl[2]);
        split2(sc[1][2], sc[1][3], ph[3], pl[3]);
        // ---- PV: O(16 x 16-cols d-half) = P(16x16) * V(16 rows) ----
        #pragma unroll
        for (int ntl = 0; ntl < 2; ntl++) {
            int d0 = h*32 + dhalf*16 + ntl*8;
            uint32_t vh[2], vl[2];
            ldsm2t(vh, sbase + T_VH + ((r0 + (lane & 15))*LDA + d0)*2);
            ldsm2t(vl, sbase + T_VL + ((r0 + (lane & 15))*LDA + d0)*2);
            float o[4] = {0.f, 0.f, 0.f, 0.f};
            mma16816(o, ph, vh);
            mma16816(o, pl, vh);
            mma16816(o, ph, vl);
            int c0 = d0 + qc;
            split_store(smc + T_XOH, smc + T_XOL, row_a*LDA + c0,     o[0]);
            split_store(smc + T_XOH, smc + T_XOL, row_a*LDA + c0 + 1, o[1]);
            split_store(smc + T_XOH, smc + T_XOL, row_b*LDA + c0,     o[2]);
            split_store(smc + T_XOH, smc + T_XOL, row_b*LDA + c0 + 1, o[3]);
        }
    }

    // ---- HMMA projection (weights alias q region) ----
    const int nh = dhalf * 48;
    float acc[6][4];
    #pragma unroll
    for (int nt = 0; nt < 6; nt++)
        acc[nt][0] = acc[nt][1] = acc[nt][2] = acc[nt][3] = 0.f;

    for (int s = 0; s < 3; s++) {
        __syncthreads();
        for (int v = tid; v < 32*48; v += 256) {
            int kl = v / 48, j = v - (v/48)*48;
            ((uint32_t*)(smc + T_WH))[kl*52 + j] = ((const uint32_t*)g_ptwh)[(s*32 + kl)*48 + j];
            ((uint32_t*)(smc + T_WL))[kl*52 + j] = ((const uint32_t*)g_ptwl)[(s*32 + kl)*48 + j];
        }
        __syncthreads();

        uint32_t ah[2][4], al[2][4];
        int arow = r0 + (lane & 15);
        int acol = (lane >> 4)*8;
        #pragma unroll
        for (int kt = 0; kt < 2; kt++) {
            uint32_t off = (arow*LDA + s*32 + kt*16 + acol)*2;
            ldsm4(ah[kt], sbase + T_XOH + off);
            ldsm4(al[kt], sbase + T_XOL + off);
        }
        #pragma unroll
        for (int nt = 0; nt < 6; nt++) {
            uint32_t bh[2][2], bl[2][2];
            #pragma unroll
            for (int kt = 0; kt < 2; kt++) {
                uint32_t off = ((kt*16 + (lane & 15))*LDA + nh + nt*8)*2;
                ldsm2t(bh[kt], sbase + T_WH + off);
                ldsm2t(bl[kt], sbase + T_WL + off);
            }
            #pragma unroll
            for (int kt = 0; kt < 2; kt++) {
                mma16816(acc[nt], ah[kt], bh[kt]);
                mma16816(acc[nt], al[kt], bh[kt]);
                mma16816(acc[nt], ah[kt], bl[kt]);
            }
        }
    }

    #pragma unroll
    for (int nt = 0; nt < 6; nt++) {
        int col = nh + nt*8 + qc;
        float2 bs = {pb[col], pb[col+1]};
        #pragma unroll
        for (int half = 0; half < 2; half++) {
            int row = r0 + qr + half*8;
            int sl = row >> 3, t = row & 7;
            float* og = out + (((size_t)b*TT + t)*NN + (n0 + sl))*CDIM;
            float2 o = {acc[nt][half*2] + bs.x, acc[nt][half*2 + 1] + bs.y};
            og[col]     = o.x;
            og[col + 1] = o.y;
        }
    }
}

extern "C" void kernel_launch(void* const* d_in, const int* in_sizes, int n_in,
                              void* d_out, int out_size)
{
    const float* x      = (const float*)d_in[0];
    const float* mask   = (const float*)d_in[1];
    const float* qkv_w  = (const float*)d_in[2];
    const float* qkv_b  = (const float*)d_in[3];
    const float* psw    = (const float*)d_in[4];
    const float* psb    = (const float*)d_in[5];
    const float* ptw    = (const float*)d_in[6];
    const float* ptb    = (const float*)d_in[7];

    float* out_t  = (float*)d_out;
    float* out_sp = out_t + (size_t)BATCH*TT*NN*CDIM;

    cudaFuncSetAttribute(qkv_mma_kernel,  cudaFuncAttributeMaxDynamicSharedMemorySize, SMEM_QKV);
    cudaFuncSetAttribute(spatial_kernel,  cudaFuncAttributeMaxDynamicSharedMemorySize, SMEM_SP);
    cudaFuncSetAttribute(temporal_kernel, cudaFuncAttributeMaxDynamicSharedMemorySize, SMEM_T);

    wconv_kernel<<<180, 256>>>(qkv_w, psw, ptw);
    qkv_mma_kernel<<<NTOK/128, 256, SMEM_QKV>>>(x, qkv_b);
    spatial_kernel<<<BATCH*TT, 256, SMEM_SP>>>(mask, psb, out_sp);
    temporal_kernel<<<BATCH*7, 256, SMEM_T>>>(ptb, out_t);
}

// round 15
// speedup vs baseline: 4.1245x; 1.0088x over previous
#include <cuda_runtime.h>
#include <cuda_bf16.h>
#include <cstdint>

#define BATCH   1024
#define TT      8
#define NN      49
#define CDIM    96
#define HEADS   3
#define HD      32
#define NTOK    (BATCH*TT*NN)
#define QKV_LD  288
#define LDA     104
#define SCALE   0.17677669529663687f

__device__ __nv_bfloat16 g_qkvh[(size_t)NTOK * QKV_LD];
__device__ __nv_bfloat16 g_qkvl[(size_t)NTOK * QKV_LD];
__device__ __nv_bfloat16 g_wqkvh[96*288], g_wqkvl[96*288];
__device__ __nv_bfloat16 g_pswh[96*96],  g_pswl[96*96];
__device__ __nv_bfloat16 g_ptwh[96*96],  g_ptwl[96*96];

// ---- qkv smem (bytes) ----
#define QK_AHI   0
#define QK_ALO   26624
#define QK_BHI   53248
#define QK_BLO   73216
#define QK_BIAS  93184
#define SMEM_QKV 94336

// ---- spatial smem (bytes) ----
#define SP_QH    0                   // 49*104*2 = 10192
#define SP_QL    10192
#define SP_WFH   0                   // proj full weight hi (96*104*2 = 19968), aliases Q
#define SP_KH    20384               // 56 rows
#define SP_KL    32032
#define SP_WFL   20384               // proj full weight lo, aliases K
#define SP_VH    43680               // 64 rows
#define SP_VL    56992
#define SP_XOH   70304               // 49 rows
#define SP_XOL   80496
#define SP_MS    90688               // mask 49*52 f32
#define SMEM_SP  100880

// ---- temporal smem (bytes) ----
#define T_QH     0                   // 56*104*2 = 11648
#define T_QL     11648
#define T_WFH    0                   // aliases Q (19968 <= 23296)
#define T_KH     23296
#define T_KL     34944
#define T_WFL    23296               // aliases K
#define T_VH     46592
#define T_VL     58240
#define T_XOH    69888
#define T_XOL    81536
#define SMEM_T   93184

// ======================= helpers =======================
__device__ __forceinline__ uint32_t smem_u32(const void* p) {
    uint32_t a;
    asm("{ .reg .u64 t; cvta.to.shared.u64 t, %1; cvt.u32.u64 %0, t; }" : "=r"(a) : "l"(p));
    return a;
}
__device__ __forceinline__ void ldsm4(uint32_t* r, uint32_t addr) {
    asm volatile("ldmatrix.sync.aligned.m8n8.x4.shared.b16 {%0,%1,%2,%3}, [%4];"
                 : "=r"(r[0]), "=r"(r[1]), "=r"(r[2]), "=r"(r[3]) : "r"(addr));
}
__device__ __forceinline__ void ldsm2(uint32_t* r, uint32_t addr) {
    asm volatile("ldmatrix.sync.aligned.m8n8.x2.shared.b16 {%0,%1}, [%2];"
                 : "=r"(r[0]), "=r"(r[1]) : "r"(addr));
}
__device__ __forceinline__ void ldsm2t(uint32_t* r, uint32_t addr) {
    asm volatile("ldmatrix.sync.aligned.m8n8.x2.trans.shared.b16 {%0,%1}, [%2];"
                 : "=r"(r[0]), "=r"(r[1]) : "r"(addr));
}
__device__ __forceinline__ void ldsm4t(uint32_t* r, uint32_t addr) {
    asm volatile("ldmatrix.sync.aligned.m8n8.x4.trans.shared.b16 {%0,%1,%2,%3}, [%4];"
                 : "=r"(r[0]), "=r"(r[1]), "=r"(r[2]), "=r"(r[3]) : "r"(addr));
}
__device__ __forceinline__ void mma16816(float* d, const uint32_t* a, const uint32_t* b) {
    asm volatile("mma.sync.aligned.m16n8k16.row.col.f32.bf16.bf16.f32 "
                 "{%0,%1,%2,%3}, {%4,%5,%6,%7}, {%8,%9}, {%0,%1,%2,%3};"
                 : "+f"(d[0]), "+f"(d[1]), "+f"(d[2]), "+f"(d[3])
                 : "r"(a[0]), "r"(a[1]), "r"(a[2]), "r"(a[3]), "r"(b[0]), "r"(b[1]));
}
__device__ __forceinline__ uint32_t bfpk(float a, float b) {
    __nv_bfloat162 h = __floats2bfloat162_rn(a, b);
    return *(uint32_t*)&h;
}
__device__ __forceinline__ void split_store(char* hi, char* lo, int idx, float v) {
    __nv_bfloat16 h = __float2bfloat16_rn(v);
    ((__nv_bfloat16*)hi)[idx] = h;
    ((__nv_bfloat16*)lo)[idx] = __float2bfloat16_rn(v - __bfloat162float(h));
}
__device__ __forceinline__ void split2(float a, float b, uint32_t& hi, uint32_t& lo) {
    __nv_bfloat16 ha = __float2bfloat16_rn(a), hb = __float2bfloat16_rn(b);
    __nv_bfloat162 hp = __halves2bfloat162(ha, hb);
    hi = *(uint32_t*)&hp;
    lo = bfpk(a - __bfloat162float(ha), b - __bfloat162float(hb));
}
__device__ __forceinline__ void gsplit(__nv_bfloat16* hi, __nv_bfloat16* lo, size_t idx, float a, float b) {
    __nv_bfloat16 h0 = __float2bfloat16_rn(a), h1 = __float2bfloat16_rn(b);
    __nv_bfloat162 hp = __halves2bfloat162(h0, h1);
    *(uint32_t*)(hi + idx) = *(uint32_t*)&hp;
    *(uint32_t*)(lo + idx) = bfpk(a - __bfloat162float(h0), b - __bfloat162float(h1));
}

// ================= weight pre-conversion =================
__global__ void wconv_kernel(const float* __restrict__ qkv_w,
                             const float* __restrict__ psw,
                             const float* __restrict__ ptw)
{
    int i = blockIdx.x*256 + threadIdx.x;
    if (i < 96*288) {
        float v = qkv_w[i];
        if ((i % 288) < 96) v *= SCALE;
        __nv_bfloat16 h = __float2bfloat16_rn(v);
        g_wqkvh[i] = h;
        g_wqkvl[i] = __float2bfloat16_rn(v - __bfloat162float(h));
    } else if (i < 96*288 + 96*96) {
        int j = i - 96*288;
        float v = psw[j];
        __nv_bfloat16 h = __float2bfloat16_rn(v);
        g_pswh[j] = h;
        g_pswl[j] = __float2bfloat16_rn(v - __bfloat162float(h));
    } else if (i < 96*288 + 2*96*96) {
        int j = i - 96*288 - 96*96;
        float v = ptw[j];
        __nv_bfloat16 h = __float2bfloat16_rn(v);
        g_ptwh[j] = h;
        g_ptwl[j] = __float2bfloat16_rn(v - __bfloat162float(h));
    }
}

// ================= Kernel A: QKV GEMM =================
__global__ __launch_bounds__(256, 2)
void qkv_mma_kernel(const float* __restrict__ x, const float* __restrict__ qkv_b)
{
    extern __shared__ char smem[];
    const uint32_t sbase = smem_u32(smem);
    float* bias_sm = (float*)(smem + QK_BIAS);

    const int tid  = threadIdx.x;
    const int lane = tid & 31;
    const int warp = tid >> 5;
    const int row0 = blockIdx.x * 128;

    for (int v = tid; v < 128*24; v += 256) {
        int r = v / 24, c = (v - (v/24)*24) * 4;
        float4 f = *(const float4*)(x + (size_t)(row0 + r)*96 + c);
        __nv_bfloat16 h0 = __float2bfloat16_rn(f.x), h1 = __float2bfloat16_rn(f.y);
        __nv_bfloat16 h2 = __float2bfloat16_rn(f.z), h3 = __float2bfloat16_rn(f.w);
        __nv_bfloat162 p0 = __halves2bfloat162(h0, h1);
        __nv_bfloat162 p1 = __halves2bfloat162(h2, h3);
        uint32_t off = (r*LDA + c)*2;
        *(uint32_t*)(smem + QK_AHI + off)     = *(uint32_t*)&p0;
        *(uint32_t*)(smem + QK_AHI + off + 4) = *(uint32_t*)&p1;
        *(uint32_t*)(smem + QK_ALO + off)     = bfpk(f.x - __bfloat162float(h0), f.y - __bfloat162float(h1));
        *(uint32_t*)(smem + QK_ALO + off + 4) = bfpk(f.z - __bfloat162float(h2), f.w - __bfloat162float(h3));
    }
    for (int v = tid; v < 288; v += 256)
        bias_sm[v] = qkv_b[v] * ((v < 96) ? SCALE : 1.0f);
    __syncthreads();

    uint32_t ah[6][4], al[6][4];
    {
        int arow = warp*16 + (lane & 15);
        int acol = (lane >> 4) * 8;
        #pragma unroll
        for (int kt = 0; kt < 6; kt++) {
            uint32_t boff = (arow*LDA + kt*16 + acol)*2;
            ldsm4(ah[kt], sbase + QK_AHI + boff);
            ldsm4(al[kt], sbase + QK_ALO + boff);
        }
    }

    for (int chunk = 0; chunk < 3; chunk++) {
        __syncthreads();
        for (int v = tid; v < 96*48; v += 256) {
            int k = v / 48, j = v - (v/48)*48;
            ((uint32_t*)(smem + QK_BHI))[k*52 + j] = ((const uint32_t*)g_wqkvh)[k*144 + chunk*48 + j];
            ((uint32_t*)(smem + QK_BLO))[k*52 + j] = ((const uint32_t*)g_wqkvl)[k*144 + chunk*48 + j];
        }
        __syncthreads();

        const int brow = lane & 15;
        #pragma unroll
        for (int nt = 0; nt < 12; nt++) {
            const int n0 = nt*8;
            uint32_t bh[6][2], bl[6][2];
            #pragma unroll
            for (int kt = 0; kt < 6; kt++) {
                uint32_t boff = ((kt*16 + brow)*LDA + n0)*2;
                ldsm2t(bh[kt], sbase + QK_BHI + boff);
                ldsm2t(bl[kt], sbase + QK_BLO + boff);
            }
            // 3-way accumulator split (chain 18 -> 6)
            float a1[4] = {0,0,0,0}, a2[4] = {0,0,0,0}, a3[4] = {0,0,0,0};
            #pragma unroll
            for (int kt = 0; kt < 6; kt++) {
                mma16816(a1, ah[kt], bh[kt]);
                mma16816(a2, al[kt], bh[kt]);
                mma16816(a3, ah[kt], bl[kt]);
            }
            int r  = lane >> 2;
            int c2 = (lane & 3)*2;
            float2 bs = *(float2*)(bias_sm + chunk*96 + n0 + c2);
            size_t gb = (size_t)(row0 + warp*16 + r)*QKV_LD + chunk*96 + n0 + c2;
            gsplit(g_qkvh, g_qkvl, gb,            a1[0]+a2[0]+a3[0] + bs.x, a1[1]+a2[1]+a3[1] + bs.y);
            gsplit(g_qkvh, g_qkvl, gb + 8*QKV_LD, a1[2]+a2[2]+a3[2] + bs.x, a1[3]+a2[3]+a3[3] + bs.y);
        }
    }
}

// ================= Kernel B: in-register FA-style spatial =================
__global__ __launch_bounds__(256, 2)
void spatial_kernel(const float* __restrict__ mask,
                    const float* __restrict__ pb, float* __restrict__ out)
{
    extern __shared__ char smc[];
    const uint32_t sbase = smem_u32(smc);
    float* ms = (float*)(smc + SP_MS);

    const int bt   = blockIdx.x;
    const int tid  = threadIdx.x;
    const int lane = tid & 31;
    const int warp = tid >> 5;

    {
        const size_t tb = (size_t)bt * NN * QKV_LD;
        for (int v = tid; v < NN*12; v += 256) {
            int r = v / 12, c8 = (v - (v/12)*12)*8;
            size_t src = tb + (size_t)r*QKV_LD + c8;
            uint32_t doff = (r*LDA + c8)*2;
            *(uint4*)(smc + SP_QH + doff) = *(const uint4*)(g_qkvh + src);
            *(uint4*)(smc + SP_QL + doff) = *(const uint4*)(g_qkvl + src);
            *(uint4*)(smc + SP_KH + doff) = *(const uint4*)(g_qkvh + src + 96);
            *(uint4*)(smc + SP_KL + doff) = *(const uint4*)(g_qkvl + src + 96);
            *(uint4*)(smc + SP_VH + doff) = *(const uint4*)(g_qkvh + src + 192);
            *(uint4*)(smc + SP_VL + doff) = *(const uint4*)(g_qkvl + src + 192);
        }
    }
    for (int i = tid; i < 15*52; i += 256) {
        int row = 49 + i/52, cw = i - (i/52)*52;
        ((uint32_t*)(smc + SP_VH))[row*52 + cw] = 0;
        ((uint32_t*)(smc + SP_VL))[row*52 + cw] = 0;
    }
    {
        const float* mrow = mask + (size_t)(bt & 63) * (49*49);
        for (int i = tid; i < 49*49; i += 256) {
            int r = i / 49, c = i - r*49;
            ms[r*52 + c] = mrow[i];
        }
    }
    __syncthreads();

    const int mt    = warp >> 1;
    const int dhalf = warp & 1;
    const int r0    = (mt == 3) ? 33 : mt*16;
    const int qr    = lane >> 2;
    const int qc    = (lane & 3)*2;
    const int row_a = r0 + qr, row_b = r0 + qr + 8;

    for (int h = 0; h < HEADS; h++) {
        uint32_t aqh[2][4], aql[2][4];
        {
            int ar = r0 + (lane & 15);
            #pragma unroll
            for (int kt = 0; kt < 2; kt++) {
                uint32_t off = (ar*LDA + h*32 + kt*16 + (lane >> 4)*8)*2;
                ldsm4(aqh[kt], sbase + SP_QH + off);
                ldsm4(aql[kt], sbase + SP_QL + off);
            }
        }
        float sc[7][4];
        {
            int l = lane & 15;
            #pragma unroll
            for (int nt = 0; nt < 7; nt++) {
                uint32_t boff = ((nt*8 + (l & 7))*LDA + h*32 + (l & 8))*2;
                uint32_t bh[2][2], bl[2][2];
                #pragma unroll
                for (int kt = 0; kt < 2; kt++) {
                    ldsm2(bh[kt], sbase + SP_KH + boff + kt*32);
                    ldsm2(bl[kt], sbase + SP_KL + boff + kt*32);
                }
                // 3-way split (chain 6 -> 2)
                float a1[4] = {0,0,0,0}, a2[4] = {0,0,0,0}, a3[4] = {0,0,0,0};
                #pragma unroll
                for (int kt = 0; kt < 2; kt++) {
                    mma16816(a1, aqh[kt], bh[kt]);
                    mma16816(a2, aql[kt], bh[kt]);
                    mma16816(a3, aqh[kt], bl[kt]);
                }
                sc[nt][0] = a1[0]+a2[0]+a3[0]; sc[nt][1] = a1[1]+a2[1]+a3[1];
                sc[nt][2] = a1[2]+a2[2]+a3[2]; sc[nt][3] = a1[3]+a2[3]+a3[3];
            }
        }
        {
            float mx0 = -3.0e38f, mx1 = -3.0e38f;
            #pragma unroll
            for (int nt = 0; nt < 7; nt++) {
                #pragma unroll
                for (int i = 0; i < 2; i++) {
                    int col = nt*8 + qc + i;
                    if (col < 49) {
                        sc[nt][i]   += ms[row_a*52 + col];
                        sc[nt][2+i] += ms[row_b*52 + col];
                    } else {
                        sc[nt][i] = -3.0e38f; sc[nt][2+i] = -3.0e38f;
                    }
                    mx0 = fmaxf(mx0, sc[nt][i]);
                    mx1 = fmaxf(mx1, sc[nt][2+i]);
                }
            }
            mx0 = fmaxf(mx0, __shfl_xor_sync(0xffffffffu, mx0, 1));
            mx0 = fmaxf(mx0, __shfl_xor_sync(0xffffffffu, mx0, 2));
            mx1 = fmaxf(mx1, __shfl_xor_sync(0xffffffffu, mx1, 1));
            mx1 = fmaxf(mx1, __shfl_xor_sync(0xffffffffu, mx1, 2));
            float s0 = 0.f, s1 = 0.f;
            #pragma unroll
            for (int nt = 0; nt < 7; nt++) {
                #pragma unroll
                for (int i = 0; i < 2; i++) {
                    sc[nt][i]   = __expf(sc[nt][i]   - mx0); s0 += sc[nt][i];
                    sc[nt][2+i] = __expf(sc[nt][2+i] - mx1); s1 += sc[nt][2+i];
                }
            }
            s0 += __shfl_xor_sync(0xffffffffu, s0, 1);
            s0 += __shfl_xor_sync(0xffffffffu, s0, 2);
            s1 += __shfl_xor_sync(0xffffffffu, s1, 1);
            s1 += __shfl_xor_sync(0xffffffffu, s1, 2);
            float inv0 = __frcp_rn(s0), inv1 = __frcp_rn(s1);
            #pragma unroll
            for (int nt = 0; nt < 7; nt++) {
                sc[nt][0] *= inv0; sc[nt][1] *= inv0;
                sc[nt][2] *= inv1; sc[nt][3] *= inv1;
            }
        }
        uint32_t ph[4][4], pl[4][4];
        #pragma unroll
        for (int kt = 0; kt < 4; kt++) {
            int nta = 2*kt, ntb = 2*kt + 1;
            split2(sc[nta][0], sc[nta][1], ph[kt][0], pl[kt][0]);
            split2(sc[nta][2], sc[nta][3], ph[kt][1], pl[kt][1]);
            if (ntb < 7) {
                split2(sc[ntb][0], sc[ntb][1], ph[kt][2], pl[kt][2]);
                split2(sc[ntb][2], sc[ntb][3], ph[kt][3], pl[kt][3]);
            } else {
                ph[kt][2] = 0; ph[kt][3] = 0; pl[kt][2] = 0; pl[kt][3] = 0;
            }
        }
        #pragma unroll
        for (int ntl = 0; ntl < 2; ntl++) {
            int d0 = h*32 + dhalf*16 + ntl*8;
            uint32_t vh01[4], vl01[4], vh23[4], vl23[4];
            ldsm4t(vh01, sbase + SP_VH + ((lane     )*LDA + d0)*2);
            ldsm4t(vl01, sbase + SP_VL + ((lane     )*LDA + d0)*2);
            ldsm4t(vh23, sbase + SP_VH + ((32 + lane)*LDA + d0)*2);
            ldsm4t(vl23, sbase + SP_VL + ((32 + lane)*LDA + d0)*2);
            // 3-way split (chain 12 -> 4)
            float o1[4] = {0,0,0,0}, o2[4] = {0,0,0,0}, o3[4] = {0,0,0,0};
            #pragma unroll
            for (int kt = 0; kt < 4; kt++) {
                const uint32_t* bh_ = (kt < 2) ? &vh01[(kt & 1)*2] : &vh23[(kt & 1)*2];
                const uint32_t* bl_ = (kt < 2) ? &vl01[(kt & 1)*2] : &vl23[(kt & 1)*2];
                mma16816(o1, ph[kt], bh_);
                mma16816(o2, pl[kt], bh_);
                mma16816(o3, ph[kt], bl_);
            }
            int c0 = d0 + qc;
            split_store(smc + SP_XOH, smc + SP_XOL, row_a*LDA + c0,     o1[0]+o2[0]+o3[0]);
            split_store(smc + SP_XOH, smc + SP_XOL, row_a*LDA + c0 + 1, o1[1]+o2[1]+o3[1]);
            split_store(smc + SP_XOH, smc + SP_XOL, row_b*LDA + c0,     o1[2]+o2[2]+o3[2]);
            split_store(smc + SP_XOH, smc + SP_XOL, row_b*LDA + c0 + 1, o1[3]+o2[3]+o3[3]);
        }
    }

    // ---- projection: stage FULL weight once (aliases Q and K regions) ----
    __syncthreads();
    for (int v = tid; v < 96*48; v += 256) {
        int kl = v / 48, j = v - (v/48)*48;
        ((uint32_t*)(smc + SP_WFH))[kl*52 + j] = ((const uint32_t*)g_pswh)[kl*48 + j];
        ((uint32_t*)(smc + SP_WFL))[kl*52 + j] = ((const uint32_t*)g_pswl)[kl*48 + j];
    }
    __syncthreads();

    const int nh = dhalf * 48;
    float acc[6][4];
    #pragma unroll
    for (int nt = 0; nt < 6; nt++)
        acc[nt][0] = acc[nt][1] = acc[nt][2] = acc[nt][3] = 0.f;

    #pragma unroll
    for (int s = 0; s < 3; s++) {
        uint32_t ah[2][4], al[2][4];
        int arow = r0 + (lane & 15);
        int acol = (lane >> 4)*8;
        #pragma unroll
        for (int kt = 0; kt < 2; kt++) {
            uint32_t off = (arow*LDA + s*32 + kt*16 + acol)*2;
            ldsm4(ah[kt], sbase + SP_XOH + off);
            ldsm4(al[kt], sbase + SP_XOL + off);
        }
        #pragma unroll
        for (int nt = 0; nt < 6; nt++) {
            uint32_t bh[2][2], bl[2][2];
            #pragma unroll
            for (int kt = 0; kt < 2; kt++) {
                uint32_t off = ((s*32 + kt*16 + (lane & 15))*LDA + nh + nt*8)*2;
                ldsm2t(bh[kt], sbase + SP_WFH + off);
                ldsm2t(bl[kt], sbase + SP_WFL + off);
            }
            #pragma unroll
            for (int kt = 0; kt < 2; kt++) {
                mma16816(acc[nt], ah[kt], bh[kt]);
                mma16816(acc[nt], al[kt], bh[kt]);
                mma16816(acc[nt], ah[kt], bl[kt]);
            }
        }
    }

    float* og = out + (size_t)bt * (NN*CDIM);
    #pragma unroll
    for (int nt = 0; nt < 6; nt++) {
        int col = nh + nt*8 + qc;
        float2 bs = {pb[col], pb[col+1]};
        int ra = r0 + qr, rb = r0 + qr + 8;
        if (ra < NN) { og[ra*CDIM + col] = acc[nt][0] + bs.x; og[ra*CDIM + col + 1] = acc[nt][1] + bs.y; }
        if (rb < NN) { og[rb*CDIM + col] = acc[nt][2] + bs.x; og[rb*CDIM + col + 1] = acc[nt][3] + bs.y; }
    }
}

// ================= Kernel C: in-register HMMA temporal =================
__global__ __launch_bounds__(256, 2)
void temporal_kernel(const float* __restrict__ pb, float* __restrict__ out)
{
    extern __shared__ char smc[];
    const uint32_t sbase = smem_u32(smc);

    const int g    = blockIdx.x;
    const int b    = g / 7;
    const int n0   = (g - b*7) * 7;
    const int tid  = threadIdx.x;
    const int lane = tid & 31;
    const int warp = tid >> 5;

    for (int v = tid; v < 56*12; v += 256) {
        int r = v / 12, c8 = (v - (v/12)*12)*8;
        int sl = r >> 3, t = r & 7;
        size_t src = ((size_t)(b*TT + t)*NN + n0 + sl)*QKV_LD + c8;
        uint32_t doff = (r*LDA + c8)*2;
        *(uint4*)(smc + T_QH + doff) = *(const uint4*)(g_qkvh + src);
        *(uint4*)(smc + T_QL + doff) = *(const uint4*)(g_qkvl + src);
        *(uint4*)(smc + T_KH + doff) = *(const uint4*)(g_qkvh + src + 96);
        *(uint4*)(smc + T_KL + doff) = *(const uint4*)(g_qkvl + src + 96);
        *(uint4*)(smc + T_VH + doff) = *(const uint4*)(g_qkvh + src + 192);
        *(uint4*)(smc + T_VL + doff) = *(const uint4*)(g_qkvl + src + 192);
    }
    __syncthreads();

    const int mt    = warp >> 1;
    const int dhalf = warp & 1;
    const int r0    = (mt == 3) ? 40 : mt*16;
    const int qr    = lane >> 2;
    const int qc    = (lane & 3)*2;
    const int row_a = r0 + qr, row_b = r0 + qr + 8;

    for (int h = 0; h < HEADS; h++) {
        uint32_t aqh[2][4], aql[2][4];
        {
            int ar = r0 + (lane & 15);
            #pragma unroll
            for (int kt = 0; kt < 2; kt++) {
                uint32_t off = (ar*LDA + h*32 + kt*16 + (lane >> 4)*8)*2;
                ldsm4(aqh[kt], sbase + T_QH + off);
                ldsm4(aql[kt], sbase + T_QL + off);
            }
        }
        float sc[2][4];
        {
            int l = lane & 15;
            #pragma unroll
            for (int nt = 0; nt < 2; nt++) {
                uint32_t boff = ((r0 + nt*8 + (l & 7))*LDA + h*32 + (l & 8))*2;
                uint32_t bh[2][2], bl[2][2];
                #pragma unroll
                for (int kt = 0; kt < 2; kt++) {
                    ldsm2(bh[kt], sbase + T_KH + boff + kt*32);
                    ldsm2(bl[kt], sbase + T_KL + boff + kt*32);
                }
                float a1[4] = {0,0,0,0}, a2[4] = {0,0,0,0}, a3[4] = {0,0,0,0};
                #pragma unroll
                for (int kt = 0; kt < 2; kt++) {
                    mma16816(a1, aqh[kt], bh[kt]);
                    mma16816(a2, aql[kt], bh[kt]);
                    mma16816(a3, aqh[kt], bl[kt]);
                }
                sc[nt][0] = a1[0]+a2[0]+a3[0]; sc[nt][1] = a1[1]+a2[1]+a3[1];
                sc[nt][2] = a1[2]+a2[2]+a3[2]; sc[nt][3] = a1[3]+a2[3]+a3[3];
            }
        }
        {
            float mx0 = fmaxf(sc[0][0], sc[0][1]);
            float mx1 = fmaxf(sc[1][2], sc[1][3]);
            mx0 = fmaxf(mx0, __shfl_xor_sync(0xffffffffu, mx0, 1));
            mx0 = fmaxf(mx0, __shfl_xor_sync(0xffffffffu, mx0, 2));
            mx1 = fmaxf(mx1, __shfl_xor_sync(0xffffffffu, mx1, 1));
            mx1 = fmaxf(mx1, __shfl_xor_sync(0xffffffffu, mx1, 2));
            float e00 = __expf(sc[0][0] - mx0), e01 = __expf(sc[0][1] - mx0);
            float e12 = __expf(sc[1][2] - mx1), e13 = __expf(sc[1][3] - mx1);
            float s0 = e00 + e01, s1 = e12 + e13;
            s0 += __shfl_xor_sync(0xffffffffu, s0, 1);
            s0 += __shfl_xor_sync(0xffffffffu, s0, 2);
            s1 += __shfl_xor_sync(0xffffffffu, s1, 1);
            s1 += __shfl_xor_sync(0xffffffffu, s1, 2);
            float inv0 = __frcp_rn(s0), inv1 = __frcp_rn(s1);
            sc[0][0] = e00*inv0; sc[0][1] = e01*inv0;
            sc[1][2] = e12*inv1; sc[1][3] = e13*inv1;
            sc[0][2] = 0.f; sc[0][3] = 0.f;
            sc[1][0] = 0.f; sc[1][1] = 0.f;
        }
        uint32_t ph[4], pl[4];
        split2(sc[0][0], sc[0][1], ph[0], pl[0]);
        split2(sc[0][2], sc[0][3], ph[1], pl[1]);
        split2(sc[1][0], sc[1][1], ph[2], pl[2]);
        split2(sc[1][2], sc[1][3], ph[3], pl[3]);
        #pragma unroll
        for (int ntl = 0; ntl < 2; ntl++) {
            int d0 = h*32 + dhalf*16 + ntl*8;
            uint32_t vh[2], vl[2];
            ldsm2t(vh, sbase + T_VH + ((r0 + (lane & 15))*LDA + d0)*2);
            ldsm2t(vl, sbase + T_VL + ((r0 + (lane & 15))*LDA + d0)*2);
            float o1[4] = {0,0,0,0}, o2[4] = {0,0,0,0}, o3[4] = {0,0,0,0};
            mma16816(o1, ph, vh);
            mma16816(o2, pl, vh);
            mma16816(o3, ph, vl);
            int c0 = d0 + qc;
            split_store(smc + T_XOH, smc + T_XOL, row_a*LDA + c0,     o1[0]+o2[0]+o3[0]);
            split_store(smc + T_XOH, smc + T_XOL, row_a*LDA + c0 + 1, o1[1]+o2[1]+o3[1]);
            split_store(smc + T_XOH, smc + T_XOL, row_b*LDA + c0,     o1[2]+o2[2]+o3[2]);
            split_store(smc + T_XOH, smc + T_XOL, row_b*LDA + c0 + 1, o1[3]+o2[3]+o3[3]);
        }
    }

    // ---- projection: stage FULL weight once (aliases Q and K regions) ----
    __syncthreads();
    for (int v = tid; v < 96*48; v += 256) {
        int kl = v / 48, j = v - (v/48)*48;
        ((uint32_t*)(smc + T_WFH))[kl*52 + j] = ((const uint32_t*)g_ptwh)[kl*48 + j];
        ((uint32_t*)(smc + T_WFL))[kl*52 + j] = ((const uint32_t*)g_ptwl)[kl*48 + j];
    }
    __syncthreads();

    const int nh = dhalf * 48;
    float acc[6][4];
    #pragma unroll
    for (int nt = 0; nt < 6; nt++)
        acc[nt][0] = acc[nt][1] = acc[nt][2] = acc[nt][3] = 0.f;

    #pragma unroll
    for (int s = 0; s < 3; s++) {
        uint32_t ah[2][4], al[2][4];
        int arow = r0 + (lane & 15);
        int acol = (lane >> 4)*8;
        #pragma unroll
        for (int kt = 0; kt < 2; kt++) {
            uint32_t off = (arow*LDA + s*32 + kt*16 + acol)*2;
            ldsm4(ah[kt], sbase + T_XOH + off);
            ldsm4(al[kt], sbase + T_XOL + off);
        }
        #pragma unroll
        for (int nt = 0; nt < 6; nt++) {
            uint32_t bh[2][2], bl[2][2];
            #pragma unroll
            for (int kt = 0; kt < 2; kt++) {
                uint32_t off = ((s*32 + kt*16 + (lane & 15))*LDA + nh + nt*8)*2;
                ldsm2t(bh[kt], sbase + T_WFH + off);
                ldsm2t(bl[kt], sbase + T_WFL + off);
            }
            #pragma unroll
            for (int kt = 0; kt < 2; kt++) {
                mma16816(acc[nt], ah[kt], bh[kt]);
                mma16816(acc[nt], al[kt], bh[kt]);
                mma16816(acc[nt], ah[kt], bl[kt]);
            }
        }
    }

    #pragma unroll
    for (int nt = 0; nt < 6; nt++) {
        int col = nh + nt*8 + qc;
        float2 bs = {pb[col], pb[col+1]};
        #pragma unroll
        for (int half = 0; half < 2; half++) {
            int row = r0 + qr + half*8;
            int sl = row >> 3, t = row & 7;
            float* og = out + (((size_t)b*TT + t)*NN + (n0 + sl))*CDIM;
            og[col]     = acc[nt][half*2]     + bs.x;
            og[col + 1] = acc[nt][half*2 + 1] + bs.y;
        }
    }
}

extern "C" void kernel_launch(void* const* d_in, const int* in_sizes, int n_in,
                              void* d_out, int out_size)
{
    const float* x      = (const float*)d_in[0];
    const float* mask   = (const float*)d_in[1];
    const float* qkv_w  = (const float*)d_in[2];
    const float* qkv_b  = (const float*)d_in[3];
    const float* psw    = (const float*)d_in[4];
    const float* psb    = (const float*)d_in[5];
    const float* ptw    = (const float*)d_in[6];
    const float* ptb    = (const float*)d_in[7];

    float* out_t  = (float*)d_out;
    float* out_sp = out_t + (size_t)BATCH*TT*NN*CDIM;

    cudaFuncSetAttribute(qkv_mma_kernel,  cudaFuncAttributeMaxDynamicSharedMemorySize, SMEM_QKV);
    cudaFuncSetAttribute(spatial_kernel,  cudaFuncAttributeMaxDynamicSharedMemorySize, SMEM_SP);
    cudaFuncSetAttribute(temporal_kernel, cudaFuncAttributeMaxDynamicSharedMemorySize, SMEM_T);

    wconv_kernel<<<180, 256>>>(qkv_w, psw, ptw);
    qkv_mma_kernel<<<NTOK/128, 256, SMEM_QKV>>>(x, qkv_b);
    spatial_kernel<<<BATCH*TT, 256, SMEM_SP>>>(mask, psb, out_sp);
    temporal_kernel<<<BATCH*7, 256, SMEM_T>>>(ptb, out_t);
}

// round 16
// speedup vs baseline: 4.3143x; 1.0460x over previous
#include <cuda_runtime.h>
#include <cuda_bf16.h>
#include <cstdint>

#define BATCH   1024
#define TT      8
#define NN      49
#define CDIM    96
#define HEADS   3
#define HD      32
#define NTOK    (BATCH*TT*NN)
#define QKV_LD  288
#define LDA     104
#define SCALE   0.17677669529663687f

__device__ __nv_bfloat16 g_qkvh[(size_t)NTOK * QKV_LD];
__device__ __nv_bfloat16 g_qkvl[(size_t)NTOK * QKV_LD];
__device__ __nv_bfloat16 g_wqkvh[96*288], g_wqkvl[96*288];
__device__ __nv_bfloat16 g_pswh[96*96],  g_pswl[96*96];
__device__ __nv_bfloat16 g_ptwh[96*96],  g_ptwl[96*96];

// ---- qkv smem (bytes) ----
#define QK_AHI   0
#define QK_ALO   26624
#define QK_BHI   53248
#define QK_BLO   73216
#define QK_BIAS  93184
#define SMEM_QKV 94336

// ---- spatial smem (bytes): no Q staging, bf16 mask ----
#define SP_KH    0                   // 56 rows: 11648
#define SP_KL    11648
#define SP_VH    23296               // 64 rows: 13312
#define SP_VL    36608
#define SP_XOH   49920               // 49 rows: 10192
#define SP_XOL   60112
#define SP_MS    70304               // mask bf16 49*52*2 = 5096
#define SMEM_SP  75400
#define SP_WFH   0                   // proj weight hi (19968) aliases K
#define SP_WFL   23296               // proj weight lo aliases V

// ---- temporal smem (bytes): no Q staging ----
#define T_KH     0                   // 56 rows: 11648
#define T_KL     11648
#define T_VH     23296
#define T_VL     34944
#define T_XOH    46592
#define T_XOL    58240
#define SMEM_T   69888
#define T_WFH    0                   // aliases K
#define T_WFL    23296               // aliases V

// ======================= helpers =======================
__device__ __forceinline__ uint32_t smem_u32(const void* p) {
    uint32_t a;
    asm("{ .reg .u64 t; cvta.to.shared.u64 t, %1; cvt.u32.u64 %0, t; }" : "=r"(a) : "l"(p));
    return a;
}
__device__ __forceinline__ void ldsm4(uint32_t* r, uint32_t addr) {
    asm volatile("ldmatrix.sync.aligned.m8n8.x4.shared.b16 {%0,%1,%2,%3}, [%4];"
                 : "=r"(r[0]), "=r"(r[1]), "=r"(r[2]), "=r"(r[3]) : "r"(addr));
}
__device__ __forceinline__ void ldsm2(uint32_t* r, uint32_t addr) {
    asm volatile("ldmatrix.sync.aligned.m8n8.x2.shared.b16 {%0,%1}, [%2];"
                 : "=r"(r[0]), "=r"(r[1]) : "r"(addr));
}
__device__ __forceinline__ void ldsm2t(uint32_t* r, uint32_t addr) {
    asm volatile("ldmatrix.sync.aligned.m8n8.x2.trans.shared.b16 {%0,%1}, [%2];"
                 : "=r"(r[0]), "=r"(r[1]) : "r"(addr));
}
__device__ __forceinline__ void ldsm4t(uint32_t* r, uint32_t addr) {
    asm volatile("ldmatrix.sync.aligned.m8n8.x4.trans.shared.b16 {%0,%1,%2,%3}, [%4];"
                 : "=r"(r[0]), "=r"(r[1]), "=r"(r[2]), "=r"(r[3]) : "r"(addr));
}
__device__ __forceinline__ void mma16816(float* d, const uint32_t* a, const uint32_t* b) {
    asm volatile("mma.sync.aligned.m16n8k16.row.col.f32.bf16.bf16.f32 "
                 "{%0,%1,%2,%3}, {%4,%5,%6,%7}, {%8,%9}, {%0,%1,%2,%3};"
                 : "+f"(d[0]), "+f"(d[1]), "+f"(d[2]), "+f"(d[3])
                 : "r"(a[0]), "r"(a[1]), "r"(a[2]), "r"(a[3]), "r"(b[0]), "r"(b[1]));
}
__device__ __forceinline__ uint32_t bfpk(float a, float b) {
    __nv_bfloat162 h = __floats2bfloat162_rn(a, b);
    return *(uint32_t*)&h;
}
__device__ __forceinline__ void split_store(char* hi, char* lo, int idx, float v) {
    __nv_bfloat16 h = __float2bfloat16_rn(v);
    ((__nv_bfloat16*)hi)[idx] = h;
    ((__nv_bfloat16*)lo)[idx] = __float2bfloat16_rn(v - __bfloat162float(h));
}
__device__ __forceinline__ void split2(float a, float b, uint32_t& hi, uint32_t& lo) {
    __nv_bfloat16 ha = __float2bfloat16_rn(a), hb = __float2bfloat16_rn(b);
    __nv_bfloat162 hp = __halves2bfloat162(ha, hb);
    hi = *(uint32_t*)&hp;
    lo = bfpk(a - __bfloat162float(ha), b - __bfloat162float(hb));
}
__device__ __forceinline__ void gsplit(__nv_bfloat16* hi, __nv_bfloat16* lo, size_t idx, float a, float b) {
    __nv_bfloat16 h0 = __float2bfloat16_rn(a), h1 = __float2bfloat16_rn(b);
    __nv_bfloat162 hp = __halves2bfloat162(h0, h1);
    *(uint32_t*)(hi + idx) = *(uint32_t*)&hp;
    *(uint32_t*)(lo + idx) = bfpk(a - __bfloat162float(h0), b - __bfloat162float(h1));
}
// load A fragment (m16n8k16) directly from global hi/lo arrays
__device__ __forceinline__ void gfragA(uint32_t* r, const __nv_bfloat16* g, size_t base_a, size_t base_b, int cb) {
    r[0] = *(const uint32_t*)(g + base_a + cb);
    r[1] = *(const uint32_t*)(g + base_b + cb);
    r[2] = *(const uint32_t*)(g + base_a + cb + 8);
    r[3] = *(const uint32_t*)(g + base_b + cb + 8);
}

// ================= weight pre-conversion =================
__global__ void wconv_kernel(const float* __restrict__ qkv_w,
                             const float* __restrict__ psw,
                             const float* __restrict__ ptw)
{
    int i = blockIdx.x*256 + threadIdx.x;
    if (i < 96*288) {
        float v = qkv_w[i];
        if ((i % 288) < 96) v *= SCALE;
        __nv_bfloat16 h = __float2bfloat16_rn(v);
        g_wqkvh[i] = h;
        g_wqkvl[i] = __float2bfloat16_rn(v - __bfloat162float(h));
    } else if (i < 96*288 + 96*96) {
        int j = i - 96*288;
        float v = psw[j];
        __nv_bfloat16 h = __float2bfloat16_rn(v);
        g_pswh[j] = h;
        g_pswl[j] = __float2bfloat16_rn(v - __bfloat162float(h));
    } else if (i < 96*288 + 2*96*96) {
        int j = i - 96*288 - 96*96;
        float v = ptw[j];
        __nv_bfloat16 h = __float2bfloat16_rn(v);
        g_ptwh[j] = h;
        g_ptwl[j] = __float2bfloat16_rn(v - __bfloat162float(h));
    }
}

// ================= Kernel A: QKV GEMM (unchanged) =================
__global__ __launch_bounds__(256, 2)
void qkv_mma_kernel(const float* __restrict__ x, const float* __restrict__ qkv_b)
{
    extern __shared__ char smem[];
    const uint32_t sbase = smem_u32(smem);
    float* bias_sm = (float*)(smem + QK_BIAS);

    const int tid  = threadIdx.x;
    const int lane = tid & 31;
    const int warp = tid >> 5;
    const int row0 = blockIdx.x * 128;

    for (int v = tid; v < 128*24; v += 256) {
        int r = v / 24, c = (v - (v/24)*24) * 4;
        float4 f = *(const float4*)(x + (size_t)(row0 + r)*96 + c);
        __nv_bfloat16 h0 = __float2bfloat16_rn(f.x), h1 = __float2bfloat16_rn(f.y);
        __nv_bfloat16 h2 = __float2bfloat16_rn(f.z), h3 = __float2bfloat16_rn(f.w);
        __nv_bfloat162 p0 = __halves2bfloat162(h0, h1);
        __nv_bfloat162 p1 = __halves2bfloat162(h2, h3);
        uint32_t off = (r*LDA + c)*2;
        *(uint32_t*)(smem + QK_AHI + off)     = *(uint32_t*)&p0;
        *(uint32_t*)(smem + QK_AHI + off + 4) = *(uint32_t*)&p1;
        *(uint32_t*)(smem + QK_ALO + off)     = bfpk(f.x - __bfloat162float(h0), f.y - __bfloat162float(h1));
        *(uint32_t*)(smem + QK_ALO + off + 4) = bfpk(f.z - __bfloat162float(h2), f.w - __bfloat162float(h3));
    }
    for (int v = tid; v < 288; v += 256)
        bias_sm[v] = qkv_b[v] * ((v < 96) ? SCALE : 1.0f);
    __syncthreads();

    uint32_t ah[6][4], al[6][4];
    {
        int arow = warp*16 + (lane & 15);
        int acol = (lane >> 4) * 8;
        #pragma unroll
        for (int kt = 0; kt < 6; kt++) {
            uint32_t boff = (arow*LDA + kt*16 + acol)*2;
            ldsm4(ah[kt], sbase + QK_AHI + boff);
            ldsm4(al[kt], sbase + QK_ALO + boff);
        }
    }

    for (int chunk = 0; chunk < 3; chunk++) {
        __syncthreads();
        for (int v = tid; v < 96*48; v += 256) {
            int k = v / 48, j = v - (v/48)*48;
            ((uint32_t*)(smem + QK_BHI))[k*52 + j] = ((const uint32_t*)g_wqkvh)[k*144 + chunk*48 + j];
            ((uint32_t*)(smem + QK_BLO))[k*52 + j] = ((const uint32_t*)g_wqkvl)[k*144 + chunk*48 + j];
        }
        __syncthreads();

        const int brow = lane & 15;
        #pragma unroll
        for (int nt = 0; nt < 12; nt++) {
            const int n0 = nt*8;
            uint32_t bh[6][2], bl[6][2];
            #pragma unroll
            for (int kt = 0; kt < 6; kt++) {
                uint32_t boff = ((kt*16 + brow)*LDA + n0)*2;
                ldsm2t(bh[kt], sbase + QK_BHI + boff);
                ldsm2t(bl[kt], sbase + QK_BLO + boff);
            }
            float a1[4] = {0,0,0,0}, a2[4] = {0,0,0,0}, a3[4] = {0,0,0,0};
            #pragma unroll
            for (int kt = 0; kt < 6; kt++) {
                mma16816(a1, ah[kt], bh[kt]);
                mma16816(a2, al[kt], bh[kt]);
                mma16816(a3, ah[kt], bl[kt]);
            }
            int r  = lane >> 2;
            int c2 = (lane & 3)*2;
            float2 bs = *(float2*)(bias_sm + chunk*96 + n0 + c2);
            size_t gb = (size_t)(row0 + warp*16 + r)*QKV_LD + chunk*96 + n0 + c2;
            gsplit(g_qkvh, g_qkvl, gb,            a1[0]+a2[0]+a3[0] + bs.x, a1[1]+a2[1]+a3[1] + bs.y);
            gsplit(g_qkvh, g_qkvl, gb + 8*QKV_LD, a1[2]+a2[2]+a3[2] + bs.x, a1[3]+a2[3]+a3[3] + bs.y);
        }
    }
}

// ================= Kernel B: spatial (3 CTAs/SM, Q from global) =================
__global__ __launch_bounds__(256, 3)
void spatial_kernel(const float* __restrict__ mask,
                    const float* __restrict__ pb, float* __restrict__ out)
{
    extern __shared__ char smc[];
    const uint32_t sbase = smem_u32(smc);
    __nv_bfloat16* ms = (__nv_bfloat16*)(smc + SP_MS);

    const int bt   = blockIdx.x;
    const int tid  = threadIdx.x;
    const int lane = tid & 31;
    const int warp = tid >> 5;

    // ---- raw copies of pre-split k/v ----
    {
        const size_t tb = (size_t)bt * NN * QKV_LD;
        for (int v = tid; v < NN*12; v += 256) {
            int r = v / 12, c8 = (v - (v/12)*12)*8;
            size_t src = tb + (size_t)r*QKV_LD + c8;
            uint32_t doff = (r*LDA + c8)*2;
            *(uint4*)(smc + SP_KH + doff) = *(const uint4*)(g_qkvh + src + 96);
            *(uint4*)(smc + SP_KL + doff) = *(const uint4*)(g_qkvl + src + 96);
            *(uint4*)(smc + SP_VH + doff) = *(const uint4*)(g_qkvh + src + 192);
            *(uint4*)(smc + SP_VL + doff) = *(const uint4*)(g_qkvl + src + 192);
        }
    }
    for (int i = tid; i < 15*52; i += 256) {
        int row = 49 + i/52, cw = i - (i/52)*52;
        ((uint32_t*)(smc + SP_VH))[row*52 + cw] = 0;
        ((uint32_t*)(smc + SP_VL))[row*52 + cw] = 0;
    }
    {
        const float* mrow = mask + (size_t)(bt & 63) * (49*49);
        for (int i = tid; i < 49*49; i += 256) {
            int r = i / 49, c = i - r*49;
            ms[r*52 + c] = __float2bfloat16_rn(mrow[i]);   // 0 / -100 exact
        }
    }
    __syncthreads();

    const int mt    = warp >> 1;
    const int dhalf = warp & 1;
    const int r0    = (mt == 3) ? 33 : mt*16;
    const int qr    = lane >> 2;
    const int qc    = (lane & 3)*2;
    const int row_a = r0 + qr, row_b = r0 + qr + 8;
    const size_t base_a = ((size_t)bt*NN + row_a)*QKV_LD;
    const size_t base_b = ((size_t)bt*NN + row_b)*QKV_LD;

    for (int h = 0; h < HEADS; h++) {
        // ---- q fragments directly from global ----
        uint32_t aqh[2][4], aql[2][4];
        #pragma unroll
        for (int kt = 0; kt < 2; kt++) {
            int cb = h*32 + kt*16 + qc;
            gfragA(aqh[kt], g_qkvh, base_a, base_b, cb);
            gfragA(aql[kt], g_qkvl, base_a, base_b, cb);
        }
        float sc[7][4];
        {
            int l = lane & 15;
            #pragma unroll
            for (int nt = 0; nt < 7; nt++) {
                uint32_t boff = ((nt*8 + (l & 7))*LDA + h*32 + (l & 8))*2;
                uint32_t bh[2][2], bl[2][2];
                #pragma unroll
                for (int kt = 0; kt < 2; kt++) {
                    ldsm2(bh[kt], sbase + SP_KH + boff + kt*32);
                    ldsm2(bl[kt], sbase + SP_KL + boff + kt*32);
                }
                float a1[4] = {0,0,0,0}, a2[4] = {0,0,0,0}, a3[4] = {0,0,0,0};
                #pragma unroll
                for (int kt = 0; kt < 2; kt++) {
                    mma16816(a1, aqh[kt], bh[kt]);
                    mma16816(a2, aql[kt], bh[kt]);
                    mma16816(a3, aqh[kt], bl[kt]);
                }
                sc[nt][0] = a1[0]+a2[0]+a3[0]; sc[nt][1] = a1[1]+a2[1]+a3[1];
                sc[nt][2] = a1[2]+a2[2]+a3[2]; sc[nt][3] = a1[3]+a2[3]+a3[3];
            }
        }
        {
            float mx0 = -3.0e38f, mx1 = -3.0e38f;
            #pragma unroll
            for (int nt = 0; nt < 7; nt++) {
                #pragma unroll
                for (int i = 0; i < 2; i++) {
                    int col = nt*8 + qc + i;
                    if (col < 49) {
                        sc[nt][i]   += __bfloat162float(ms[row_a*52 + col]);
                        sc[nt][2+i] += __bfloat162float(ms[row_b*52 + col]);
                    } else {
                        sc[nt][i] = -3.0e38f; sc[nt][2+i] = -3.0e38f;
                    }
                    mx0 = fmaxf(mx0, sc[nt][i]);
                    mx1 = fmaxf(mx1, sc[nt][2+i]);
                }
            }
            mx0 = fmaxf(mx0, __shfl_xor_sync(0xffffffffu, mx0, 1));
            mx0 = fmaxf(mx0, __shfl_xor_sync(0xffffffffu, mx0, 2));
            mx1 = fmaxf(mx1, __shfl_xor_sync(0xffffffffu, mx1, 1));
            mx1 = fmaxf(mx1, __shfl_xor_sync(0xffffffffu, mx1, 2));
            float s0 = 0.f, s1 = 0.f;
            #pragma unroll
            for (int nt = 0; nt < 7; nt++) {
                #pragma unroll
                for (int i = 0; i < 2; i++) {
                    sc[nt][i]   = __expf(sc[nt][i]   - mx0); s0 += sc[nt][i];
                    sc[nt][2+i] = __expf(sc[nt][2+i] - mx1); s1 += sc[nt][2+i];
                }
            }
            s0 += __shfl_xor_sync(0xffffffffu, s0, 1);
            s0 += __shfl_xor_sync(0xffffffffu, s0, 2);
            s1 += __shfl_xor_sync(0xffffffffu, s1, 1);
            s1 += __shfl_xor_sync(0xffffffffu, s1, 2);
            float inv0 = __frcp_rn(s0), inv1 = __frcp_rn(s1);
            #pragma unroll
            for (int nt = 0; nt < 7; nt++) {
                sc[nt][0] *= inv0; sc[nt][1] *= inv0;
                sc[nt][2] *= inv1; sc[nt][3] *= inv1;
            }
        }
        uint32_t ph[4][4], pl[4][4];
        #pragma unroll
        for (int kt = 0; kt < 4; kt++) {
            int nta = 2*kt, ntb = 2*kt + 1;
            split2(sc[nta][0], sc[nta][1], ph[kt][0], pl[kt][0]);
            split2(sc[nta][2], sc[nta][3], ph[kt][1], pl[kt][1]);
            if (ntb < 7) {
                split2(sc[ntb][0], sc[ntb][1], ph[kt][2], pl[kt][2]);
                split2(sc[ntb][2], sc[ntb][3], ph[kt][3], pl[kt][3]);
            } else {
                ph[kt][2] = 0; ph[kt][3] = 0; pl[kt][2] = 0; pl[kt][3] = 0;
            }
        }
        #pragma unroll
        for (int ntl = 0; ntl < 2; ntl++) {
            int d0 = h*32 + dhalf*16 + ntl*8;
            uint32_t vh01[4], vl01[4], vh23[4], vl23[4];
            ldsm4t(vh01, sbase + SP_VH + ((lane     )*LDA + d0)*2);
            ldsm4t(vl01, sbase + SP_VL + ((lane     )*LDA + d0)*2);
            ldsm4t(vh23, sbase + SP_VH + ((32 + lane)*LDA + d0)*2);
            ldsm4t(vl23, sbase + SP_VL + ((32 + lane)*LDA + d0)*2);
            float o1[4] = {0,0,0,0}, o2[4] = {0,0,0,0}, o3[4] = {0,0,0,0};
            #pragma unroll
            for (int kt = 0; kt < 4; kt++) {
                const uint32_t* bh_ = (kt < 2) ? &vh01[(kt & 1)*2] : &vh23[(kt & 1)*2];
                const uint32_t* bl_ = (kt < 2) ? &vl01[(kt & 1)*2] : &vl23[(kt & 1)*2];
                mma16816(o1, ph[kt], bh_);
                mma16816(o2, pl[kt], bh_);
                mma16816(o3, ph[kt], bl_);
            }
            int c0 = d0 + qc;
            split_store(smc + SP_XOH, smc + SP_XOL, row_a*LDA + c0,     o1[0]+o2[0]+o3[0]);
            split_store(smc + SP_XOH, smc + SP_XOL, row_a*LDA + c0 + 1, o1[1]+o2[1]+o3[1]);
            split_store(smc + SP_XOH, smc + SP_XOL, row_b*LDA + c0,     o1[2]+o2[2]+o3[2]);
            split_store(smc + SP_XOH, smc + SP_XOL, row_b*LDA + c0 + 1, o1[3]+o2[3]+o3[3]);
        }
    }

    // ---- projection: stage FULL weight once (aliases K and V regions) ----
    __syncthreads();
    for (int v = tid; v < 96*48; v += 256) {
        int kl = v / 48, j = v - (v/48)*48;
        ((uint32_t*)(smc + SP_WFH))[kl*52 + j] = ((const uint32_t*)g_pswh)[kl*48 + j];
        ((uint32_t*)(smc + SP_WFL))[kl*52 + j] = ((const uint32_t*)g_pswl)[kl*48 + j];
    }
    __syncthreads();

    const int nh = dhalf * 48;
    float acc[6][4];
    #pragma unroll
    for (int nt = 0; nt < 6; nt++)
        acc[nt][0] = acc[nt][1] = acc[nt][2] = acc[nt][3] = 0.f;

    #pragma unroll
    for (int s = 0; s < 3; s++) {
        uint32_t ah[2][4], al[2][4];
        int arow = r0 + (lane & 15);
        int acol = (lane >> 4)*8;
        #pragma unroll
        for (int kt = 0; kt < 2; kt++) {
            uint32_t off = (arow*LDA + s*32 + kt*16 + acol)*2;
            ldsm4(ah[kt], sbase + SP_XOH + off);
            ldsm4(al[kt], sbase + SP_XOL + off);
        }
        #pragma unroll
        for (int nt = 0; nt < 6; nt++) {
            uint32_t bh[2][2], bl[2][2];
            #pragma unroll
            for (int kt = 0; kt < 2; kt++) {
                uint32_t off = ((s*32 + kt*16 + (lane & 15))*LDA + nh + nt*8)*2;
                ldsm2t(bh[kt], sbase + SP_WFH + off);
                ldsm2t(bl[kt], sbase + SP_WFL + off);
            }
            #pragma unroll
            for (int kt = 0; kt < 2; kt++) {
                mma16816(acc[nt], ah[kt], bh[kt]);
                mma16816(acc[nt], al[kt], bh[kt]);
                mma16816(acc[nt], ah[kt], bl[kt]);
            }
        }
    }

    float* og = out + (size_t)bt * (NN*CDIM);
    #pragma unroll
    for (int nt = 0; nt < 6; nt++) {
        int col = nh + nt*8 + qc;
        float2 bs = {pb[col], pb[col+1]};
        int ra = r0 + qr, rb = r0 + qr + 8;
        if (ra < NN) { og[ra*CDIM + col] = acc[nt][0] + bs.x; og[ra*CDIM + col + 1] = acc[nt][1] + bs.y; }
        if (rb < NN) { og[rb*CDIM + col] = acc[nt][2] + bs.x; og[rb*CDIM + col + 1] = acc[nt][3] + bs.y; }
    }
}

// ================= Kernel C: temporal (3 CTAs/SM, Q from global) =================
__global__ __launch_bounds__(256, 3)
void temporal_kernel(const float* __restrict__ pb, float* __restrict__ out)
{
    extern __shared__ char smc[];
    const uint32_t sbase = smem_u32(smc);

    const int g    = blockIdx.x;
    const int b    = g / 7;
    const int n0   = (g - b*7) * 7;
    const int tid  = threadIdx.x;
    const int lane = tid & 31;
    const int warp = tid >> 5;

    for (int v = tid; v < 56*12; v += 256) {
        int r = v / 12, c8 = (v - (v/12)*12)*8;
        int sl = r >> 3, t = r & 7;
        size_t src = ((size_t)(b*TT + t)*NN + n0 + sl)*QKV_LD + c8;
        uint32_t doff = (r*LDA + c8)*2;
        *(uint4*)(smc + T_KH + doff) = *(const uint4*)(g_qkvh + src + 96);
        *(uint4*)(smc + T_KL + doff) = *(const uint4*)(g_qkvl + src + 96);
        *(uint4*)(smc + T_VH + doff) = *(const uint4*)(g_qkvh + src + 192);
        *(uint4*)(smc + T_VL + doff) = *(const uint4*)(g_qkvl + src + 192);
    }
    __syncthreads();

    const int mt    = warp >> 1;
    const int dhalf = warp & 1;
    const int r0    = (mt == 3) ? 40 : mt*16;
    const int qr    = lane >> 2;
    const int qc    = (lane & 3)*2;
    const int row_a = r0 + qr, row_b = r0 + qr + 8;
    const size_t base_a = ((size_t)(b*TT + (row_a & 7))*NN + n0 + (row_a >> 3))*QKV_LD;
    const size_t base_b = ((size_t)(b*TT + (row_b & 7))*NN + n0 + (row_b >> 3))*QKV_LD;

    for (int h = 0; h < HEADS; h++) {
        uint32_t aqh[2][4], aql[2][4];
        #pragma unroll
        for (int kt = 0; kt < 2; kt++) {
            int cb = h*32 + kt*16 + qc;
            gfragA(aqh[kt], g_qkvh, base_a, base_b, cb);
            gfragA(aql[kt], g_qkvl, base_a, base_b, cb);
        }
        float sc[2][4];
        {
            int l = lane & 15;
            #pragma unroll
            for (int nt = 0; nt < 2; nt++) {
                uint32_t boff = ((r0 + nt*8 + (l & 7))*LDA + h*32 + (l & 8))*2;
                uint32_t bh[2][2], bl[2][2];
                #pragma unroll
                for (int kt = 0; kt < 2; kt++) {
                    ldsm2(bh[kt], sbase + T_KH + boff + kt*32);
                    ldsm2(bl[kt], sbase + T_KL + boff + kt*32);
                }
                float a1[4] = {0,0,0,0}, a2[4] = {0,0,0,0}, a3[4] = {0,0,0,0};
                #pragma unroll
                for (int kt = 0; kt < 2; kt++) {
                    mma16816(a1, aqh[kt], bh[kt]);
                    mma16816(a2, aql[kt], bh[kt]);
                    mma16816(a3, aqh[kt], bl[kt]);
                }
                sc[nt][0] = a1[0]+a2[0]+a3[0]; sc[nt][1] = a1[1]+a2[1]+a3[1];
                sc[nt][2] = a1[2]+a2[2]+a3[2]; sc[nt][3] = a1[3]+a2[3]+a3[3];
            }
        }
        {
            float mx0 = fmaxf(sc[0][0], sc[0][1]);
            float mx1 = fmaxf(sc[1][2], sc[1][3]);
            mx0 = fmaxf(mx0, __shfl_xor_sync(0xffffffffu, mx0, 1));
            mx0 = fmaxf(mx0, __shfl_xor_sync(0xffffffffu, mx0, 2));
            mx1 = fmaxf(mx1, __shfl_xor_sync(0xffffffffu, mx1, 1));
            mx1 = fmaxf(mx1, __shfl_xor_sync(0xffffffffu, mx1, 2));
            float e00 = __expf(sc[0][0] - mx0), e01 = __expf(sc[0][1] - mx0);
            float e12 = __expf(sc[1][2] - mx1), e13 = __expf(sc[1][3] - mx1);
            float s0 = e00 + e01, s1 = e12 + e13;
            s0 += __shfl_xor_sync(0xffffffffu, s0, 1);
            s0 += __shfl_xor_sync(0xffffffffu, s0, 2);
            s1 += __shfl_xor_sync(0xffffffffu, s1, 1);
            s1 += __shfl_xor_sync(0xffffffffu, s1, 2);
            float inv0 = __frcp_rn(s0), inv1 = __frcp_rn(s1);
            sc[0][0] = e00*inv0; sc[0][1] = e01*inv0;
            sc[1][2] = e12*inv1; sc[1][3] = e13*inv1;
            sc[0][2] = 0.f; sc[0][3] = 0.f;
            sc[1][0] = 0.f; sc[1][1] = 0.f;
        }
        uint32_t ph[4], pl[4];
        split2(sc[0][0], sc[0][1], ph[0], pl[0]);
        split2(sc[0][2], sc[0][3], ph[1], pl[1]);
        split2(sc[1][0], sc[1][1], ph[2], pl[2]);
        split2(sc[1][2], sc[1][3], ph[3], pl[3]);
        #pragma unroll
        for (int ntl = 0; ntl < 2; ntl++) {
            int d0 = h*32 + dhalf*16 + ntl*8;
            uint32_t vh[2], vl[2];
            ldsm2t(vh, sbase + T_VH + ((r0 + (lane & 15))*LDA + d0)*2);
            ldsm2t(vl, sbase + T_VL + ((r0 + (lane & 15))*LDA + d0)*2);
            float o1[4] = {0,0,0,0}, o2[4] = {0,0,0,0}, o3[4] = {0,0,0,0};
            mma16816(o1, ph, vh);
            mma16816(o2, pl, vh);
            mma16816(o3, ph, vl);
            int c0 = d0 + qc;
            split_store(smc + T_XOH, smc + T_XOL, row_a*LDA + c0,     o1[0]+o2[0]+o3[0]);
            split_store(smc + T_XOH, smc + T_XOL, row_a*LDA + c0 + 1, o1[1]+o2[1]+o3[1]);
            split_store(smc + T_XOH, smc + T_XOL, row_b*LDA + c0,     o1[2]+o2[2]+o3[2]);
            split_store(smc + T_XOH, smc + T_XOL, row_b*LDA + c0 + 1, o1[3]+o2[3]+o3[3]);
        }
    }

    // ---- projection: stage FULL weight once (aliases K and V regions) ----
    __syncthreads();
    for (int v = tid; v < 96*48; v += 256) {
        int kl = v / 48, j = v - (v/48)*48;
        ((uint32_t*)(smc + T_WFH))[kl*52 + j] = ((const uint32_t*)g_ptwh)[kl*48 + j];
        ((uint32_t*)(smc + T_WFL))[kl*52 + j] = ((const uint32_t*)g_ptwl)[kl*48 + j];
    }
    __syncthreads();

    const int nh = dhalf * 48;
    float acc[6][4];
    #pragma unroll
    for (int nt = 0; nt < 6; nt++)
        acc[nt][0] = acc[nt][1] = acc[nt][2] = acc[nt][3] = 0.f;

    #pragma unroll
    for (int s = 0; s < 3; s++) {
        uint32_t ah[2][4], al[2][4];
        int arow = r0 + (lane & 15);
        int acol = (lane >> 4)*8;
        #pragma unroll
        for (int kt = 0; kt < 2; kt++) {
            uint32_t off = (arow*LDA + s*32 + kt*16 + acol)*2;
            ldsm4(ah[kt], sbase + T_XOH + off);
            ldsm4(al[kt], sbase + T_XOL + off);
        }
        #pragma unroll
        for (int nt = 0; nt < 6; nt++) {
            uint32_t bh[2][2], bl[2][2];
            #pragma unroll
            for (int kt = 0; kt < 2; kt++) {
                uint32_t off = ((s*32 + kt*16 + (lane & 15))*LDA + nh + nt*8)*2;
                ldsm2t(bh[kt], sbase + T_WFH + off);
                ldsm2t(bl[kt], sbase + T_WFL + off);
            }
            #pragma unroll
            for (int kt = 0; kt < 2; kt++) {
                mma16816(acc[nt], ah[kt], bh[kt]);
                mma16816(acc[nt], al[kt], bh[kt]);
                mma16816(acc[nt], ah[kt], bl[kt]);
            }
        }
    }

    #pragma unroll
    for (int nt = 0; nt < 6; nt++) {
        int col = nh + nt*8 + qc;
        float2 bs = {pb[col], pb[col+1]};
        #pragma unroll
        for (int half = 0; half < 2; half++) {
            int row = r0 + qr + half*8;
            int sl = row >> 3, t = row & 7;
            float* og = out + (((size_t)b*TT + t)*NN + (n0 + sl))*CDIM;
            og[col]     = acc[nt][half*2]     + bs.x;
            og[col + 1] = acc[nt][half*2 + 1] + bs.y;
        }
    }
}

extern "C" void kernel_launch(void* const* d_in, const int* in_sizes, int n_in,
                              void* d_out, int out_size)
{
    const float* x      = (const float*)d_in[0];
    const float* mask   = (const float*)d_in[1];
    const float* qkv_w  = (const float*)d_in[2];
    const float* qkv_b  = (const float*)d_in[3];
    const float* psw    = (const float*)d_in[4];
    const float* psb    = (const float*)d_in[5];
    const float* ptw    = (const float*)d_in[6];
    const float* ptb    = (const float*)d_in[7];

    float* out_t  = (float*)d_out;
    float* out_sp = out_t + (size_t)BATCH*TT*NN*CDIM;

    cudaFuncSetAttribute(qkv_mma_kernel,  cudaFuncAttributeMaxDynamicSharedMemorySize, SMEM_QKV);
    cudaFuncSetAttribute(spatial_kernel,  cudaFuncAttributeMaxDynamicSharedMemorySize, SMEM_SP);
    cudaFuncSetAttribute(temporal_kernel, cudaFuncAttributeMaxDynamicSharedMemorySize, SMEM_T);

    wconv_kernel<<<180, 256>>>(qkv_w, psw, ptw);
    qkv_mma_kernel<<<NTOK/128, 256, SMEM_QKV>>>(x, qkv_b);
    spatial_kernel<<<BATCH*TT, 256, SMEM_SP>>>(mask, psb, out_sp);
    temporal_kernel<<<BATCH*7, 256, SMEM_T>>>(ptb, out_t);
}

// round 17
// speedup vs baseline: 4.5286x; 1.0497x over previous
#include <cuda_runtime.h>
#include <cuda_bf16.h>
#include <cstdint>

#define BATCH   1024
#define TT      8
#define NN      49
#define CDIM    96
#define HEADS   3
#define HD      32
#define NTOK    (BATCH*TT*NN)
#define QKV_LD  288
#define LDA     104
#define SCALE   0.17677669529663687f

__device__ __nv_bfloat16 g_qkvh[(size_t)NTOK * QKV_LD];
__device__ __nv_bfloat16 g_qkvl[(size_t)NTOK * QKV_LD];
__device__ __nv_bfloat16 g_wqkvh[96*288], g_wqkvl[96*288];
__device__ __nv_bfloat16 g_pswh[96*96],  g_pswl[96*96];
__device__ __nv_bfloat16 g_ptwh[96*96],  g_ptwl[96*96];
__device__ __nv_bfloat16 g_maskb[64*49*52];          // padded bf16 mask

// ---- qkv smem (bytes) ----
#define QK_AHI   0                   // A hi; reused as fp32 stage (128x100 = 51200 <= 53248)
#define QK_ALO   26624
#define QK_BHI   53248
#define QK_BLO   73216
#define QK_BIAS  93184
#define SMEM_QKV 94336

// ---- spatial smem (bytes) ----
#define SP_KH    0                   // 56 rows: 11648
#define SP_KL    11648
#define SP_VH    23296               // 64 rows: 13312
#define SP_VL    36608
#define SP_XOH   49920               // 49 rows: 10192
#define SP_XOL   60112
#define SP_MS    70304               // mask bf16 49*52*2 = 5096
#define SMEM_SP  75400
#define SP_WFH   0                   // proj weight hi aliases K
#define SP_WFL   23296               // proj weight lo aliases V

// ---- temporal smem (bytes) ----
#define T_KH     0
#define T_KL     11648
#define T_VH     23296
#define T_VL     34944
#define T_XOH    46592
#define T_XOL    58240
#define SMEM_T   69888
#define T_WFH    0
#define T_WFL    23296

// ======================= helpers =======================
__device__ __forceinline__ uint32_t smem_u32(const void* p) {
    uint32_t a;
    asm("{ .reg .u64 t; cvta.to.shared.u64 t, %1; cvt.u32.u64 %0, t; }" : "=r"(a) : "l"(p));
    return a;
}
__device__ __forceinline__ void ldsm4(uint32_t* r, uint32_t addr) {
    asm volatile("ldmatrix.sync.aligned.m8n8.x4.shared.b16 {%0,%1,%2,%3}, [%4];"
                 : "=r"(r[0]), "=r"(r[1]), "=r"(r[2]), "=r"(r[3]) : "r"(addr));
}
__device__ __forceinline__ void ldsm2(uint32_t* r, uint32_t addr) {
    asm volatile("ldmatrix.sync.aligned.m8n8.x2.shared.b16 {%0,%1}, [%2];"
                 : "=r"(r[0]), "=r"(r[1]) : "r"(addr));
}
__device__ __forceinline__ void ldsm2t(uint32_t* r, uint32_t addr) {
    asm volatile("ldmatrix.sync.aligned.m8n8.x2.trans.shared.b16 {%0,%1}, [%2];"
                 : "=r"(r[0]), "=r"(r[1]) : "r"(addr));
}
__device__ __forceinline__ void ldsm4t(uint32_t* r, uint32_t addr) {
    asm volatile("ldmatrix.sync.aligned.m8n8.x4.trans.shared.b16 {%0,%1,%2,%3}, [%4];"
                 : "=r"(r[0]), "=r"(r[1]), "=r"(r[2]), "=r"(r[3]) : "r"(addr));
}
__device__ __forceinline__ void mma16816(float* d, const uint32_t* a, const uint32_t* b) {
    asm volatile("mma.sync.aligned.m16n8k16.row.col.f32.bf16.bf16.f32 "
                 "{%0,%1,%2,%3}, {%4,%5,%6,%7}, {%8,%9}, {%0,%1,%2,%3};"
                 : "+f"(d[0]), "+f"(d[1]), "+f"(d[2]), "+f"(d[3])
                 : "r"(a[0]), "r"(a[1]), "r"(a[2]), "r"(a[3]), "r"(b[0]), "r"(b[1]));
}
__device__ __forceinline__ uint32_t bfpk(float a, float b) {
    __nv_bfloat162 h = __floats2bfloat162_rn(a, b);
    return *(uint32_t*)&h;
}
__device__ __forceinline__ void split2(float a, float b, uint32_t& hi, uint32_t& lo) {
    __nv_bfloat16 ha = __float2bfloat16_rn(a), hb = __float2bfloat16_rn(b);
    __nv_bfloat162 hp = __halves2bfloat162(ha, hb);
    hi = *(uint32_t*)&hp;
    lo = bfpk(a - __bfloat162float(ha), b - __bfloat162float(hb));
}
// load A fragment (m16n8k16) directly from global hi/lo arrays
__device__ __forceinline__ void gfragA(uint32_t* r, const __nv_bfloat16* g, size_t base_a, size_t base_b, int cb) {
    r[0] = *(const uint32_t*)(g + base_a + cb);
    r[1] = *(const uint32_t*)(g + base_b + cb);
    r[2] = *(const uint32_t*)(g + base_a + cb + 8);
    r[3] = *(const uint32_t*)(g + base_b + cb + 8);
}

// ================= weight + mask pre-conversion =================
__global__ void wconv_kernel(const float* __restrict__ qkv_w,
                             const float* __restrict__ psw,
                             const float* __restrict__ ptw,
                             const float* __restrict__ mask)
{
    int i = blockIdx.x*256 + threadIdx.x;
    if (i < 96*288) {
        float v = qkv_w[i];
        if ((i % 288) < 96) v *= SCALE;
        __nv_bfloat16 h = __float2bfloat16_rn(v);
        g_wqkvh[i] = h;
        g_wqkvl[i] = __float2bfloat16_rn(v - __bfloat162float(h));
    } else if (i < 96*288 + 96*96) {
        int j = i - 96*288;
        float v = psw[j];
        __nv_bfloat16 h = __float2bfloat16_rn(v);
        g_pswh[j] = h;
        g_pswl[j] = __float2bfloat16_rn(v - __bfloat162float(h));
    } else if (i < 96*288 + 2*96*96) {
        int j = i - 96*288 - 96*96;
        float v = ptw[j];
        __nv_bfloat16 h = __float2bfloat16_rn(v);
        g_ptwh[j] = h;
        g_ptwl[j] = __float2bfloat16_rn(v - __bfloat162float(h));
    } else if (i < 96*288 + 2*96*96 + 64*49*49) {
        int j = i - 96*288 - 2*96*96;
        int w = j / 2401, rem = j - w*2401;
        int r = rem / 49, c = rem - r*49;
        g_maskb[w*2548 + r*52 + c] = __float2bfloat16_rn(mask[j]);   // 0 / -100 exact
    }
}

// ================= Kernel A: QKV GEMM (staged coalesced epilogue) =================
__global__ __launch_bounds__(256, 2)
void qkv_mma_kernel(const float* __restrict__ x, const float* __restrict__ qkv_b)
{
    extern __shared__ char smem[];
    const uint32_t sbase = smem_u32(smem);
    float* bias_sm = (float*)(smem + QK_BIAS);
    float* stg = (float*)(smem + QK_AHI);    // fp32 stage 128 x 100 (A region dead post-frag-load)

    const int tid  = threadIdx.x;
    const int lane = tid & 31;
    const int warp = tid >> 5;
    const int row0 = blockIdx.x * 128;

    for (int v = tid; v < 128*24; v += 256) {
        int r = v / 24, c = (v - (v/24)*24) * 4;
        float4 f = *(const float4*)(x + (size_t)(row0 + r)*96 + c);
        __nv_bfloat16 h0 = __float2bfloat16_rn(f.x), h1 = __float2bfloat16_rn(f.y);
        __nv_bfloat16 h2 = __float2bfloat16_rn(f.z), h3 = __float2bfloat16_rn(f.w);
        __nv_bfloat162 p0 = __halves2bfloat162(h0, h1);
        __nv_bfloat162 p1 = __halves2bfloat162(h2, h3);
        uint32_t off = (r*LDA + c)*2;
        *(uint32_t*)(smem + QK_AHI + off)     = *(uint32_t*)&p0;
        *(uint32_t*)(smem + QK_AHI + off + 4) = *(uint32_t*)&p1;
        *(uint32_t*)(smem + QK_ALO + off)     = bfpk(f.x - __bfloat162float(h0), f.y - __bfloat162float(h1));
        *(uint32_t*)(smem + QK_ALO + off + 4) = bfpk(f.z - __bfloat162float(h2), f.w - __bfloat162float(h3));
    }
    for (int v = tid; v < 288; v += 256)
        bias_sm[v] = qkv_b[v] * ((v < 96) ? SCALE : 1.0f);
    __syncthreads();

    uint32_t ah[6][4], al[6][4];
    {
        int arow = warp*16 + (lane & 15);
        int acol = (lane >> 4) * 8;
        #pragma unroll
        for (int kt = 0; kt < 6; kt++) {
            uint32_t boff = (arow*LDA + kt*16 + acol)*2;
            ldsm4(ah[kt], sbase + QK_AHI + boff);
            ldsm4(al[kt], sbase + QK_ALO + boff);
        }
    }

    for (int chunk = 0; chunk < 3; chunk++) {
        __syncthreads();    // prior stage reads + B ldsm done
        for (int v = tid; v < 96*48; v += 256) {
            int k = v / 48, j = v - (v/48)*48;
            ((uint32_t*)(smem + QK_BHI))[k*52 + j] = ((const uint32_t*)g_wqkvh)[k*144 + chunk*48 + j];
            ((uint32_t*)(smem + QK_BLO))[k*52 + j] = ((const uint32_t*)g_wqkvl)[k*144 + chunk*48 + j];
        }
        __syncthreads();

        const int brow = lane & 15;
        #pragma unroll
        for (int nt = 0; nt < 12; nt++) {
            const int n0 = nt*8;
            uint32_t bh[6][2], bl[6][2];
            #pragma unroll
            for (int kt = 0; kt < 6; kt++) {
                uint32_t boff = ((kt*16 + brow)*LDA + n0)*2;
                ldsm2t(bh[kt], sbase + QK_BHI + boff);
                ldsm2t(bl[kt], sbase + QK_BLO + boff);
            }
            float a1[4] = {0,0,0,0}, a2[4] = {0,0,0,0}, a3[4] = {0,0,0,0};
            #pragma unroll
            for (int kt = 0; kt < 6; kt++) {
                mma16816(a1, ah[kt], bh[kt]);
                mma16816(a2, al[kt], bh[kt]);
                mma16816(a3, ah[kt], bl[kt]);
            }
            int r  = lane >> 2;
            int c2 = (lane & 3)*2;
            int rw = warp*16 + r;
            float2 s0 = {a1[0]+a2[0]+a3[0], a1[1]+a2[1]+a3[1]};
            float2 s1 = {a1[2]+a2[2]+a3[2], a1[3]+a2[3]+a3[3]};
            *(float2*)(stg + rw*100 + n0 + c2)       = s0;
            *(float2*)(stg + (rw+8)*100 + n0 + c2)   = s1;
        }
        __syncthreads();

        // coalesced split epilogue: 128 rows x 96 cols
        for (int v = tid; v < 128*12; v += 256) {
            int r = v / 12, c8 = (v - (v/12)*12)*8;
            float4 f0 = *(const float4*)(stg + r*100 + c8);
            float4 f1 = *(const float4*)(stg + r*100 + c8 + 4);
            const float* bp = bias_sm + chunk*96 + c8;
            float w0 = f0.x + bp[0], w1 = f0.y + bp[1], w2 = f0.z + bp[2], w3 = f0.w + bp[3];
            float w4 = f1.x + bp[4], w5 = f1.y + bp[5], w6 = f1.z + bp[6], w7 = f1.w + bp[7];
            uint4 hv, lv;
            split2(w0, w1, hv.x, lv.x);
            split2(w2, w3, hv.y, lv.y);
            split2(w4, w5, hv.z, lv.z);
            split2(w6, w7, hv.w, lv.w);
            size_t gb = (size_t)(row0 + r)*QKV_LD + chunk*96 + c8;
            *(uint4*)(g_qkvh + gb) = hv;
            *(uint4*)(g_qkvl + gb) = lv;
        }
    }
}

// ================= Kernel B: spatial (3 CTAs/SM) =================
__global__ __launch_bounds__(256, 3)
void spatial_kernel(const float* __restrict__ pb, float* __restrict__ out)
{
    extern __shared__ char smc[];
    const uint32_t sbase = smem_u32(smc);
    __nv_bfloat16* ms = (__nv_bfloat16*)(smc + SP_MS);

    const int bt   = blockIdx.x;
    const int tid  = threadIdx.x;
    const int lane = tid & 31;
    const int warp = tid >> 5;

    {
        const size_t tb = (size_t)bt * NN * QKV_LD;
        for (int v = tid; v < NN*12; v += 256) {
            int r = v / 12, c8 = (v - (v/12)*12)*8;
            size_t src = tb + (size_t)r*QKV_LD + c8;
            uint32_t doff = (r*LDA + c8)*2;
            *(uint4*)(smc + SP_KH + doff) = *(const uint4*)(g_qkvh + src + 96);
            *(uint4*)(smc + SP_KL + doff) = *(const uint4*)(g_qkvl + src + 96);
            *(uint4*)(smc + SP_VH + doff) = *(const uint4*)(g_qkvh + src + 192);
            *(uint4*)(smc + SP_VL + doff) = *(const uint4*)(g_qkvl + src + 192);
        }
    }
    for (int i = tid; i < 15*52; i += 256) {
        int row = 49 + i/52, cw = i - (i/52)*52;
        ((uint32_t*)(smc + SP_VH))[row*52 + cw] = 0;
        ((uint32_t*)(smc + SP_VL))[row*52 + cw] = 0;
    }
    {
        const uint32_t* msrc = (const uint32_t*)(g_maskb + (size_t)(bt & 63)*2548);
        for (int i = tid; i < 1274; i += 256)
            ((uint32_t*)ms)[i] = msrc[i];
    }
    __syncthreads();

    const int mt    = warp >> 1;
    const int dhalf = warp & 1;
    const int r0    = (mt == 3) ? 33 : mt*16;
    const int qr    = lane >> 2;
    const int qc    = (lane & 3)*2;
    const int row_a = r0 + qr, row_b = r0 + qr + 8;
    const size_t base_a = ((size_t)bt*NN + row_a)*QKV_LD;
    const size_t base_b = ((size_t)bt*NN + row_b)*QKV_LD;

    for (int h = 0; h < HEADS; h++) {
        uint32_t aqh[2][4], aql[2][4];
        #pragma unroll
        for (int kt = 0; kt < 2; kt++) {
            int cb = h*32 + kt*16 + qc;
            gfragA(aqh[kt], g_qkvh, base_a, base_b, cb);
            gfragA(aql[kt], g_qkvl, base_a, base_b, cb);
        }
        float sc[7][4];
        {
            int l = lane & 15;
            #pragma unroll
            for (int nt = 0; nt < 7; nt++) {
                uint32_t boff = ((nt*8 + (l & 7))*LDA + h*32 + (l & 8))*2;
                uint32_t bh[2][2], bl[2][2];
                #pragma unroll
                for (int kt = 0; kt < 2; kt++) {
                    ldsm2(bh[kt], sbase + SP_KH + boff + kt*32);
                    ldsm2(bl[kt], sbase + SP_KL + boff + kt*32);
                }
                float a1[4] = {0,0,0,0}, a2[4] = {0,0,0,0}, a3[4] = {0,0,0,0};
                #pragma unroll
                for (int kt = 0; kt < 2; kt++) {
                    mma16816(a1, aqh[kt], bh[kt]);
                    mma16816(a2, aql[kt], bh[kt]);
                    mma16816(a3, aqh[kt], bl[kt]);
                }
                sc[nt][0] = a1[0]+a2[0]+a3[0]; sc[nt][1] = a1[1]+a2[1]+a3[1];
                sc[nt][2] = a1[2]+a2[2]+a3[2]; sc[nt][3] = a1[3]+a2[3]+a3[3];
            }
        }
        {
            float mx0 = -3.0e38f, mx1 = -3.0e38f;
            #pragma unroll
            for (int nt = 0; nt < 7; nt++) {
                #pragma unroll
                for (int i = 0; i < 2; i++) {
                    int col = nt*8 + qc + i;
                    if (col < 49) {
                        sc[nt][i]   += __bfloat162float(ms[row_a*52 + col]);
                        sc[nt][2+i] += __bfloat162float(ms[row_b*52 + col]);
                    } else {
                        sc[nt][i] = -3.0e38f; sc[nt][2+i] = -3.0e38f;
                    }
                    mx0 = fmaxf(mx0, sc[nt][i]);
                    mx1 = fmaxf(mx1, sc[nt][2+i]);
                }
            }
            mx0 = fmaxf(mx0, __shfl_xor_sync(0xffffffffu, mx0, 1));
            mx0 = fmaxf(mx0, __shfl_xor_sync(0xffffffffu, mx0, 2));
            mx1 = fmaxf(mx1, __shfl_xor_sync(0xffffffffu, mx1, 1));
            mx1 = fmaxf(mx1, __shfl_xor_sync(0xffffffffu, mx1, 2));
            float s0 = 0.f, s1 = 0.f;
            #pragma unroll
            for (int nt = 0; nt < 7; nt++) {
                #pragma unroll
                for (int i = 0; i < 2; i++) {
                    sc[nt][i]   = __expf(sc[nt][i]   - mx0); s0 += sc[nt][i];
                    sc[nt][2+i] = __expf(sc[nt][2+i] - mx1); s1 += sc[nt][2+i];
                }
            }
            s0 += __shfl_xor_sync(0xffffffffu, s0, 1);
            s0 += __shfl_xor_sync(0xffffffffu, s0, 2);
            s1 += __shfl_xor_sync(0xffffffffu, s1, 1);
            s1 += __shfl_xor_sync(0xffffffffu, s1, 2);
            float inv0 = __frcp_rn(s0), inv1 = __frcp_rn(s1);
            #pragma unroll
            for (int nt = 0; nt < 7; nt++) {
                sc[nt][0] *= inv0; sc[nt][1] *= inv0;
                sc[nt][2] *= inv1; sc[nt][3] *= inv1;
            }
        }
        uint32_t ph[4][4], pl[4][4];
        #pragma unroll
        for (int kt = 0; kt < 4; kt++) {
            int nta = 2*kt, ntb = 2*kt + 1;
            split2(sc[nta][0], sc[nta][1], ph[kt][0], pl[kt][0]);
            split2(sc[nta][2], sc[nta][3], ph[kt][1], pl[kt][1]);
            if (ntb < 7) {
                split2(sc[ntb][0], sc[ntb][1], ph[kt][2], pl[kt][2]);
                split2(sc[ntb][2], sc[ntb][3], ph[kt][3], pl[kt][3]);
            } else {
                ph[kt][2] = 0; ph[kt][3] = 0; pl[kt][2] = 0; pl[kt][3] = 0;
            }
        }
        #pragma unroll
        for (int ntl = 0; ntl < 2; ntl++) {
            int d0 = h*32 + dhalf*16 + ntl*8;
            uint32_t vh01[4], vl01[4], vh23[4], vl23[4];
            ldsm4t(vh01, sbase + SP_VH + ((lane     )*LDA + d0)*2);
            ldsm4t(vl01, sbase + SP_VL + ((lane     )*LDA + d0)*2);
            ldsm4t(vh23, sbase + SP_VH + ((32 + lane)*LDA + d0)*2);
            ldsm4t(vl23, sbase + SP_VL + ((32 + lane)*LDA + d0)*2);
            float o1[4] = {0,0,0,0}, o2[4] = {0,0,0,0}, o3[4] = {0,0,0,0};
            #pragma unroll
            for (int kt = 0; kt < 4; kt++) {
                const uint32_t* bh_ = (kt < 2) ? &vh01[(kt & 1)*2] : &vh23[(kt & 1)*2];
                const uint32_t* bl_ = (kt < 2) ? &vl01[(kt & 1)*2] : &vl23[(kt & 1)*2];
                mma16816(o1, ph[kt], bh_);
                mma16816(o2, pl[kt], bh_);
                mma16816(o3, ph[kt], bl_);
            }
            int c0 = d0 + qc;
            uint32_t hA, lA, hB, lB;
            split2(o1[0]+o2[0]+o3[0], o1[1]+o2[1]+o3[1], hA, lA);
            split2(o1[2]+o2[2]+o3[2], o1[3]+o2[3]+o3[3], hB, lB);
            *(uint32_t*)(smc + SP_XOH + (row_a*LDA + c0)*2) = hA;
            *(uint32_t*)(smc + SP_XOL + (row_a*LDA + c0)*2) = lA;
            *(uint32_t*)(smc + SP_XOH + (row_b*LDA + c0)*2) = hB;
            *(uint32_t*)(smc + SP_XOL + (row_b*LDA + c0)*2) = lB;
        }
    }

    // ---- projection: stage FULL weight once (aliases K and V regions) ----
    __syncthreads();
    for (int v = tid; v < 96*48; v += 256) {
        int kl = v / 48, j = v - (v/48)*48;
        ((uint32_t*)(smc + SP_WFH))[kl*52 + j] = ((const uint32_t*)g_pswh)[kl*48 + j];
        ((uint32_t*)(smc + SP_WFL))[kl*52 + j] = ((const uint32_t*)g_pswl)[kl*48 + j];
    }
    __syncthreads();

    const int nh = dhalf * 48;
    float acc[6][4];
    #pragma unroll
    for (int nt = 0; nt < 6; nt++)
        acc[nt][0] = acc[nt][1] = acc[nt][2] = acc[nt][3] = 0.f;

    #pragma unroll
    for (int s = 0; s < 3; s++) {
        uint32_t ah[2][4], al[2][4];
        int arow = r0 + (lane & 15);
        int acol = (lane >> 4)*8;
        #pragma unroll
        for (int kt = 0; kt < 2; kt++) {
            uint32_t off = (arow*LDA + s*32 + kt*16 + acol)*2;
            ldsm4(ah[kt], sbase + SP_XOH + off);
            ldsm4(al[kt], sbase + SP_XOL + off);
        }
        #pragma unroll
        for (int nt = 0; nt < 6; nt++) {
            uint32_t bh[2][2], bl[2][2];
            #pragma unroll
            for (int kt = 0; kt < 2; kt++) {
                uint32_t off = ((s*32 + kt*16 + (lane & 15))*LDA + nh + nt*8)*2;
                ldsm2t(bh[kt], sbase + SP_WFH + off);
                ldsm2t(bl[kt], sbase + SP_WFL + off);
            }
            #pragma unroll
            for (int kt = 0; kt < 2; kt++) {
                mma16816(acc[nt], ah[kt], bh[kt]);
                mma16816(acc[nt], al[kt], bh[kt]);
                mma16816(acc[nt], ah[kt], bl[kt]);
            }
        }
    }

    float* og = out + (size_t)bt * (NN*CDIM);
    #pragma unroll
    for (int nt = 0; nt < 6; nt++) {
        int col = nh + nt*8 + qc;
        float2 bs = {pb[col], pb[col+1]};
        int ra = r0 + qr, rb = r0 + qr + 8;
        if (ra < NN) { og[ra*CDIM + col] = acc[nt][0] + bs.x; og[ra*CDIM + col + 1] = acc[nt][1] + bs.y; }
        if (rb < NN) { og[rb*CDIM + col] = acc[nt][2] + bs.x; og[rb*CDIM + col + 1] = acc[nt][3] + bs.y; }
    }
}

// ================= Kernel C: temporal (3 CTAs/SM) =================
__global__ __launch_bounds__(256, 3)
void temporal_kernel(const float* __restrict__ pb, float* __restrict__ out)
{
    extern __shared__ char smc[];
    const uint32_t sbase = smem_u32(smc);

    const int g    = blockIdx.x;
    const int b    = g / 7;
    const int n0   = (g - b*7) * 7;
    const int tid  = threadIdx.x;
    const int lane = tid & 31;
    const int warp = tid >> 5;

    for (int v = tid; v < 56*12; v += 256) {
        int r = v / 12, c8 = (v - (v/12)*12)*8;
        int sl = r >> 3, t = r & 7;
        size_t src = ((size_t)(b*TT + t)*NN + n0 + sl)*QKV_LD + c8;
        uint32_t doff = (r*LDA + c8)*2;
        *(uint4*)(smc + T_KH + doff) = *(const uint4*)(g_qkvh + src + 96);
        *(uint4*)(smc + T_KL + doff) = *(const uint4*)(g_qkvl + src + 96);
        *(uint4*)(smc + T_VH + doff) = *(const uint4*)(g_qkvh + src + 192);
        *(uint4*)(smc + T_VL + doff) = *(const uint4*)(g_qkvl + src + 192);
    }
    __syncthreads();

    const int mt    = warp >> 1;
    const int dhalf = warp & 1;
    const int r0    = (mt == 3) ? 40 : mt*16;
    const int qr    = lane >> 2;
    const int qc    = (lane & 3)*2;
    const int row_a = r0 + qr, row_b = r0 + qr + 8;
    const size_t base_a = ((size_t)(b*TT + (row_a & 7))*NN + n0 + (row_a >> 3))*QKV_LD;
    const size_t base_b = ((size_t)(b*TT + (row_b & 7))*NN + n0 + (row_b >> 3))*QKV_LD;

    for (int h = 0; h < HEADS; h++) {
        uint32_t aqh[2][4], aql[2][4];
        #pragma unroll
        for (int kt = 0; kt < 2; kt++) {
            int cb = h*32 + kt*16 + qc;
            gfragA(aqh[kt], g_qkvh, base_a, base_b, cb);
            gfragA(aql[kt], g_qkvl, base_a, base_b, cb);
        }
        float sc[2][4];
        {
            int l = lane & 15;
            #pragma unroll
            for (int nt = 0; nt < 2; nt++) {
                uint32_t boff = ((r0 + nt*8 + (l & 7))*LDA + h*32 + (l & 8))*2;
                uint32_t bh[2][2], bl[2][2];
                #pragma unroll
                for (int kt = 0; kt < 2; kt++) {
                    ldsm2(bh[kt], sbase + T_KH + boff + kt*32);
                    ldsm2(bl[kt], sbase + T_KL + boff + kt*32);
                }
                float a1[4] = {0,0,0,0}, a2[4] = {0,0,0,0}, a3[4] = {0,0,0,0};
                #pragma unroll
                for (int kt = 0; kt < 2; kt++) {
                    mma16816(a1, aqh[kt], bh[kt]);
                    mma16816(a2, aql[kt], bh[kt]);
                    mma16816(a3, aqh[kt], bl[kt]);
                }
                sc[nt][0] = a1[0]+a2[0]+a3[0]; sc[nt][1] = a1[1]+a2[1]+a3[1];
                sc[nt][2] = a1[2]+a2[2]+a3[2]; sc[nt][3] = a1[3]+a2[3]+a3[3];
            }
        }
        {
            float mx0 = fmaxf(sc[0][0], sc[0][1]);
            float mx1 = fmaxf(sc[1][2], sc[1][3]);
            mx0 = fmaxf(mx0, __shfl_xor_sync(0xffffffffu, mx0, 1));
            mx0 = fmaxf(mx0, __shfl_xor_sync(0xffffffffu, mx0, 2));
            mx1 = fmaxf(mx1, __shfl_xor_sync(0xffffffffu, mx1, 1));
            mx1 = fmaxf(mx1, __shfl_xor_sync(0xffffffffu, mx1, 2));
            float e00 = __expf(sc[0][0] - mx0), e01 = __expf(sc[0][1] - mx0);
            float e12 = __expf(sc[1][2] - mx1), e13 = __expf(sc[1][3] - mx1);
            float s0 = e00 + e01, s1 = e12 + e13;
            s0 += __shfl_xor_sync(0xffffffffu, s0, 1);
            s0 += __shfl_xor_sync(0xffffffffu, s0, 2);
            s1 += __shfl_xor_sync(0xffffffffu, s1, 1);
            s1 += __shfl_xor_sync(0xffffffffu, s1, 2);
            float inv0 = __frcp_rn(s0), inv1 = __frcp_rn(s1);
            sc[0][0] = e00*inv0; sc[0][1] = e01*inv0;
            sc[1][2] = e12*inv1; sc[1][3] = e13*inv1;
            sc[0][2] = 0.f; sc[0][3] = 0.f;
            sc[1][0] = 0.f; sc[1][1] = 0.f;
        }
        uint32_t ph[4], pl[4];
        split2(sc[0][0], sc[0][1], ph[0], pl[0]);
        split2(sc[0][2], sc[0][3], ph[1], pl[1]);
        split2(sc[1][0], sc[1][1], ph[2], pl[2]);
        split2(sc[1][2], sc[1][3], ph[3], pl[3]);
        #pragma unroll
        for (int ntl = 0; ntl < 2; ntl++) {
            int d0 = h*32 + dhalf*16 + ntl*8;
            uint32_t vh[2], vl[2];
            ldsm2t(vh, sbase + T_VH + ((r0 + (lane & 15))*LDA + d0)*2);
            ldsm2t(vl, sbase + T_VL + ((r0 + (lane & 15))*LDA + d0)*2);
            float o1[4] = {0,0,0,0}, o2[4] = {0,0,0,0}, o3[4] = {0,0,0,0};
            mma16816(o1, ph, vh);
            mma16816(o2, pl, vh);
            mma16816(o3, ph, vl);
            int c0 = d0 + qc;
            uint32_t hA, lA, hB, lB;
            split2(o1[0]+o2[0]+o3[0], o1[1]+o2[1]+o3[1], hA, lA);
            split2(o1[2]+o2[2]+o3[2], o1[3]+o2[3]+o3[3], hB, lB);
            *(uint32_t*)(smc + T_XOH + (row_a*LDA + c0)*2) = hA;
            *(uint32_t*)(smc + T_XOL + (row_a*LDA + c0)*2) = lA;
            *(uint32_t*)(smc + T_XOH + (row_b*LDA + c0)*2) = hB;
            *(uint32_t*)(smc + T_XOL + (row_b*LDA + c0)*2) = lB;
        }
    }

    // ---- projection: stage FULL weight once (aliases K and V regions) ----
    __syncthreads();
    for (int v = tid; v < 96*48; v += 256) {
        int kl = v / 48, j = v - (v/48)*48;
        ((uint32_t*)(smc + T_WFH))[kl*52 + j] = ((const uint32_t*)g_ptwh)[kl*48 + j];
        ((uint32_t*)(smc + T_WFL))[kl*52 + j] = ((const uint32_t*)g_ptwl)[kl*48 + j];
    }
    __syncthreads();

    const int nh = dhalf * 48;
    float acc[6][4];
    #pragma unroll
    for (int nt = 0; nt < 6; nt++)
        acc[nt][0] = acc[nt][1] = acc[nt][2] = acc[nt][3] = 0.f;

    #pragma unroll
    for (int s = 0; s < 3; s++) {
        uint32_t ah[2][4], al[2][4];
        int arow = r0 + (lane & 15);
        int acol = (lane >> 4)*8;
        #pragma unroll
        for (int kt = 0; kt < 2; kt++) {
            uint32_t off = (arow*LDA + s*32 + kt*16 + acol)*2;
            ldsm4(ah[kt], sbase + T_XOH + off);
            ldsm4(al[kt], sbase + T_XOL + off);
        }
        #pragma unroll
        for (int nt = 0; nt < 6; nt++) {
            uint32_t bh[2][2], bl[2][2];
            #pragma unroll
            for (int kt = 0; kt < 2; kt++) {
                uint32_t off = ((s*32 + kt*16 + (lane & 15))*LDA + nh + nt*8)*2;
                ldsm2t(bh[kt], sbase + T_WFH + off);
                ldsm2t(bl[kt], sbase + T_WFL + off);
            }
            #pragma unroll
            for (int kt = 0; kt < 2; kt++) {
                mma16816(acc[nt], ah[kt], bh[kt]);
                mma16816(acc[nt], al[kt], bh[kt]);
                mma16816(acc[nt], ah[kt], bl[kt]);
            }
        }
    }

    #pragma unroll
    for (int nt = 0; nt < 6; nt++) {
        int col = nh + nt*8 + qc;
        float2 bs = {pb[col], pb[col+1]};
        #pragma unroll
        for (int half = 0; half < 2; half++) {
            int row = r0 + qr + half*8;
            int sl = row >> 3, t = row & 7;
            float* og = out + (((size_t)b*TT + t)*NN + (n0 + sl))*CDIM;
            og[col]     = acc[nt][half*2]     + bs.x;
            og[col + 1] = acc[nt][half*2 + 1] + bs.y;
        }
    }
}

extern "C" void kernel_launch(void* const* d_in, const int* in_sizes, int n_in,
                              void* d_out, int out_size)
{
    const float* x      = (const float*)d_in[0];
    const float* mask   = (const float*)d_in[1];
    const float* qkv_w  = (const float*)d_in[2];
    const float* qkv_b  = (const float*)d_in[3];
    const float* psw    = (const float*)d_in[4];
    const float* psb    = (const float*)d_in[5];
    const float* ptw    = (const float*)d_in[6];
    const float* ptb    = (const float*)d_in[7];

    float* out_t  = (float*)d_out;
    float* out_sp = out_t + (size_t)BATCH*TT*NN*CDIM;

    cudaFuncSetAttribute(qkv_mma_kernel,  cudaFuncAttributeMaxDynamicSharedMemorySize, SMEM_QKV);
    cudaFuncSetAttribute(spatial_kernel,  cudaFuncAttributeMaxDynamicSharedMemorySize, SMEM_SP);
    cudaFuncSetAttribute(temporal_kernel, cudaFuncAttributeMaxDynamicSharedMemorySize, SMEM_T);

    wconv_kernel<<<781, 256>>>(qkv_w, psw, ptw, mask);
    qkv_mma_kernel<<<NTOK/128, 256, SMEM_QKV>>>(x, qkv_b);
    spatial_kernel<<<BATCH*TT, 256, SMEM_SP>>>(psb, out_sp);
    temporal_kernel<<<BATCH*7, 256, SMEM_T>>>(ptb, out_t);
}